// round 2
// baseline (speedup 1.0000x reference)
#include <cuda_runtime.h>
#include <math.h>

// ----------------------------------------------------------------------------
// DYS_opt_net: z_{k+1} = relu(z) - a*w + c - (G (A u^T))^T,  u = |z| - a*w
// with G = A^T (A A^T)^{-1} (= pinv(A)), c = G b.
// Precompute per call: S = A A^T, power-iteration lambda_max, Newton-Schulz
// inverse of S (10 iters), G, c, MLP w. Then 50 guarded DYS iterations with
// early-stop flag + one final unguarded step with relu into d_out.
// ----------------------------------------------------------------------------

#define N1C 1024
#define N2C 4096
#define BC  256
#define DC  512
#define HC  2048

#define ALPHA_C 0.05f
#define EPS_C   0.01f
#define SPLITS  4
#define NS_ITERS 10
#define PI_ITERS 12

#define BMM 128
#define BNN 64
#define BKK 16
#define TMM 8
#define TNN 4
#define NTHR 256

#define EPI_STORE 0
#define EPI_SPLIT 1
#define EPI_NS    2
#define EPI_BIAS  3
#define EPI_BRELU 4
#define EPI_Z     5
#define EPI_ZFIN  6

__device__ float g_S [(size_t)N1C*N1C];
__device__ float g_Xa[(size_t)N1C*N1C];
__device__ float g_Xb[(size_t)N1C*N1C];
__device__ float g_T [(size_t)N1C*N1C];
__device__ float g_G [(size_t)N2C*N1C];
__device__ float g_c [N2C];
__device__ float g_tv[N1C];
__device__ float g_v [N1C];
__device__ float g_y [N1C];
__device__ float g_h [(size_t)BC*HC];
__device__ float g_w [(size_t)BC*N2C];
__device__ float g_za[(size_t)BC*N2C];
__device__ float g_zb[(size_t)BC*N2C];
__device__ float g_r [(size_t)N1C*BC];
__device__ float g_P [(size_t)SPLITS*N1C*BC];
__device__ float g_lam;
__device__ float g_ss;
__device__ int   g_flag;

__global__ void init_k() { g_ss = 0.f; g_flag = 0; }

__global__ void copy_k(float* __restrict__ dst, const float* __restrict__ src) {
    int i = blockIdx.x * blockDim.x + threadIdx.x;
    dst[i] = src[i];
}

__global__ void fill_k(float* v, float val, int n) {
    int i = blockIdx.x * blockDim.x + threadIdx.x;
    if (i < n) v[i] = val;
}

// y = M_ * v  (M_ is N1C x N1C row-major), one warp per row
__global__ void spmv_k(const float* __restrict__ M_, const float* __restrict__ v,
                       float* __restrict__ y) {
    int row = blockIdx.x * 8 + threadIdx.y;
    const float* mr = M_ + (size_t)row * N1C;
    float s = 0.f;
    for (int j = threadIdx.x; j < N1C; j += 32) s += mr[j] * v[j];
    #pragma unroll
    for (int o = 16; o; o >>= 1) s += __shfl_xor_sync(0xffffffffu, s, o);
    if (threadIdx.x == 0) y[row] = s;
}

// v = y / ||y||, g_lam = ||y||
__global__ void pi_norm_k(const float* __restrict__ y, float* __restrict__ v) {
    __shared__ float red[256];
    float s = 0.f;
    for (int i = threadIdx.x; i < N1C; i += 256) { float t = y[i]; s += t * t; }
    red[threadIdx.x] = s; __syncthreads();
    for (int o = 128; o; o >>= 1) {
        if (threadIdx.x < o) red[threadIdx.x] += red[threadIdx.x + o];
        __syncthreads();
    }
    float nrm = sqrtf(red[0]);
    float inv = 1.f / nrm;
    for (int i = threadIdx.x; i < N1C; i += 256) v[i] = y[i] * inv;
    if (threadIdx.x == 0) g_lam = nrm;
}

__global__ void initX_k(float* X) {
    float a = 1.f / (1.02f * g_lam);
    int i = blockIdx.x * 256 + threadIdx.x;
    int rr = i / N1C, cc = i % N1C;
    X[i] = (rr == cc) ? a : 0.f;
}

// c[j] = sum_i A[i*N2C + j] * t[i]
__global__ void atmv_k(const float* __restrict__ A, const float* __restrict__ t,
                       float* __restrict__ c) {
    __shared__ float ts[N1C];
    for (int i = threadIdx.x; i < N1C; i += 256) ts[i] = t[i];
    __syncthreads();
    int j = blockIdx.x * 256 + threadIdx.x;
    float s = 0.f;
    for (int i = 0; i < N1C; i++) s += A[(size_t)i * N2C + j] * ts[i];
    c[j] = s;
}

__global__ void reduce_r_k(const float* __restrict__ P, float* __restrict__ r,
                           const int* __restrict__ guard) {
    if (guard && *guard) return;
    int i = blockIdx.x * 256 + threadIdx.x;
    float s = 0.f;
    #pragma unroll
    for (int sp = 0; sp < SPLITS; sp++) s += P[(size_t)sp * N1C * BC + i];
    r[i] = s;
}

__global__ void check_k() {
    if (g_ss <= EPS_C * EPS_C) g_flag = 1;
    g_ss = 0.f;
}

// Generic tiled SGEMM.
// A_KC:  A element [m][k] = Ag[m*lda + k]  (else Ag[k*lda + m])
// B_NC:  B element [k][n] = Bg[k*ldb + n]  (else Bg[n*ldb + k])
// B_U:   B element = |Bg[..]| - ALPHA*Bw[..]   (NT layout only)
// acc[m][n] = sum_k A[m][k]*B[k][n]
template<bool A_KC, bool B_NC, bool B_U, int EPI>
__global__ void __launch_bounds__(NTHR)
gemm_k(const float* __restrict__ Ag, int lda,
       const float* __restrict__ Bg, int ldb,
       const float* __restrict__ Bw,
       float* __restrict__ Cg, int N, int K, int kchunk,
       const float* __restrict__ E0,
       const float* __restrict__ E1,
       const float* __restrict__ E2,
       float* __restrict__ sumsq,
       const int* __restrict__ guard)
{
    const int m0 = blockIdx.y * BMM;
    const int n0 = blockIdx.x * BNN;
    const int tid = threadIdx.x;

    if (guard && *guard) {
        if (EPI == EPI_Z) {           // converged: z_out tile = z_in tile
            for (int e = tid; e < BMM * BNN; e += NTHR) {
                int m = e >> 6;
                int n = e & 63;
                size_t idx = (size_t)(m0 + m) * N + (n0 + n);
                Cg[idx] = E0[idx];
            }
        }
        return;
    }

    __shared__ float As[BKK][BMM + 1];
    __shared__ float Bs[BKK][BNN + 1];

    const int tx = tid & 15;
    const int ty = tid >> 4;

    float acc[TMM][TNN];
    #pragma unroll
    for (int i = 0; i < TMM; i++)
        #pragma unroll
        for (int j = 0; j < TNN; j++) acc[i][j] = 0.f;

    const int k0 = blockIdx.z * kchunk;
    const int kend = k0 + kchunk;

    for (int kb = k0; kb < kend; kb += BKK) {
        #pragma unroll
        for (int e = tid; e < BMM * BKK; e += NTHR) {
            int m, kk;
            if (A_KC) { m = e >> 4; kk = e & 15; }
            else      { kk = e >> 7; m = e & 127; }
            size_t gi = A_KC ? (size_t)(m0 + m) * lda + (kb + kk)
                             : (size_t)(kb + kk) * lda + (m0 + m);
            As[kk][m] = Ag[gi];
        }
        #pragma unroll
        for (int e = tid; e < BNN * BKK; e += NTHR) {
            int n, kk;
            if (B_NC) { kk = e >> 6; n = e & 63; }
            else      { n = e >> 4; kk = e & 15; }
            size_t gi = B_NC ? (size_t)(kb + kk) * ldb + (n0 + n)
                             : (size_t)(n0 + n) * ldb + (kb + kk);
            float val = B_U ? (fabsf(Bg[gi]) - ALPHA_C * Bw[gi]) : Bg[gi];
            Bs[kk][n] = val;
        }
        __syncthreads();
        #pragma unroll
        for (int kk = 0; kk < BKK; kk++) {
            float ra[TMM], rb[TNN];
            #pragma unroll
            for (int i = 0; i < TMM; i++) ra[i] = As[kk][ty + i * 16];
            #pragma unroll
            for (int j = 0; j < TNN; j++) rb[j] = Bs[kk][tx + j * 16];
            #pragma unroll
            for (int i = 0; i < TMM; i++)
                #pragma unroll
                for (int j = 0; j < TNN; j++)
                    acc[i][j] = fmaf(ra[i], rb[j], acc[i][j]);
        }
        __syncthreads();
    }

    float local_ss = 0.f;
    #pragma unroll
    for (int i = 0; i < TMM; i++) {
        int m = m0 + ty + i * 16;
        #pragma unroll
        for (int j = 0; j < TNN; j++) {
            int n = n0 + tx + j * 16;
            size_t ci = (size_t)m * N + n;
            float a = acc[i][j];
            if (EPI == EPI_STORE) {
                Cg[ci] = a;
            } else if (EPI == EPI_SPLIT) {
                size_t off = (size_t)blockIdx.z * gridDim.y * BMM * N;
                Cg[off + ci] = a;
            } else if (EPI == EPI_NS) {
                Cg[ci] = 2.f * E0[ci] - a;              // X(2I - SX)
            } else if (EPI == EPI_BIAS) {
                Cg[ci] = a + E0[n];
            } else if (EPI == EPI_BRELU) {
                Cg[ci] = fmaxf(a + E0[n], 0.f);
            } else if (EPI == EPI_Z || EPI == EPI_ZFIN) {
                float zi = E0[ci];
                float zn = fmaxf(zi, 0.f) - ALPHA_C * E1[ci] + E2[n] - a;
                if (EPI == EPI_Z) {
                    Cg[ci] = zn;
                    float dd = zn - zi;
                    local_ss += dd * dd;
                } else {
                    Cg[ci] = fmaxf(zn, 0.f);            // project_C1 of final step
                }
            }
        }
    }
    if (EPI == EPI_Z) {
        __shared__ float red[NTHR];
        red[tid] = local_ss;
        __syncthreads();
        for (int o = NTHR / 2; o; o >>= 1) {
            if (tid < o) red[tid] += red[tid + o];
            __syncthreads();
        }
        if (tid == 0) atomicAdd(sumsq, red[0]);
    }
}

extern "C" void kernel_launch(void* const* d_in, const int* in_sizes, int n_in,
                              void* d_out, int out_size) {
    (void)in_sizes; (void)n_in; (void)out_size;
    const float* dd  = (const float*)d_in[0];
    const float* dA  = (const float*)d_in[1];
    const float* dB  = (const float*)d_in[2];
    const float* dW1 = (const float*)d_in[3];
    const float* db1 = (const float*)d_in[4];
    const float* dW2 = (const float*)d_in[5];
    const float* db2 = (const float*)d_in[6];
    const float* dz0 = (const float*)d_in[7];
    float* out = (float*)d_out;

    void* p;
    cudaGetSymbolAddress(&p, g_S);  float* S    = (float*)p;
    cudaGetSymbolAddress(&p, g_Xa); float* Xa   = (float*)p;
    cudaGetSymbolAddress(&p, g_Xb); float* Xb   = (float*)p;
    cudaGetSymbolAddress(&p, g_T);  float* Tm   = (float*)p;
    cudaGetSymbolAddress(&p, g_G);  float* G    = (float*)p;
    cudaGetSymbolAddress(&p, g_c);  float* c    = (float*)p;
    cudaGetSymbolAddress(&p, g_tv); float* tv   = (float*)p;
    cudaGetSymbolAddress(&p, g_v);  float* v    = (float*)p;
    cudaGetSymbolAddress(&p, g_y);  float* y    = (float*)p;
    cudaGetSymbolAddress(&p, g_h);  float* h    = (float*)p;
    cudaGetSymbolAddress(&p, g_w);  float* wbuf = (float*)p;
    cudaGetSymbolAddress(&p, g_za); float* za   = (float*)p;
    cudaGetSymbolAddress(&p, g_zb); float* zbb  = (float*)p;
    cudaGetSymbolAddress(&p, g_r);  float* r    = (float*)p;
    cudaGetSymbolAddress(&p, g_P);  float* P    = (float*)p;
    cudaGetSymbolAddress(&p, g_ss); float* ss   = (float*)p;
    cudaGetSymbolAddress(&p, g_flag); int* flag = (int*)p;

    init_k<<<1, 1>>>();
    copy_k<<<(BC * N2C) / 256, 256>>>(za, dz0);

    // S = A A^T   (NT: both operands K-contig)
    dim3 gS(N1C / BNN, N1C / BMM, 1);
    gemm_k<true, false, false, EPI_STORE><<<gS, NTHR>>>(
        dA, N2C, dA, N2C, nullptr, S, N1C, N2C, N2C,
        nullptr, nullptr, nullptr, nullptr, nullptr);

    // power iteration for lambda_max(S)
    fill_k<<<N1C / 256, 256>>>(v, 0.03125f, N1C);
    for (int i = 0; i < PI_ITERS; i++) {
        spmv_k<<<N1C / 8, dim3(32, 8)>>>(S, v, y);
        pi_norm_k<<<1, 256>>>(y, v);
    }
    initX_k<<<(N1C * N1C) / 256, 256>>>(Xa);

    // Newton-Schulz: X <- X(2I - S X)
    float* Xc = Xa; float* Xn = Xb;
    for (int i = 0; i < NS_ITERS; i++) {
        gemm_k<true, true, false, EPI_STORE><<<gS, NTHR>>>(
            S, N1C, Xc, N1C, nullptr, Tm, N1C, N1C, N1C,
            nullptr, nullptr, nullptr, nullptr, nullptr);
        gemm_k<true, true, false, EPI_NS><<<gS, NTHR>>>(
            Xc, N1C, Tm, N1C, nullptr, Xn, N1C, N1C, N1C,
            Xc, nullptr, nullptr, nullptr, nullptr);
        float* t2 = Xc; Xc = Xn; Xn = t2;
    }

    // c = A^T (X b)
    spmv_k<<<N1C / 8, dim3(32, 8)>>>(Xc, dB, tv);
    atmv_k<<<N2C / 256, 256>>>(dA, tv, c);

    // G = A^T X    (TN: A m-contig, X n-contig)
    dim3 gG(N1C / BNN, N2C / BMM, 1);
    gemm_k<false, true, false, EPI_STORE><<<gG, NTHR>>>(
        dA, N2C, Xc, N1C, nullptr, G, N1C, N1C, N1C,
        nullptr, nullptr, nullptr, nullptr, nullptr);

    // MLP: h = relu(d W1 + b1); w = h W2 + b2
    dim3 gM1(HC / BNN, BC / BMM, 1);
    gemm_k<true, true, false, EPI_BRELU><<<gM1, NTHR>>>(
        dd, DC, dW1, HC, nullptr, h, HC, DC, DC,
        db1, nullptr, nullptr, nullptr, nullptr);
    dim3 gM2(N2C / BNN, BC / BMM, 1);
    gemm_k<true, true, false, EPI_BIAS><<<gM2, NTHR>>>(
        h, HC, dW2, N2C, nullptr, wbuf, N2C, HC, HC,
        db2, nullptr, nullptr, nullptr, nullptr);

    // DYS fixed-point loop: 50 guarded iterations
    dim3 g1(BC / BNN, N1C / BMM, SPLITS);        // r = A u^T (split-K)
    dim3 g2(N2C / BNN, BC / BMM, 1);             // z update
    float* zb2[2] = { za, zbb };
    for (int it = 1; it <= 50; ++it) {
        const float* zin = zb2[(it - 1) & 1];
        float* zout = zb2[it & 1];
        gemm_k<true, false, true, EPI_SPLIT><<<g1, NTHR>>>(
            dA, N2C, zin, N2C, wbuf, P, BC, N2C, N2C / SPLITS,
            nullptr, nullptr, nullptr, nullptr, flag);
        reduce_r_k<<<(N1C * BC) / 256, 256>>>(P, r, flag);
        gemm_k<false, false, false, EPI_Z><<<g2, NTHR>>>(
            r, BC, G, N1C, nullptr, zout, N2C, N1C, N1C,
            zin, wbuf, c, ss, flag);
        check_k<<<1, 1>>>();
    }

    // final training-branch step (unguarded), relu into d_out
    gemm_k<true, false, true, EPI_SPLIT><<<g1, NTHR>>>(
        dA, N2C, za, N2C, wbuf, P, BC, N2C, N2C / SPLITS,
        nullptr, nullptr, nullptr, nullptr, nullptr);
    reduce_r_k<<<(N1C * BC) / 256, 256>>>(P, r, nullptr);
    gemm_k<false, false, false, EPI_ZFIN><<<g2, NTHR>>>(
        r, BC, G, N1C, nullptr, out, N2C, N1C, N1C,
        za, wbuf, c, nullptr, nullptr);
}

// round 3
// speedup vs baseline: 1.8619x; 1.8619x over previous
#include <cuda_runtime.h>
#include <math.h>

// ----------------------------------------------------------------------------
// DYS_opt_net: z' = relu(z) - a*w + c - (G (A u^T))^T,  u = |z| - a*w
// G = A^T (A A^T)^{-1} via Newton-Schulz; c = G b.
// Round 3: 128x128x16 double-buffered fp32 SGEMM (float4 everywhere),
// split-K on every small-grid GEMM, fused epilogues in float4 reduce kernels.
// ----------------------------------------------------------------------------

#define N1C 1024
#define N2C 4096
#define BC  256
#define DC  512
#define HC  2048

#define ALPHA_C 0.05f
#define EPS_C   0.01f
#define NS_ITERS 10
#define PI_ITERS 12

#define BM 128
#define BN 128
#define BK 16
#define PAD 4
#define NTHR 256

__device__ float g_S [(size_t)N1C*N1C];
__device__ float g_Xa[(size_t)N1C*N1C];
__device__ float g_Xb[(size_t)N1C*N1C];
__device__ float g_T [(size_t)N1C*N1C];
__device__ float g_G [(size_t)N2C*N1C];
__device__ float g_c [N2C];
__device__ float g_tv[N1C];
__device__ float g_v [N1C];
__device__ float g_y [N1C];
__device__ float g_h [(size_t)BC*HC];
__device__ float g_w [(size_t)BC*N2C];
__device__ float g_za[(size_t)BC*N2C];
__device__ float g_zb[(size_t)BC*N2C];
__device__ float g_r [(size_t)N1C*BC];
__device__ float g_P [(size_t)4*1024*1024];   // max split-K partials (16MB)
__device__ float g_lam;
__device__ float g_ss;
__device__ int   g_flag;

__global__ void init_k() { g_ss = 0.f; g_flag = 0; }

__global__ void copy4_k(float4* __restrict__ dst, const float4* __restrict__ src) {
    int i = blockIdx.x * blockDim.x + threadIdx.x;
    dst[i] = src[i];
}

__global__ void fill_k(float* v, float val, int n) {
    int i = blockIdx.x * blockDim.x + threadIdx.x;
    if (i < n) v[i] = val;
}

// y = M_ * v (N1C x N1C row-major), one warp per row
__global__ void spmv_k(const float* __restrict__ M_, const float* __restrict__ v,
                       float* __restrict__ y) {
    int row = blockIdx.x * 8 + threadIdx.y;
    const float* mr = M_ + (size_t)row * N1C;
    float s = 0.f;
    for (int j = threadIdx.x; j < N1C; j += 32) s += mr[j] * v[j];
    #pragma unroll
    for (int o = 16; o; o >>= 1) s += __shfl_xor_sync(0xffffffffu, s, o);
    if (threadIdx.x == 0) y[row] = s;
}

__global__ void pi_norm_k(const float* __restrict__ y, float* __restrict__ v) {
    __shared__ float red[256];
    float s = 0.f;
    for (int i = threadIdx.x; i < N1C; i += 256) { float t = y[i]; s += t * t; }
    red[threadIdx.x] = s; __syncthreads();
    for (int o = 128; o; o >>= 1) {
        if (threadIdx.x < o) red[threadIdx.x] += red[threadIdx.x + o];
        __syncthreads();
    }
    float nrm = sqrtf(red[0]);
    float inv = 1.f / nrm;
    for (int i = threadIdx.x; i < N1C; i += 256) v[i] = y[i] * inv;
    if (threadIdx.x == 0) g_lam = nrm;
}

__global__ void initX_k(float* X) {
    float a = 1.f / (1.02f * g_lam);
    int i = blockIdx.x * 256 + threadIdx.x;
    int rr = i / N1C, cc = i % N1C;
    X[i] = (rr == cc) ? a : 0.f;
}

// c[j] = sum_i A[i*N2C + j] * t[i]
__global__ void atmv_k(const float* __restrict__ A, const float* __restrict__ t,
                       float* __restrict__ c) {
    __shared__ float ts[N1C];
    for (int i = threadIdx.x; i < N1C; i += 256) ts[i] = t[i];
    __syncthreads();
    int j = blockIdx.x * 256 + threadIdx.x;
    float s = 0.f;
    for (int i = 0; i < N1C; i++) s += A[(size_t)i * N2C + j] * ts[i];
    c[j] = s;
}

__global__ void check_k() {
    if (g_ss <= EPS_C * EPS_C) g_flag = 1;
    g_ss = 0.f;
}

// ---------------- reduce kernels (float4) ----------------
// plain sum of ns partials
__global__ void reduce_sum_k(const float* __restrict__ P, float* __restrict__ out,
                             size_t stride4, int ns, const int* __restrict__ guard) {
    if (guard && *guard) return;
    size_t i = (size_t)blockIdx.x * 256 + threadIdx.x;
    const float4* p = (const float4*)P;
    float4 s = p[i];
    for (int sp = 1; sp < ns; sp++) {
        float4 t = p[(size_t)sp * stride4 + i];
        s.x += t.x; s.y += t.y; s.z += t.z; s.w += t.w;
    }
    ((float4*)out)[i] = s;
}

// Newton-Schulz update: out = 2*X - sum
__global__ void reduce_ns_k(const float* __restrict__ P, const float* __restrict__ X,
                            float* __restrict__ out, size_t stride4, int ns) {
    size_t i = (size_t)blockIdx.x * 256 + threadIdx.x;
    const float4* p = (const float4*)P;
    float4 s = p[i];
    for (int sp = 1; sp < ns; sp++) {
        float4 t = p[(size_t)sp * stride4 + i];
        s.x += t.x; s.y += t.y; s.z += t.z; s.w += t.w;
    }
    float4 x = ((const float4*)X)[i];
    float4 o;
    o.x = 2.f * x.x - s.x; o.y = 2.f * x.y - s.y;
    o.z = 2.f * x.z - s.z; o.w = 2.f * x.w - s.w;
    ((float4*)out)[i] = o;
}

// bias (+ optional relu): out = [relu](sum + bias[col])
template<bool RELU>
__global__ void reduce_bias_k(const float* __restrict__ P, const float* __restrict__ bias,
                              float* __restrict__ out, size_t stride4, int ns, int n4) {
    size_t i = (size_t)blockIdx.x * 256 + threadIdx.x;
    const float4* p = (const float4*)P;
    float4 s = p[i];
    for (int sp = 1; sp < ns; sp++) {
        float4 t = p[(size_t)sp * stride4 + i];
        s.x += t.x; s.y += t.y; s.z += t.z; s.w += t.w;
    }
    float4 b = ((const float4*)bias)[i % n4];
    s.x += b.x; s.y += b.y; s.z += b.z; s.w += b.w;
    if (RELU) {
        s.x = fmaxf(s.x, 0.f); s.y = fmaxf(s.y, 0.f);
        s.z = fmaxf(s.z, 0.f); s.w = fmaxf(s.w, 0.f);
    }
    ((float4*)out)[i] = s;
}

// z-update: zn = relu(z) - a*w + c[col] - (p0+p1); FIN: relu(zn) to out, no norm
template<bool FIN>
__global__ void zupd_k(const float* __restrict__ P, const float* __restrict__ zin,
                       const float* __restrict__ w, const float* __restrict__ c,
                       float* __restrict__ zout, float* __restrict__ sumsq,
                       const int* __restrict__ guard) {
    size_t i = (size_t)blockIdx.x * 256 + threadIdx.x;
    if (!FIN && guard && *guard) {          // converged: keep ping-pong consistent
        ((float4*)zout)[i] = ((const float4*)zin)[i];
        return;
    }
    const float4* p = (const float4*)P;
    float4 s = p[i];
    {   // 2 split-K partials, stride = BC*N2C/4 float4s
        float4 t = p[(size_t)(BC * (N2C / 4)) + i];
        s.x += t.x; s.y += t.y; s.z += t.z; s.w += t.w;
    }
    float4 z = ((const float4*)zin)[i];
    float4 ww = ((const float4*)w)[i];
    float4 cc = ((const float4*)c)[i & (N2C / 4 - 1)];
    float4 o;
    o.x = fmaxf(z.x, 0.f) - ALPHA_C * ww.x + cc.x - s.x;
    o.y = fmaxf(z.y, 0.f) - ALPHA_C * ww.y + cc.y - s.y;
    o.z = fmaxf(z.z, 0.f) - ALPHA_C * ww.z + cc.z - s.z;
    o.w = fmaxf(z.w, 0.f) - ALPHA_C * ww.w + cc.w - s.w;
    if (FIN) {
        o.x = fmaxf(o.x, 0.f); o.y = fmaxf(o.y, 0.f);
        o.z = fmaxf(o.z, 0.f); o.w = fmaxf(o.w, 0.f);
        ((float4*)zout)[i] = o;
    } else {
        ((float4*)zout)[i] = o;
        float dx = o.x - z.x, dy = o.y - z.y, dz = o.z - z.z, dw = o.w - z.w;
        float ls = dx * dx + dy * dy + dz * dz + dw * dw;
        __shared__ float red[256];
        red[threadIdx.x] = ls;
        __syncthreads();
        for (int o2 = 128; o2; o2 >>= 1) {
            if (threadIdx.x < o2) red[threadIdx.x] += red[threadIdx.x + o2];
            __syncthreads();
        }
        if (threadIdx.x == 0) atomicAdd(sumsq, red[0]);
    }
}

// ---------------- the SGEMM ----------------
// C[m][n] = sum_k A[m][k]*B[k][n],  M=gridDim.y*128, N=gridDim.x*128
// A_KC: A[m][k] = Ag[m*lda+k] (k-contig), else Ag[k*lda+m] (m-contig)
// B_NC: B[k][n] = Bg[k*ldb+n] (n-contig), else Bg[n*ldb+k] (k-contig)
// B_U (only with !B_NC): B = |Bg| - ALPHA*Bw
// SPLIT: write to partial buffer at blockIdx.z offset
template<bool A_KC, bool B_NC, bool B_U, bool SPLIT>
__global__ void __launch_bounds__(NTHR)
gemm_k(const float* __restrict__ Ag, int lda,
       const float* __restrict__ Bg, int ldb,
       const float* __restrict__ Bw,
       float* __restrict__ Cg, int N, int kchunk,
       const int* __restrict__ guard)
{
    if (guard && *guard) return;

    __shared__ __align__(16) float As[2][BK][BM + PAD];
    __shared__ __align__(16) float Bs[2][BK][BN + PAD];

    const int tid = threadIdx.x;
    const int m0 = blockIdx.y * BM;
    const int n0 = blockIdx.x * BN;
    const int k0 = blockIdx.z * kchunk;
    const int kend = k0 + kchunk;
    const int tx = tid & 15;
    const int ty = tid >> 4;

    float4 ra[2], rb[2];

    auto loadA = [&](int kb) {
        #pragma unroll
        for (int v = 0; v < 2; v++) {
            int id = v * 256 + tid;
            if (A_KC) {
                int m = id >> 2, kq = (id & 3) * 4;
                ra[v] = *(const float4*)&Ag[(size_t)(m0 + m) * lda + kb + kq];
            } else {
                int kk = id >> 5, mq = (id & 31) * 4;
                ra[v] = *(const float4*)&Ag[(size_t)(kb + kk) * lda + m0 + mq];
            }
        }
    };
    auto storeA = [&](int buf) {
        #pragma unroll
        for (int v = 0; v < 2; v++) {
            int id = v * 256 + tid;
            if (A_KC) {
                int m = id >> 2, kq = (id & 3) * 4;
                As[buf][kq + 0][m] = ra[v].x;
                As[buf][kq + 1][m] = ra[v].y;
                As[buf][kq + 2][m] = ra[v].z;
                As[buf][kq + 3][m] = ra[v].w;
            } else {
                int kk = id >> 5, mq = (id & 31) * 4;
                *(float4*)&As[buf][kk][mq] = ra[v];
            }
        }
    };
    auto loadB = [&](int kb) {
        #pragma unroll
        for (int v = 0; v < 2; v++) {
            int id = v * 256 + tid;
            if (B_NC) {
                int kk = id >> 5, nq = (id & 31) * 4;
                rb[v] = *(const float4*)&Bg[(size_t)(kb + kk) * ldb + n0 + nq];
            } else {
                int n = id >> 2, kq = (id & 3) * 4;
                size_t gi = (size_t)(n0 + n) * ldb + kb + kq;
                float4 z = *(const float4*)&Bg[gi];
                if (B_U) {
                    float4 w = *(const float4*)&Bw[gi];
                    z.x = fabsf(z.x) - ALPHA_C * w.x;
                    z.y = fabsf(z.y) - ALPHA_C * w.y;
                    z.z = fabsf(z.z) - ALPHA_C * w.z;
                    z.w = fabsf(z.w) - ALPHA_C * w.w;
                }
                rb[v] = z;
            }
        }
    };
    auto storeB = [&](int buf) {
        #pragma unroll
        for (int v = 0; v < 2; v++) {
            int id = v * 256 + tid;
            if (B_NC) {
                int kk = id >> 5, nq = (id & 31) * 4;
                *(float4*)&Bs[buf][kk][nq] = rb[v];
            } else {
                int n = id >> 2, kq = (id & 3) * 4;
                Bs[buf][kq + 0][n] = rb[v].x;
                Bs[buf][kq + 1][n] = rb[v].y;
                Bs[buf][kq + 2][n] = rb[v].z;
                Bs[buf][kq + 3][n] = rb[v].w;
            }
        }
    };

    float acc[8][8];
    #pragma unroll
    for (int i = 0; i < 8; i++)
        #pragma unroll
        for (int j = 0; j < 8; j++) acc[i][j] = 0.f;

    loadA(k0); loadB(k0);
    storeA(0); storeB(0);
    __syncthreads();

    int buf = 0;
    for (int kb = k0; kb < kend; kb += BK) {
        bool nxt = (kb + BK) < kend;
        if (nxt) { loadA(kb + BK); loadB(kb + BK); }
        #pragma unroll
        for (int kk = 0; kk < BK; kk++) {
            float a[8], b[8];
            *(float4*)(a)     = *(const float4*)&As[buf][kk][ty * 4];
            *(float4*)(a + 4) = *(const float4*)&As[buf][kk][ty * 4 + 64];
            *(float4*)(b)     = *(const float4*)&Bs[buf][kk][tx * 4];
            *(float4*)(b + 4) = *(const float4*)&Bs[buf][kk][tx * 4 + 64];
            #pragma unroll
            for (int i = 0; i < 8; i++)
                #pragma unroll
                for (int j = 0; j < 8; j++)
                    acc[i][j] = fmaf(a[i], b[j], acc[i][j]);
        }
        if (nxt) {
            storeA(buf ^ 1); storeB(buf ^ 1);
            __syncthreads();
            buf ^= 1;
        }
    }

    size_t off = SPLIT ? (size_t)blockIdx.z * ((size_t)gridDim.y * BM) * N : 0;
    #pragma unroll
    for (int fi = 0; fi < 2; fi++)
        #pragma unroll
        for (int i = 0; i < 4; i++) {
            int m = m0 + ty * 4 + fi * 64 + i;
            #pragma unroll
            for (int fj = 0; fj < 2; fj++) {
                int n = n0 + tx * 4 + fj * 64;
                float4 v;
                v.x = acc[fi * 4 + i][fj * 4 + 0];
                v.y = acc[fi * 4 + i][fj * 4 + 1];
                v.z = acc[fi * 4 + i][fj * 4 + 2];
                v.w = acc[fi * 4 + i][fj * 4 + 3];
                *(float4*)&Cg[off + (size_t)m * N + n] = v;
            }
        }
}

extern "C" void kernel_launch(void* const* d_in, const int* in_sizes, int n_in,
                              void* d_out, int out_size) {
    (void)in_sizes; (void)n_in; (void)out_size;
    const float* dd  = (const float*)d_in[0];
    const float* dA  = (const float*)d_in[1];
    const float* dB  = (const float*)d_in[2];
    const float* dW1 = (const float*)d_in[3];
    const float* db1 = (const float*)d_in[4];
    const float* dW2 = (const float*)d_in[5];
    const float* db2 = (const float*)d_in[6];
    const float* dz0 = (const float*)d_in[7];
    float* out = (float*)d_out;

    void* p;
    cudaGetSymbolAddress(&p, g_S);  float* S    = (float*)p;
    cudaGetSymbolAddress(&p, g_Xa); float* Xa   = (float*)p;
    cudaGetSymbolAddress(&p, g_Xb); float* Xb   = (float*)p;
    cudaGetSymbolAddress(&p, g_T);  float* Tm   = (float*)p;
    cudaGetSymbolAddress(&p, g_G);  float* G    = (float*)p;
    cudaGetSymbolAddress(&p, g_c);  float* c    = (float*)p;
    cudaGetSymbolAddress(&p, g_tv); float* tv   = (float*)p;
    cudaGetSymbolAddress(&p, g_v);  float* v    = (float*)p;
    cudaGetSymbolAddress(&p, g_y);  float* y    = (float*)p;
    cudaGetSymbolAddress(&p, g_h);  float* h    = (float*)p;
    cudaGetSymbolAddress(&p, g_w);  float* wbuf = (float*)p;
    cudaGetSymbolAddress(&p, g_za); float* za   = (float*)p;
    cudaGetSymbolAddress(&p, g_zb); float* zbb  = (float*)p;
    cudaGetSymbolAddress(&p, g_r);  float* r    = (float*)p;
    cudaGetSymbolAddress(&p, g_P);  float* P    = (float*)p;
    cudaGetSymbolAddress(&p, g_ss); float* ss   = (float*)p;
    cudaGetSymbolAddress(&p, g_flag); int* flag = (int*)p;

    init_k<<<1, 1>>>();
    copy4_k<<<(BC * N2C / 4) / 256, 256>>>((float4*)za, (const float4*)dz0);

    // S = A A^T : M=N=1024, K=4096, split 4
    {
        dim3 g(N1C / BN, N1C / BM, 4);
        gemm_k<true, false, false, true><<<g, NTHR>>>(
            dA, N2C, dA, N2C, nullptr, P, N1C, N2C / 4, nullptr);
        reduce_sum_k<<<(N1C * N1C / 4) / 256, 256>>>(P, S, (size_t)N1C * N1C / 4, 4, nullptr);
    }

    // power iteration for lambda_max(S)
    fill_k<<<N1C / 256, 256>>>(v, 0.03125f, N1C);
    for (int i = 0; i < PI_ITERS; i++) {
        spmv_k<<<N1C / 8, dim3(32, 8)>>>(S, v, y);
        pi_norm_k<<<1, 256>>>(y, v);
    }
    initX_k<<<(N1C * N1C) / 256, 256>>>(Xa);

    // Newton-Schulz: X <- 2X - X(SX), split 2 each GEMM
    float* Xc = Xa; float* Xn = Xb;
    {
        dim3 g(N1C / BN, N1C / BM, 2);
        size_t s4 = (size_t)N1C * N1C / 4;
        for (int i = 0; i < NS_ITERS; i++) {
            gemm_k<true, true, false, true><<<g, NTHR>>>(
                S, N1C, Xc, N1C, nullptr, P, N1C, N1C / 2, nullptr);
            reduce_sum_k<<<(N1C * N1C / 4) / 256, 256>>>(P, Tm, s4, 2, nullptr);
            gemm_k<true, true, false, true><<<g, NTHR>>>(
                Xc, N1C, Tm, N1C, nullptr, P, N1C, N1C / 2, nullptr);
            reduce_ns_k<<<(N1C * N1C / 4) / 256, 256>>>(P, Xc, Xn, s4, 2);
            float* t2 = Xc; Xc = Xn; Xn = t2;
        }
    }

    // c = A^T (X b)
    spmv_k<<<N1C / 8, dim3(32, 8)>>>(Xc, dB, tv);
    atmv_k<<<N2C / 256, 256>>>(dA, tv, c);

    // G = A^T X : M=4096, N=1024, K=1024, 256 blocks, no split
    {
        dim3 g(N1C / BN, N2C / BM, 1);
        gemm_k<false, true, false, false><<<g, NTHR>>>(
            dA, N2C, Xc, N1C, nullptr, G, N1C, N1C, nullptr);
    }

    // MLP: h = relu(d W1 + b1), split 4 ; w = h W2 + b2, split 2
    {
        dim3 g1(HC / BN, BC / BM, 4);
        gemm_k<true, true, false, true><<<g1, NTHR>>>(
            dd, DC, dW1, HC, nullptr, P, HC, DC / 4, nullptr);
        reduce_bias_k<true><<<(BC * HC / 4) / 256, 256>>>(
            P, db1, h, (size_t)BC * HC / 4, 4, HC / 4);
        dim3 g2(N2C / BN, BC / BM, 2);
        gemm_k<true, true, false, true><<<g2, NTHR>>>(
            h, HC, dW2, N2C, nullptr, P, N2C, HC / 2, nullptr);
        reduce_bias_k<false><<<(BC * N2C / 4) / 256, 256>>>(
            P, db2, wbuf, (size_t)BC * N2C / 4, 2, N2C / 4);
    }

    // DYS fixed-point loop: 50 guarded iterations
    dim3 gr(BC / BN, N1C / BM, 8);     // r = A u^T  (M=1024,N=256,K=4096, split 8)
    dim3 gz(N2C / BN, BC / BM, 2);     // (G r)^T    (M=256,N=4096,K=1024, split 2)
    size_t r4 = (size_t)N1C * BC / 4;
    float* zb2[2] = { za, zbb };
    for (int it = 1; it <= 50; ++it) {
        const float* zin = zb2[(it - 1) & 1];
        float* zout = zb2[it & 1];
        gemm_k<true, false, true, true><<<gr, NTHR>>>(
            dA, N2C, zin, N2C, wbuf, P, BC, N2C / 8, flag);
        reduce_sum_k<<<(N1C * BC / 4) / 256, 256>>>(P, r, r4, 8, flag);
        gemm_k<false, false, false, true><<<gz, NTHR>>>(
            r, BC, G, N1C, nullptr, P, N2C, N1C / 2, flag);
        zupd_k<false><<<(BC * N2C / 4) / 256, 256>>>(P, zin, wbuf, c, zout, ss, flag);
        check_k<<<1, 1>>>();
    }

    // final training-branch step (unguarded), relu into d_out
    gemm_k<true, false, true, true><<<gr, NTHR>>>(
        dA, N2C, za, N2C, wbuf, P, BC, N2C / 8, nullptr);
    reduce_sum_k<<<(N1C * BC / 4) / 256, 256>>>(P, r, r4, 8, nullptr);
    gemm_k<false, false, false, true><<<gz, NTHR>>>(
        r, BC, G, N1C, nullptr, P, N2C, N1C / 2, nullptr);
    zupd_k<true><<<(BC * N2C / 4) / 256, 256>>>(P, za, wbuf, c, out, nullptr, nullptr);
}

// round 4
// speedup vs baseline: 2.1660x; 1.1633x over previous
#include <cuda_runtime.h>
#include <math.h>
#include <stdint.h>

// ----------------------------------------------------------------------------
// DYS_opt_net on tensor cores (3xTF32 mma.sync.m16n8k8).
// z' = relu(z) - a*w + c - (G (A u^T))^T,  u = |z| - a*w
// G = A^T (A A^T)^{-1} via Newton-Schulz (symmetric form X'=2X-(XS)X); c = G b.
// All GEMMs share one NT layout: A [m][k] k-contig, B [n][k] k-contig.
// ----------------------------------------------------------------------------

#define N1C 1024
#define N2C 4096
#define BC  256
#define DC  512
#define HC  2048

#define ALPHA_C 0.05f
#define EPS_C   0.01f
#define NS_ITERS 9
#define PI_ITERS 12

#define NTHR 256
#define SMEM_BYTES 98304        // 2 bufs * (A hi/lo + B hi/lo) * 128*24*4

__device__ float g_S  [(size_t)N1C*N1C];
__device__ float g_Xa [(size_t)N1C*N1C];
__device__ float g_Xb [(size_t)N1C*N1C];
__device__ float g_T  [(size_t)N1C*N1C];
__device__ float g_G  [(size_t)N2C*N1C];
__device__ float g_At [(size_t)N2C*N1C];
__device__ float g_W1t[(size_t)HC*DC];
__device__ float g_W2t[(size_t)N2C*HC];
__device__ float g_c  [N2C];
__device__ float g_tv [N1C];
__device__ float g_v  [N1C];
__device__ float g_y  [N1C];
__device__ float g_h  [(size_t)BC*HC];
__device__ float g_w  [(size_t)BC*N2C];
__device__ float g_za [(size_t)BC*N2C];
__device__ float g_zb [(size_t)BC*N2C];
__device__ float g_rt [(size_t)BC*N1C];
__device__ float g_P  [(size_t)4*1024*1024];   // split-K partials (16MB)
__device__ float g_lam;
__device__ float g_ss;
__device__ int   g_flag;
__device__ int   g_cnt;

__global__ void init_k() { g_ss = 0.f; g_flag = 0; g_cnt = 0; }

__global__ void copy4_k(float4* __restrict__ dst, const float4* __restrict__ src) {
    int i = blockIdx.x * blockDim.x + threadIdx.x;
    dst[i] = src[i];
}

__global__ void fill_k(float* v, float val, int n) {
    int i = blockIdx.x * blockDim.x + threadIdx.x;
    if (i < n) v[i] = val;
}

__global__ void spmv_k(const float* __restrict__ M_, const float* __restrict__ v,
                       float* __restrict__ y) {
    int row = blockIdx.x * 8 + threadIdx.y;
    const float* mr = M_ + (size_t)row * N1C;
    float s = 0.f;
    for (int j = threadIdx.x; j < N1C; j += 32) s += mr[j] * v[j];
    #pragma unroll
    for (int o = 16; o; o >>= 1) s += __shfl_xor_sync(0xffffffffu, s, o);
    if (threadIdx.x == 0) y[row] = s;
}

__global__ void pi_norm_k(const float* __restrict__ y, float* __restrict__ v) {
    __shared__ float red[256];
    float s = 0.f;
    for (int i = threadIdx.x; i < N1C; i += 256) { float t = y[i]; s += t * t; }
    red[threadIdx.x] = s; __syncthreads();
    for (int o = 128; o; o >>= 1) {
        if (threadIdx.x < o) red[threadIdx.x] += red[threadIdx.x + o];
        __syncthreads();
    }
    float nrm = sqrtf(red[0]);
    float inv = 1.f / nrm;
    for (int i = threadIdx.x; i < N1C; i += 256) v[i] = y[i] * inv;
    if (threadIdx.x == 0) g_lam = nrm;
}

__global__ void initX_k(float* X) {
    float a = 1.8f / g_lam;                 // ~2/(lmax+lmin), lmin ~ lmax/9
    int i = blockIdx.x * 256 + threadIdx.x;
    int rr = i / N1C, cc = i % N1C;
    X[i] = (rr == cc) ? a : 0.f;
}

__global__ void atmv_k(const float* __restrict__ A, const float* __restrict__ t,
                       float* __restrict__ c) {
    __shared__ float ts[N1C];
    for (int i = threadIdx.x; i < N1C; i += 256) ts[i] = t[i];
    __syncthreads();
    int j = blockIdx.x * 256 + threadIdx.x;
    float s = 0.f;
    for (int i = 0; i < N1C; i++) s += A[(size_t)i * N2C + j] * ts[i];
    c[j] = s;
}

// dst[c][r] = src[r][c]; src is R x C. grid (C/32, R/32), block (32,8)
__global__ void transp_k(float* __restrict__ dst, const float* __restrict__ src,
                         int R, int C) {
    __shared__ float t[32][33];
    int bx = blockIdx.x * 32, by = blockIdx.y * 32;
    #pragma unroll
    for (int i = 0; i < 4; i++) {
        int r = by + threadIdx.y + i * 8;
        t[threadIdx.y + i * 8][threadIdx.x] = src[(size_t)r * C + bx + threadIdx.x];
    }
    __syncthreads();
    #pragma unroll
    for (int i = 0; i < 4; i++) {
        int r = bx + threadIdx.y + i * 8;
        dst[(size_t)r * R + by + threadIdx.x] = t[threadIdx.x][threadIdx.y + i * 8];
    }
}

// ---------------- reduce kernels ----------------
__global__ void reduce_sum_k(const float* __restrict__ P, float* __restrict__ out,
                             size_t stride4, int ns, const int* __restrict__ guard) {
    if (guard && *guard) return;
    size_t i = (size_t)blockIdx.x * 256 + threadIdx.x;
    const float4* p = (const float4*)P;
    float4 s = p[i];
    for (int sp = 1; sp < ns; sp++) {
        float4 t = p[(size_t)sp * stride4 + i];
        s.x += t.x; s.y += t.y; s.z += t.z; s.w += t.w;
    }
    ((float4*)out)[i] = s;
}

__global__ void reduce_ns_k(const float* __restrict__ P, const float* __restrict__ X,
                            float* __restrict__ out, size_t stride4, int ns) {
    size_t i = (size_t)blockIdx.x * 256 + threadIdx.x;
    const float4* p = (const float4*)P;
    float4 s = p[i];
    for (int sp = 1; sp < ns; sp++) {
        float4 t = p[(size_t)sp * stride4 + i];
        s.x += t.x; s.y += t.y; s.z += t.z; s.w += t.w;
    }
    float4 x = ((const float4*)X)[i];
    float4 o;
    o.x = 2.f * x.x - s.x; o.y = 2.f * x.y - s.y;
    o.z = 2.f * x.z - s.z; o.w = 2.f * x.w - s.w;
    ((float4*)out)[i] = o;
}

template<bool RELU>
__global__ void reduce_bias_k(const float* __restrict__ P, const float* __restrict__ bias,
                              float* __restrict__ out, size_t stride4, int ns, int n4) {
    size_t i = (size_t)blockIdx.x * 256 + threadIdx.x;
    const float4* p = (const float4*)P;
    float4 s = p[i];
    for (int sp = 1; sp < ns; sp++) {
        float4 t = p[(size_t)sp * stride4 + i];
        s.x += t.x; s.y += t.y; s.z += t.z; s.w += t.w;
    }
    float4 b = ((const float4*)bias)[i % n4];
    s.x += b.x; s.y += b.y; s.z += b.z; s.w += b.w;
    if (RELU) {
        s.x = fmaxf(s.x, 0.f); s.y = fmaxf(s.y, 0.f);
        s.z = fmaxf(s.z, 0.f); s.w = fmaxf(s.w, 0.f);
    }
    ((float4*)out)[i] = s;
}

// sum 8 partials of r [N1C][BC] and write transposed rt [BC][N1C]
__global__ void reduce_tr_k(const float* __restrict__ P, float* __restrict__ rt,
                            const int* __restrict__ guard) {
    if (guard && *guard) return;
    __shared__ float t[32][33];
    int bm = blockIdx.x * 32;      // over N1C
    int bb = blockIdx.y * 32;      // over BC
    #pragma unroll
    for (int i = 0; i < 4; i++) {
        int m = bm + threadIdx.y + i * 8;
        size_t idx = (size_t)m * BC + bb + threadIdx.x;
        float s = 0.f;
        #pragma unroll
        for (int sp = 0; sp < 8; sp++) s += P[(size_t)sp * N1C * BC + idx];
        t[threadIdx.y + i * 8][threadIdx.x] = s;
    }
    __syncthreads();
    #pragma unroll
    for (int i = 0; i < 4; i++) {
        int b = bb + threadIdx.y + i * 8;
        rt[(size_t)b * N1C + bm + threadIdx.x] = t[threadIdx.x][threadIdx.y + i * 8];
    }
}

// z-update with fused convergence check (FIN: relu into out, unguarded)
template<bool FIN>
__global__ void zupd_k(const float* __restrict__ P, const float* __restrict__ zin,
                       const float* __restrict__ w, const float* __restrict__ c,
                       float* __restrict__ zout, const int* __restrict__ guard) {
    size_t i = (size_t)blockIdx.x * 256 + threadIdx.x;
    if (!FIN && guard && *guard) {
        ((float4*)zout)[i] = ((const float4*)zin)[i];
        return;
    }
    const float4* p = (const float4*)P;
    float4 s = p[i];
    {
        float4 t = p[(size_t)(BC * (N2C / 4)) + i];
        s.x += t.x; s.y += t.y; s.z += t.z; s.w += t.w;
    }
    float4 z = ((const float4*)zin)[i];
    float4 ww = ((const float4*)w)[i];
    float4 cc = ((const float4*)c)[i & (N2C / 4 - 1)];
    float4 o;
    o.x = fmaxf(z.x, 0.f) - ALPHA_C * ww.x + cc.x - s.x;
    o.y = fmaxf(z.y, 0.f) - ALPHA_C * ww.y + cc.y - s.y;
    o.z = fmaxf(z.z, 0.f) - ALPHA_C * ww.z + cc.z - s.z;
    o.w = fmaxf(z.w, 0.f) - ALPHA_C * ww.w + cc.w - s.w;
    if (FIN) {
        o.x = fmaxf(o.x, 0.f); o.y = fmaxf(o.y, 0.f);
        o.z = fmaxf(o.z, 0.f); o.w = fmaxf(o.w, 0.f);
        ((float4*)zout)[i] = o;
    } else {
        ((float4*)zout)[i] = o;
        float dx = o.x - z.x, dy = o.y - z.y, dz = o.z - z.z, dw = o.w - z.w;
        float ls = dx * dx + dy * dy + dz * dz + dw * dw;
        __shared__ float red[256];
        red[threadIdx.x] = ls;
        __syncthreads();
        for (int o2 = 128; o2; o2 >>= 1) {
            if (threadIdx.x < o2) red[threadIdx.x] += red[threadIdx.x + o2];
            __syncthreads();
        }
        if (threadIdx.x == 0) {
            atomicAdd(&g_ss, red[0]);
            __threadfence();
            int t = atomicAdd(&g_cnt, 1);
            if (t == (int)gridDim.x - 1) {          // last block: do the check
                if (g_ss <= EPS_C * EPS_C) g_flag = 1;
                g_ss = 0.f;
                g_cnt = 0;
            }
        }
    }
}

// ---------------- 3xTF32 tensor-core GEMM ----------------
__device__ __forceinline__ void split_tf32(float x, uint32_t& hi, uint32_t& lo) {
    asm("cvt.rna.tf32.f32 %0, %1;" : "=r"(hi) : "f"(x));
    float hf = __uint_as_float(hi);
    asm("cvt.rna.tf32.f32 %0, %1;" : "=r"(lo) : "f"(x - hf));
}

__device__ __forceinline__ void mma8(float* c, const uint32_t* a, const uint32_t* b) {
    asm("mma.sync.aligned.m16n8k8.row.col.f32.tf32.tf32.f32 "
        "{%0,%1,%2,%3}, {%4,%5,%6,%7}, {%8,%9}, {%0,%1,%2,%3};"
        : "+f"(c[0]), "+f"(c[1]), "+f"(c[2]), "+f"(c[3])
        : "r"(a[0]), "r"(a[1]), "r"(a[2]), "r"(a[3]), "r"(b[0]), "r"(b[1]));
}

// C[m][n] = sum_k A[m][k] * B[n][k]   (both k-contig; BM=BN=128, BK=16)
// B_U: B element = |Bg| - ALPHA*Bw.  SPLIT: write partials per blockIdx.z.
#define TSTR 24          // smem row stride in floats (16 k + 8 pad)
#define TBUF 3072        // 128 * 24
template<bool B_U, bool SPLIT>
__global__ void __launch_bounds__(NTHR)
tgemm_k(const float* __restrict__ Ag, int lda,
        const float* __restrict__ Bg, int ldb,
        const float* __restrict__ Bw,
        float* __restrict__ Cg, int N, int kchunk,
        const int* __restrict__ guard)
{
    if (guard && *guard) return;
    extern __shared__ uint32_t sm[];

    const int tid = threadIdx.x;
    const int wid = tid >> 5, lane = tid & 31;
    const int wm = wid >> 2, wn = wid & 3;      // 2 x 4 warp grid
    const int gr = lane >> 2, qc = lane & 3;
    const int m0 = blockIdx.y * 128, n0 = blockIdx.x * 128;
    const int k0 = blockIdx.z * kchunk, kend = k0 + kchunk;

    float acc[4][4][4];
    #pragma unroll
    for (int f = 0; f < 4; f++)
        #pragma unroll
        for (int g = 0; g < 4; g++)
            #pragma unroll
            for (int e = 0; e < 4; e++) acc[f][g][e] = 0.f;

    float4 ra[2], rb[2];

    auto loadG = [&](int kb) {
        #pragma unroll
        for (int v = 0; v < 2; v++) {
            int id = v * 256 + tid;
            int row = id >> 2, kq = (id & 3) * 4;
            ra[v] = *(const float4*)&Ag[(size_t)(m0 + row) * lda + kb + kq];
            size_t gi = (size_t)(n0 + row) * ldb + kb + kq;
            float4 z = *(const float4*)&Bg[gi];
            if (B_U) {
                float4 w = *(const float4*)&Bw[gi];
                z.x = fabsf(z.x) - ALPHA_C * w.x;
                z.y = fabsf(z.y) - ALPHA_C * w.y;
                z.z = fabsf(z.z) - ALPHA_C * w.z;
                z.w = fabsf(z.w) - ALPHA_C * w.w;
            }
            rb[v] = z;
        }
    };
    auto stage = [&](int buf) {
        uint32_t* AH = sm + buf * (4 * TBUF);
        uint32_t* AL = AH + TBUF;
        uint32_t* BH = AL + TBUF;
        uint32_t* BL = BH + TBUF;
        #pragma unroll
        for (int v = 0; v < 2; v++) {
            int id = v * 256 + tid;
            int row = id >> 2, kq = (id & 3) * 4;
            uint4 h, l;
            split_tf32(ra[v].x, h.x, l.x); split_tf32(ra[v].y, h.y, l.y);
            split_tf32(ra[v].z, h.z, l.z); split_tf32(ra[v].w, h.w, l.w);
            *(uint4*)&AH[row * TSTR + kq] = h;
            *(uint4*)&AL[row * TSTR + kq] = l;
            split_tf32(rb[v].x, h.x, l.x); split_tf32(rb[v].y, h.y, l.y);
            split_tf32(rb[v].z, h.z, l.z); split_tf32(rb[v].w, h.w, l.w);
            *(uint4*)&BH[row * TSTR + kq] = h;
            *(uint4*)&BL[row * TSTR + kq] = l;
        }
    };

    loadG(k0);
    stage(0);
    __syncthreads();

    int buf = 0;
    for (int kb = k0; kb < kend; kb += 16) {
        bool nxt = (kb + 16) < kend;
        if (nxt) loadG(kb + 16);

        const uint32_t* AH = sm + buf * (4 * TBUF);
        const uint32_t* AL = AH + TBUF;
        const uint32_t* BH = AL + TBUF;
        const uint32_t* BL = BH + TBUF;

        #pragma unroll
        for (int ks = 0; ks < 2; ks++) {
            uint32_t ah[4][4], al[4][4], bh[4][2], bl[4][2];
            #pragma unroll
            for (int f = 0; f < 4; f++) {
                int r0 = wm * 64 + f * 16 + gr;
                int off = r0 * TSTR + ks * 8 + 2 * qc;
                uint2 t0 = *(const uint2*)&AH[off];
                uint2 t1 = *(const uint2*)&AH[off + 8 * TSTR];
                ah[f][0] = t0.x; ah[f][2] = t0.y; ah[f][1] = t1.x; ah[f][3] = t1.y;
                t0 = *(const uint2*)&AL[off];
                t1 = *(const uint2*)&AL[off + 8 * TSTR];
                al[f][0] = t0.x; al[f][2] = t0.y; al[f][1] = t1.x; al[f][3] = t1.y;
            }
            #pragma unroll
            for (int g = 0; g < 4; g++) {
                int cl = wn * 32 + g * 8 + gr;
                int off = cl * TSTR + ks * 8 + 2 * qc;
                uint2 t = *(const uint2*)&BH[off];
                bh[g][0] = t.x; bh[g][1] = t.y;
                t = *(const uint2*)&BL[off];
                bl[g][0] = t.x; bl[g][1] = t.y;
            }
            #pragma unroll
            for (int f = 0; f < 4; f++)
                #pragma unroll
                for (int g = 0; g < 4; g++) {
                    mma8(acc[f][g], ah[f], bh[g]);
                    mma8(acc[f][g], ah[f], bl[g]);
                    mma8(acc[f][g], al[f], bh[g]);
                }
        }

        if (nxt) {
            stage(buf ^ 1);
            __syncthreads();
            buf ^= 1;
        }
    }

    size_t off = SPLIT ? (size_t)blockIdx.z * ((size_t)gridDim.y * 128) * N : 0;
    #pragma unroll
    for (int f = 0; f < 4; f++) {
        int m = m0 + wm * 64 + f * 16 + gr;
        #pragma unroll
        for (int g = 0; g < 4; g++) {
            int n = n0 + wn * 32 + g * 8 + 2 * qc;
            float2 v0 = make_float2(acc[f][g][0], acc[f][g][1]);
            float2 v1 = make_float2(acc[f][g][2], acc[f][g][3]);
            *(float2*)&Cg[off + (size_t)m * N + n] = v0;
            *(float2*)&Cg[off + (size_t)(m + 8) * N + n] = v1;
        }
    }
}

extern "C" void kernel_launch(void* const* d_in, const int* in_sizes, int n_in,
                              void* d_out, int out_size) {
    (void)in_sizes; (void)n_in; (void)out_size;
    const float* dd  = (const float*)d_in[0];
    const float* dA  = (const float*)d_in[1];
    const float* dB  = (const float*)d_in[2];
    const float* dW1 = (const float*)d_in[3];
    const float* db1 = (const float*)d_in[4];
    const float* dW2 = (const float*)d_in[5];
    const float* db2 = (const float*)d_in[6];
    const float* dz0 = (const float*)d_in[7];
    float* out = (float*)d_out;

    void* p;
    cudaGetSymbolAddress(&p, g_S);   float* S    = (float*)p;
    cudaGetSymbolAddress(&p, g_Xa);  float* Xa   = (float*)p;
    cudaGetSymbolAddress(&p, g_Xb);  float* Xb   = (float*)p;
    cudaGetSymbolAddress(&p, g_T);   float* Tm   = (float*)p;
    cudaGetSymbolAddress(&p, g_G);   float* G    = (float*)p;
    cudaGetSymbolAddress(&p, g_At);  float* At   = (float*)p;
    cudaGetSymbolAddress(&p, g_W1t); float* W1t  = (float*)p;
    cudaGetSymbolAddress(&p, g_W2t); float* W2t  = (float*)p;
    cudaGetSymbolAddress(&p, g_c);   float* c    = (float*)p;
    cudaGetSymbolAddress(&p, g_tv);  float* tv   = (float*)p;
    cudaGetSymbolAddress(&p, g_v);   float* v    = (float*)p;
    cudaGetSymbolAddress(&p, g_y);   float* y    = (float*)p;
    cudaGetSymbolAddress(&p, g_h);   float* h    = (float*)p;
    cudaGetSymbolAddress(&p, g_w);   float* wbuf = (float*)p;
    cudaGetSymbolAddress(&p, g_za);  float* za   = (float*)p;
    cudaGetSymbolAddress(&p, g_zb);  float* zbb  = (float*)p;
    cudaGetSymbolAddress(&p, g_rt);  float* rt   = (float*)p;
    cudaGetSymbolAddress(&p, g_P);   float* P    = (float*)p;
    cudaGetSymbolAddress(&p, g_flag); int* flag  = (int*)p;

    cudaFuncSetAttribute(tgemm_k<false, true>,
                         cudaFuncAttributeMaxDynamicSharedMemorySize, SMEM_BYTES);
    cudaFuncSetAttribute(tgemm_k<true, true>,
                         cudaFuncAttributeMaxDynamicSharedMemorySize, SMEM_BYTES);
    cudaFuncSetAttribute(tgemm_k<false, false>,
                         cudaFuncAttributeMaxDynamicSharedMemorySize, SMEM_BYTES);

    init_k<<<1, 1>>>();
    copy4_k<<<(BC * N2C / 4) / 256, 256>>>((float4*)za, (const float4*)dz0);

    // transposes: At = A^T, W1t = W1^T, W2t = W2^T
    transp_k<<<dim3(N2C / 32, N1C / 32), dim3(32, 8)>>>(At, dA, N1C, N2C);
    transp_k<<<dim3(HC / 32, DC / 32), dim3(32, 8)>>>(W1t, dW1, DC, HC);
    transp_k<<<dim3(N2C / 32, HC / 32), dim3(32, 8)>>>(W2t, dW2, HC, N2C);

    // S = A A^T : M=N=1024, K=4096, split 2
    {
        dim3 g(N1C / 128, N1C / 128, 2);
        tgemm_k<false, true><<<g, NTHR, SMEM_BYTES>>>(
            dA, N2C, dA, N2C, nullptr, P, N1C, N2C / 2, nullptr);
        reduce_sum_k<<<(N1C * N1C / 4) / 256, 256>>>(P, S, (size_t)N1C * N1C / 4, 2, nullptr);
    }

    // power iteration for lambda_max(S)
    fill_k<<<N1C / 256, 256>>>(v, 0.03125f, N1C);
    for (int i = 0; i < PI_ITERS; i++) {
        spmv_k<<<N1C / 8, dim3(32, 8)>>>(S, v, y);
        pi_norm_k<<<1, 256>>>(y, v);
    }
    initX_k<<<(N1C * N1C) / 256, 256>>>(Xa);

    // Newton-Schulz (symmetric): T2 = X S ; X' = 2X - T2 X
    float* Xc = Xa; float* Xn = Xb;
    {
        dim3 g(N1C / 128, N1C / 128, 2);
        size_t s4 = (size_t)N1C * N1C / 4;
        for (int i = 0; i < NS_ITERS; i++) {
            tgemm_k<false, true><<<g, NTHR, SMEM_BYTES>>>(
                Xc, N1C, S, N1C, nullptr, P, N1C, N1C / 2, nullptr);
            reduce_sum_k<<<(N1C * N1C / 4) / 256, 256>>>(P, Tm, s4, 2, nullptr);
            tgemm_k<false, true><<<g, NTHR, SMEM_BYTES>>>(
                Tm, N1C, Xc, N1C, nullptr, P, N1C, N1C / 2, nullptr);
            reduce_ns_k<<<(N1C * N1C / 4) / 256, 256>>>(P, Xc, Xn, s4, 2);
            float* t2 = Xc; Xc = Xn; Xn = t2;
        }
    }

    // c = A^T (X b)
    spmv_k<<<N1C / 8, dim3(32, 8)>>>(Xc, dB, tv);
    atmv_k<<<N2C / 256, 256>>>(dA, tv, c);

    // G = A^T X : M=4096, N=1024, K=1024 (A-op = At, B-op = X symmetric)
    {
        dim3 g(N1C / 128, N2C / 128, 1);
        tgemm_k<false, false><<<g, NTHR, SMEM_BYTES>>>(
            At, N1C, Xc, N1C, nullptr, G, N1C, N1C, nullptr);
    }

    // MLP: h = relu(d W1 + b1) split 4 ; w = h W2 + b2 split 2
    {
        dim3 g1(HC / 128, BC / 128, 4);
        tgemm_k<false, true><<<g1, NTHR, SMEM_BYTES>>>(
            dd, DC, W1t, DC, nullptr, P, HC, DC / 4, nullptr);
        reduce_bias_k<true><<<(BC * HC / 4) / 256, 256>>>(
            P, db1, h, (size_t)BC * HC / 4, 4, HC / 4);
        dim3 g2(N2C / 128, BC / 128, 2);
        tgemm_k<false, true><<<g2, NTHR, SMEM_BYTES>>>(
            h, HC, W2t, HC, nullptr, P, N2C, HC / 2, nullptr);
        reduce_bias_k<false><<<(BC * N2C / 4) / 256, 256>>>(
            P, db2, wbuf, (size_t)BC * N2C / 4, 2, N2C / 4);
    }

    // DYS loop: 50 guarded iterations, 4 kernels each
    dim3 gr(BC / 128, N1C / 128, 8);     // r = A u^T   (split 8)
    dim3 gz(N2C / 128, BC / 128, 2);     // (G r)^T     (split 2)
    float* zb2[2] = { za, zbb };
    for (int it = 1; it <= 50; ++it) {
        const float* zin = zb2[(it - 1) & 1];
        float* zout = zb2[it & 1];
        tgemm_k<true, true><<<gr, NTHR, SMEM_BYTES>>>(
            dA, N2C, zin, N2C, wbuf, P, BC, N2C / 8, flag);
        reduce_tr_k<<<dim3(N1C / 32, BC / 32), dim3(32, 8)>>>(P, rt, flag);
        tgemm_k<false, true><<<gz, NTHR, SMEM_BYTES>>>(
            rt, N1C, G, N1C, nullptr, P, N2C, N1C / 2, flag);
        zupd_k<false><<<(BC * N2C / 4) / 256, 256>>>(P, zin, wbuf, c, zout, flag);
    }

    // final unguarded step, relu into d_out
    tgemm_k<true, true><<<gr, NTHR, SMEM_BYTES>>>(
        dA, N2C, za, N2C, wbuf, P, BC, N2C / 8, nullptr);
    reduce_tr_k<<<dim3(N1C / 32, BC / 32), dim3(32, 8)>>>(P, rt, nullptr);
    tgemm_k<false, true><<<gz, NTHR, SMEM_BYTES>>>(
        rt, N1C, G, N1C, nullptr, P, N2C, N1C / 2, nullptr);
    zupd_k<true><<<(BC * N2C / 4) / 256, 256>>>(P, za, wbuf, c, out, nullptr);
}

// round 7
// speedup vs baseline: 3.6158x; 1.6693x over previous
#include <cuda_runtime.h>
#include <cuda_fp16.h>
#include <math.h>
#include <stdint.h>

// ----------------------------------------------------------------------------
// DYS_opt_net.  Loop GEMMs: legacy fp16 mma.sync m16n8k16, fp16x3 split
// (hh+hl+lh, fp32 accum), matrices pre-scaled so lo planes stay fp16-normal.
// cp.async staging + ldmatrix fragments. Precompute on 3xTF32 mma.sync.
// z' = relu(z) - a*w + c - (G (A u^T))^T,  u = |z| - a*w
// ----------------------------------------------------------------------------

#define N1C 1024
#define N2C 4096
#define BC  256
#define DC  512
#define HC  2048

#define ALPHA_C 0.05f
#define EPS_C   0.01f
#define NS_ITERS 7
#define PI_ITERS 12

#define A_SC 64.f
#define G_SC 32.f
#define INV_A_SC 0.015625f
#define INV_G_SC 0.03125f

#define NTHR 256
#define SMEM_BYTES 98304

// fp16 GEMM tile config
#define HBK 32
#define HSTR 40                  // halves per smem row (32 + 8 pad)
#define HPL (128*HSTR)           // halves per plane buffer
#define HST (4*HPL)              // halves per stage (Ah,Al,Bh,Bl)
#define HSMEM (2*HST*2)          // bytes: 81920

__device__ float g_S  [(size_t)N1C*N1C];
__device__ float g_Xa [(size_t)N1C*N1C];
__device__ float g_Xb [(size_t)N1C*N1C];
__device__ float g_T  [(size_t)N1C*N1C];
__device__ float g_G  [(size_t)N2C*N1C];
__device__ float g_At [(size_t)N2C*N1C];
__device__ float g_W1t[(size_t)HC*DC];
__device__ float g_W2t[(size_t)N2C*HC];
__device__ float g_c  [N2C];
__device__ float g_tv [N1C];
__device__ float g_v  [N1C];
__device__ float g_y  [N1C];
__device__ float g_h  [(size_t)BC*HC];
__device__ float g_w  [(size_t)BC*N2C];
__device__ float g_za [(size_t)BC*N2C];
__device__ float g_zb [(size_t)BC*N2C];
__device__ float g_P  [(size_t)4*1024*1024];
__device__ __half g_Ah [(size_t)N1C*N2C];
__device__ __half g_Al [(size_t)N1C*N2C];
__device__ __half g_Gh [(size_t)N2C*N1C];
__device__ __half g_Gl [(size_t)N2C*N1C];
__device__ __half g_uh [(size_t)BC*N2C];
__device__ __half g_ul [(size_t)BC*N2C];
__device__ __half g_rth[(size_t)BC*N1C];
__device__ __half g_rtl[(size_t)BC*N1C];
__device__ float g_lam;
__device__ float g_ss;
__device__ int   g_flag;
__device__ int   g_cnt;

// ---------------- small utility kernels ----------------
__global__ void init_k() { g_ss = 0.f; g_flag = 0; g_cnt = 0; }

__global__ void copy4_k(float4* __restrict__ dst, const float4* __restrict__ src) {
    int i = blockIdx.x * blockDim.x + threadIdx.x;
    dst[i] = src[i];
}

__global__ void fill_k(float* v, float val, int n) {
    int i = blockIdx.x * blockDim.x + threadIdx.x;
    if (i < n) v[i] = val;
}

__global__ void spmv_k(const float* __restrict__ M_, const float* __restrict__ v,
                       float* __restrict__ y) {
    int row = blockIdx.x * 8 + threadIdx.y;
    const float* mr = M_ + (size_t)row * N1C;
    float s = 0.f;
    for (int j = threadIdx.x; j < N1C; j += 32) s += mr[j] * v[j];
    #pragma unroll
    for (int o = 16; o; o >>= 1) s += __shfl_xor_sync(0xffffffffu, s, o);
    if (threadIdx.x == 0) y[row] = s;
}

__global__ void pi_norm_k(const float* __restrict__ y, float* __restrict__ v) {
    __shared__ float red[256];
    float s = 0.f;
    for (int i = threadIdx.x; i < N1C; i += 256) { float t = y[i]; s += t * t; }
    red[threadIdx.x] = s; __syncthreads();
    for (int o = 128; o; o >>= 1) {
        if (threadIdx.x < o) red[threadIdx.x] += red[threadIdx.x + o];
        __syncthreads();
    }
    float nrm = sqrtf(red[0]);
    float inv = 1.f / nrm;
    for (int i = threadIdx.x; i < N1C; i += 256) v[i] = y[i] * inv;
    if (threadIdx.x == 0) g_lam = nrm;
}

__global__ void initX_k(float* X) {
    float a = 1.8f / g_lam;
    int i = blockIdx.x * 256 + threadIdx.x;
    int rr = i / N1C, cc = i % N1C;
    X[i] = (rr == cc) ? a : 0.f;
}

__global__ void atmv_k(const float* __restrict__ A, const float* __restrict__ t,
                       float* __restrict__ c) {
    __shared__ float ts[N1C];
    for (int i = threadIdx.x; i < N1C; i += 256) ts[i] = t[i];
    __syncthreads();
    int j = blockIdx.x * 256 + threadIdx.x;
    float s = 0.f;
    for (int i = 0; i < N1C; i++) s += A[(size_t)i * N2C + j] * ts[i];
    c[j] = s;
}

__global__ void transp_k(float* __restrict__ dst, const float* __restrict__ src,
                         int R, int C) {
    __shared__ float t[32][33];
    int bx = blockIdx.x * 32, by = blockIdx.y * 32;
    #pragma unroll
    for (int i = 0; i < 4; i++) {
        int r = by + threadIdx.y + i * 8;
        t[threadIdx.y + i * 8][threadIdx.x] = src[(size_t)r * C + bx + threadIdx.x];
    }
    __syncthreads();
    #pragma unroll
    for (int i = 0; i < 4; i++) {
        int r = bx + threadIdx.y + i * 8;
        dst[(size_t)r * R + by + threadIdx.x] = t[threadIdx.x][threadIdx.y + i * 8];
    }
}

__device__ __forceinline__ void split2h(float x, __half& h, __half& l) {
    h = __float2half_rn(x);
    l = __float2half_rn(x - __half2float(h));
}

// split scaled fp32 -> (hi, lo) fp16 planes; 8 elements per thread
__global__ void splitH_k(const float* __restrict__ src, __half* __restrict__ ph,
                         __half* __restrict__ pl, float scale) {
    size_t e = ((size_t)blockIdx.x * 256 + threadIdx.x) * 8;
    uint32_t hh[4], ll[4];
    #pragma unroll
    for (int p = 0; p < 4; p++) {
        __half h0, h1, l0, l1;
        split2h(src[e + 2 * p] * scale, h0, l0);
        split2h(src[e + 2 * p + 1] * scale, h1, l1);
        __half2 hp = __halves2half2(h0, h1), lp = __halves2half2(l0, l1);
        hh[p] = *(uint32_t*)&hp; ll[p] = *(uint32_t*)&lp;
    }
    *(uint4*)(ph + e) = make_uint4(hh[0], hh[1], hh[2], hh[3]);
    *(uint4*)(pl + e) = make_uint4(ll[0], ll[1], ll[2], ll[3]);
}

// u = |z| - a*w -> u planes; 4 elements per thread
__global__ void u0_k(const float* __restrict__ z, const float* __restrict__ w) {
    size_t i = (size_t)blockIdx.x * 256 + threadIdx.x;
    float4 zv = ((const float4*)z)[i];
    float4 wv = ((const float4*)w)[i];
    __half h0, h1, h2, h3, l0, l1, l2, l3;
    split2h(fabsf(zv.x) - ALPHA_C * wv.x, h0, l0);
    split2h(fabsf(zv.y) - ALPHA_C * wv.y, h1, l1);
    split2h(fabsf(zv.z) - ALPHA_C * wv.z, h2, l2);
    split2h(fabsf(zv.w) - ALPHA_C * wv.w, h3, l3);
    __half2 ha = __halves2half2(h0, h1), hb = __halves2half2(h2, h3);
    __half2 la = __halves2half2(l0, l1), lb = __halves2half2(l2, l3);
    ((uint2*)g_uh)[i] = make_uint2(*(uint32_t*)&ha, *(uint32_t*)&hb);
    ((uint2*)g_ul)[i] = make_uint2(*(uint32_t*)&la, *(uint32_t*)&lb);
}

// ---------------- reduce kernels ----------------
__global__ void reduce_sum_k(const float* __restrict__ P, float* __restrict__ out,
                             size_t stride4, int ns, const int* __restrict__ guard) {
    if (guard && *guard) return;
    size_t i = (size_t)blockIdx.x * 256 + threadIdx.x;
    const float4* p = (const float4*)P;
    float4 s = p[i];
    for (int sp = 1; sp < ns; sp++) {
        float4 t = p[(size_t)sp * stride4 + i];
        s.x += t.x; s.y += t.y; s.z += t.z; s.w += t.w;
    }
    ((float4*)out)[i] = s;
}

__global__ void reduce_ns_k(const float* __restrict__ P, const float* __restrict__ X,
                            float* __restrict__ out, size_t stride4, int ns) {
    size_t i = (size_t)blockIdx.x * 256 + threadIdx.x;
    const float4* p = (const float4*)P;
    float4 s = p[i];
    for (int sp = 1; sp < ns; sp++) {
        float4 t = p[(size_t)sp * stride4 + i];
        s.x += t.x; s.y += t.y; s.z += t.z; s.w += t.w;
    }
    float4 x = ((const float4*)X)[i];
    float4 o;
    o.x = 2.f * x.x - s.x; o.y = 2.f * x.y - s.y;
    o.z = 2.f * x.z - s.z; o.w = 2.f * x.w - s.w;
    ((float4*)out)[i] = o;
}

template<bool RELU>
__global__ void reduce_bias_k(const float* __restrict__ P, const float* __restrict__ bias,
                              float* __restrict__ out, size_t stride4, int ns, int n4) {
    size_t i = (size_t)blockIdx.x * 256 + threadIdx.x;
    const float4* p = (const float4*)P;
    float4 s = p[i];
    for (int sp = 1; sp < ns; sp++) {
        float4 t = p[(size_t)sp * stride4 + i];
        s.x += t.x; s.y += t.y; s.z += t.z; s.w += t.w;
    }
    float4 b = ((const float4*)bias)[i % n4];
    s.x += b.x; s.y += b.y; s.z += b.z; s.w += b.w;
    if (RELU) {
        s.x = fmaxf(s.x, 0.f); s.y = fmaxf(s.y, 0.f);
        s.z = fmaxf(s.z, 0.f); s.w = fmaxf(s.w, 0.f);
    }
    ((float4*)out)[i] = s;
}

// sum 8 partials of 64*(A u^T) [N1C][BC]; write rt planes [BC][N1C] (x 1/64)
__global__ void reduce_tr_k(const float* __restrict__ P, const int* __restrict__ guard) {
    if (guard && *guard) return;
    __shared__ float t[32][33];
    int bm = blockIdx.x * 32;
    int bb = blockIdx.y * 32;
    #pragma unroll
    for (int i = 0; i < 4; i++) {
        int m = bm + threadIdx.y + i * 8;
        size_t idx = (size_t)m * BC + bb + threadIdx.x;
        float s = 0.f;
        #pragma unroll
        for (int sp = 0; sp < 8; sp++) s += P[(size_t)sp * N1C * BC + idx];
        t[threadIdx.y + i * 8][threadIdx.x] = s;
    }
    __syncthreads();
    #pragma unroll
    for (int i = 0; i < 4; i++) {
        int b = bb + threadIdx.y + i * 8;
        float vv = t[threadIdx.x][threadIdx.y + i * 8] * INV_A_SC;
        __half h, l;
        split2h(vv, h, l);
        size_t o = (size_t)b * N1C + bm + threadIdx.x;
        g_rth[o] = h;
        g_rtl[o] = l;
    }
}

// z-update: zn = relu(z) - a*w + c - (1/32)*sum; + u planes + convergence check
template<bool FIN>
__global__ void zupd_k(const float* __restrict__ P, const float* __restrict__ zin,
                       const float* __restrict__ w, const float* __restrict__ c,
                       float* __restrict__ zout, const int* __restrict__ guard) {
    size_t i = (size_t)blockIdx.x * 256 + threadIdx.x;
    if (!FIN && guard && *guard) {
        ((float4*)zout)[i] = ((const float4*)zin)[i];
        return;
    }
    const float4* p = (const float4*)P;
    float4 s = p[i];
    {
        float4 t = p[(size_t)(BC * (N2C / 4)) + i];
        s.x += t.x; s.y += t.y; s.z += t.z; s.w += t.w;
    }
    float4 z = ((const float4*)zin)[i];
    float4 ww = ((const float4*)w)[i];
    float4 cc = ((const float4*)c)[i & (N2C / 4 - 1)];
    float4 o;
    o.x = fmaxf(z.x, 0.f) - ALPHA_C * ww.x + cc.x - s.x * INV_G_SC;
    o.y = fmaxf(z.y, 0.f) - ALPHA_C * ww.y + cc.y - s.y * INV_G_SC;
    o.z = fmaxf(z.z, 0.f) - ALPHA_C * ww.z + cc.z - s.z * INV_G_SC;
    o.w = fmaxf(z.w, 0.f) - ALPHA_C * ww.w + cc.w - s.w * INV_G_SC;
    if (FIN) {
        o.x = fmaxf(o.x, 0.f); o.y = fmaxf(o.y, 0.f);
        o.z = fmaxf(o.z, 0.f); o.w = fmaxf(o.w, 0.f);
        ((float4*)zout)[i] = o;
    } else {
        ((float4*)zout)[i] = o;
        __half h0, h1, h2, h3, l0, l1, l2, l3;
        split2h(fabsf(o.x) - ALPHA_C * ww.x, h0, l0);
        split2h(fabsf(o.y) - ALPHA_C * ww.y, h1, l1);
        split2h(fabsf(o.z) - ALPHA_C * ww.z, h2, l2);
        split2h(fabsf(o.w) - ALPHA_C * ww.w, h3, l3);
        __half2 ha = __halves2half2(h0, h1), hb = __halves2half2(h2, h3);
        __half2 la = __halves2half2(l0, l1), lb = __halves2half2(l2, l3);
        ((uint2*)g_uh)[i] = make_uint2(*(uint32_t*)&ha, *(uint32_t*)&hb);
        ((uint2*)g_ul)[i] = make_uint2(*(uint32_t*)&la, *(uint32_t*)&lb);
        float dx = o.x - z.x, dy = o.y - z.y, dz = o.z - z.z, dw = o.w - z.w;
        float ls = dx * dx + dy * dy + dz * dz + dw * dw;
        __shared__ float red[256];
        red[threadIdx.x] = ls;
        __syncthreads();
        for (int o2 = 128; o2; o2 >>= 1) {
            if (threadIdx.x < o2) red[threadIdx.x] += red[threadIdx.x + o2];
            __syncthreads();
        }
        if (threadIdx.x == 0) {
            atomicAdd(&g_ss, red[0]);
            __threadfence();
            int t = atomicAdd(&g_cnt, 1);
            if (t == (int)gridDim.x - 1) {
                if (g_ss <= EPS_C * EPS_C) g_flag = 1;
                g_ss = 0.f;
                g_cnt = 0;
            }
        }
    }
}

// ---------------- legacy 3xTF32 GEMM (precompute only) ----------------
__device__ __forceinline__ void split_tf32(float x, uint32_t& hi, uint32_t& lo) {
    asm("cvt.rna.tf32.f32 %0, %1;" : "=r"(hi) : "f"(x));
    float hf = __uint_as_float(hi);
    asm("cvt.rna.tf32.f32 %0, %1;" : "=r"(lo) : "f"(x - hf));
}
__device__ __forceinline__ void mma8(float* c, const uint32_t* a, const uint32_t* b) {
    asm("mma.sync.aligned.m16n8k8.row.col.f32.tf32.tf32.f32 "
        "{%0,%1,%2,%3}, {%4,%5,%6,%7}, {%8,%9}, {%0,%1,%2,%3};"
        : "+f"(c[0]), "+f"(c[1]), "+f"(c[2]), "+f"(c[3])
        : "r"(a[0]), "r"(a[1]), "r"(a[2]), "r"(a[3]), "r"(b[0]), "r"(b[1]));
}

#define TSTR 24
#define TBUF 3072
template<bool SPLIT>
__global__ void __launch_bounds__(NTHR)
tgemm_k(const float* __restrict__ Ag, int lda,
        const float* __restrict__ Bg, int ldb,
        float* __restrict__ Cg, int N, int kchunk)
{
    extern __shared__ uint32_t sm[];
    const int tid = threadIdx.x;
    const int wid = tid >> 5, lane = tid & 31;
    const int wm = wid >> 2, wn = wid & 3;
    const int gr = lane >> 2, qc = lane & 3;
    const int m0 = blockIdx.y * 128, n0 = blockIdx.x * 128;
    const int k0 = blockIdx.z * kchunk, kend = k0 + kchunk;

    float acc[4][4][4];
    #pragma unroll
    for (int f = 0; f < 4; f++)
        #pragma unroll
        for (int g = 0; g < 4; g++)
            #pragma unroll
            for (int e = 0; e < 4; e++) acc[f][g][e] = 0.f;

    float4 ra[2], rb[2];
    auto loadG = [&](int kb) {
        #pragma unroll
        for (int v = 0; v < 2; v++) {
            int id = v * 256 + tid;
            int row = id >> 2, kq = (id & 3) * 4;
            ra[v] = *(const float4*)&Ag[(size_t)(m0 + row) * lda + kb + kq];
            rb[v] = *(const float4*)&Bg[(size_t)(n0 + row) * ldb + kb + kq];
        }
    };
    auto stage = [&](int buf) {
        uint32_t* AH = sm + buf * (4 * TBUF);
        uint32_t* AL = AH + TBUF;
        uint32_t* BH = AL + TBUF;
        uint32_t* BL = BH + TBUF;
        #pragma unroll
        for (int v = 0; v < 2; v++) {
            int id = v * 256 + tid;
            int row = id >> 2, kq = (id & 3) * 4;
            uint4 h, l;
            split_tf32(ra[v].x, h.x, l.x); split_tf32(ra[v].y, h.y, l.y);
            split_tf32(ra[v].z, h.z, l.z); split_tf32(ra[v].w, h.w, l.w);
            *(uint4*)&AH[row * TSTR + kq] = h;
            *(uint4*)&AL[row * TSTR + kq] = l;
            split_tf32(rb[v].x, h.x, l.x); split_tf32(rb[v].y, h.y, l.y);
            split_tf32(rb[v].z, h.z, l.z); split_tf32(rb[v].w, h.w, l.w);
            *(uint4*)&BH[row * TSTR + kq] = h;
            *(uint4*)&BL[row * TSTR + kq] = l;
        }
    };

    loadG(k0);
    stage(0);
    __syncthreads();

    int buf = 0;
    for (int kb = k0; kb < kend; kb += 16) {
        bool nxt = (kb + 16) < kend;
        if (nxt) loadG(kb + 16);
        const uint32_t* AH = sm + buf * (4 * TBUF);
        const uint32_t* AL = AH + TBUF;
        const uint32_t* BH = AL + TBUF;
        const uint32_t* BL = BH + TBUF;
        #pragma unroll
        for (int ks = 0; ks < 2; ks++) {
            uint32_t ah[4][4], al[4][4], bh[4][2], bl[4][2];
            #pragma unroll
            for (int f = 0; f < 4; f++) {
                int r0 = wm * 64 + f * 16 + gr;
                int off = r0 * TSTR + ks * 8 + 2 * qc;
                uint2 t0 = *(const uint2*)&AH[off];
                uint2 t1 = *(const uint2*)&AH[off + 8 * TSTR];
                ah[f][0] = t0.x; ah[f][2] = t0.y; ah[f][1] = t1.x; ah[f][3] = t1.y;
                t0 = *(const uint2*)&AL[off];
                t1 = *(const uint2*)&AL[off + 8 * TSTR];
                al[f][0] = t0.x; al[f][2] = t0.y; al[f][1] = t1.x; al[f][3] = t1.y;
            }
            #pragma unroll
            for (int g = 0; g < 4; g++) {
                int cl = wn * 32 + g * 8 + gr;
                int off = cl * TSTR + ks * 8 + 2 * qc;
                uint2 t = *(const uint2*)&BH[off];
                bh[g][0] = t.x; bh[g][1] = t.y;
                t = *(const uint2*)&BL[off];
                bl[g][0] = t.x; bl[g][1] = t.y;
            }
            #pragma unroll
            for (int f = 0; f < 4; f++)
                #pragma unroll
                for (int g = 0; g < 4; g++) {
                    mma8(acc[f][g], ah[f], bh[g]);
                    mma8(acc[f][g], ah[f], bl[g]);
                    mma8(acc[f][g], al[f], bh[g]);
                }
        }
        if (nxt) {
            stage(buf ^ 1);
            __syncthreads();
            buf ^= 1;
        }
    }

    size_t off = SPLIT ? (size_t)blockIdx.z * ((size_t)gridDim.y * 128) * N : 0;
    #pragma unroll
    for (int f = 0; f < 4; f++) {
        int m = m0 + wm * 64 + f * 16 + gr;
        #pragma unroll
        for (int g = 0; g < 4; g++) {
            int n = n0 + wn * 32 + g * 8 + 2 * qc;
            *(float2*)&Cg[off + (size_t)m * N + n] = make_float2(acc[f][g][0], acc[f][g][1]);
            *(float2*)&Cg[off + (size_t)(m + 8) * N + n] = make_float2(acc[f][g][2], acc[f][g][3]);
        }
    }
}

// ---------------- fp16x3 loop GEMM ----------------
__device__ __forceinline__ uint32_t smem_u32(const void* p) {
    uint32_t a;
    asm("{ .reg .u64 t; cvta.to.shared.u64 t, %1; cvt.u32.u64 %0, t; }" : "=r"(a) : "l"(p));
    return a;
}
__device__ __forceinline__ void cp16(uint32_t dst, const void* src) {
    asm volatile("cp.async.cg.shared.global [%0], [%1], 16;" :: "r"(dst), "l"(src));
}
__device__ __forceinline__ void ldsm4(uint32_t* r, uint32_t a) {
    asm volatile("ldmatrix.sync.aligned.m8n8.x4.shared.b16 {%0,%1,%2,%3}, [%4];"
        : "=r"(r[0]), "=r"(r[1]), "=r"(r[2]), "=r"(r[3]) : "r"(a));
}
__device__ __forceinline__ void mma16(float* c, const uint32_t* a, const uint32_t* b) {
    asm volatile("mma.sync.aligned.m16n8k16.row.col.f32.f16.f16.f32 "
        "{%0,%1,%2,%3}, {%4,%5,%6,%7}, {%8,%9}, {%0,%1,%2,%3};"
        : "+f"(c[0]), "+f"(c[1]), "+f"(c[2]), "+f"(c[3])
        : "r"(a[0]), "r"(a[1]), "r"(a[2]), "r"(a[3]), "r"(b[0]), "r"(b[1]));
}

// C[m][n] = sum_k (Ah+Al)[m][k]*(Bh+Bl)[n][k]  (hh+hl+lh), partial per blockIdx.z
__global__ void __launch_bounds__(256)
hgemm_k(const __half* __restrict__ Ahp, const __half* __restrict__ Alp, int lda,
        const __half* __restrict__ Bhp, const __half* __restrict__ Blp, int ldb,
        float* __restrict__ Cg, int N, int kchunk, const int* __restrict__ guard)
{
    if (guard && *guard) return;
    extern __shared__ __half hsm[];
    const int tid = threadIdx.x, lane = tid & 31, wid = tid >> 5;
    const int wm = wid >> 2, wn = wid & 3;
    const int m0 = blockIdx.y * 128, n0 = blockIdx.x * 128;
    const int k0 = blockIdx.z * kchunk;
    const int ST = kchunk / HBK;
    const __half* psrc[4] = { Ahp, Alp, Bhp, Blp };
    uint32_t sbase = smem_u32(hsm);

    auto load = [&](int s) {
        int buf = s & 1;
        int kb = k0 + s * HBK;
        #pragma unroll
        for (int t = 0; t < 8; t++) {
            int id = t * 256 + tid;
            int pl = id >> 9, idx = id & 511;
            int row = idx >> 2, kc = idx & 3;
            int isB = pl >> 1;
            const __half* src = psrc[pl] +
                (size_t)((isB ? n0 : m0) + row) * (isB ? ldb : lda) + kb + kc * 8;
            uint32_t dst = sbase + (uint32_t)(buf * HST + pl * HPL + row * HSTR + kc * 8) * 2;
            cp16(dst, src);
        }
    };

    float acc[4][4][4];
    #pragma unroll
    for (int f = 0; f < 4; f++)
        #pragma unroll
        for (int g = 0; g < 4; g++)
            #pragma unroll
            for (int e = 0; e < 4; e++) acc[f][g][e] = 0.f;

    load(0);
    asm volatile("cp.async.commit_group;");
    load(1);
    asm volatile("cp.async.commit_group;");

    const int offA = (lane & 15) * HSTR + (lane >> 4) * 8;
    const int offB = ((lane & 7) + ((lane >> 4) << 3)) * HSTR + ((lane >> 3) & 1) * 8;

    for (int s = 0; s < ST; s++) {
        asm volatile("cp.async.wait_group 1;");
        __syncthreads();
        uint32_t stg = sbase + (uint32_t)((s & 1) * HST) * 2;
        #pragma unroll
        for (int ks = 0; ks < 2; ks++) {
            uint32_t aH[4][4], aL[4][4], bH[4][2], bL[4][2];
            #pragma unroll
            for (int f = 0; f < 4; f++) {
                uint32_t base = stg + (uint32_t)((wm * 64 + f * 16) * HSTR + ks * 16 + offA) * 2;
                ldsm4(aH[f], base);
                ldsm4(aL[f], base + HPL * 2);
            }
            #pragma unroll
            for (int gp = 0; gp < 2; gp++) {
                uint32_t r[4];
                uint32_t base = stg + (uint32_t)(2 * HPL + (wn * 32 + gp * 16) * HSTR + ks * 16 + offB) * 2;
                ldsm4(r, base);
                bH[gp * 2][0] = r[0]; bH[gp * 2][1] = r[1];
                bH[gp * 2 + 1][0] = r[2]; bH[gp * 2 + 1][1] = r[3];
                ldsm4(r, base + HPL * 2);
                bL[gp * 2][0] = r[0]; bL[gp * 2][1] = r[1];
                bL[gp * 2 + 1][0] = r[2]; bL[gp * 2 + 1][1] = r[3];
            }
            #pragma unroll
            for (int f = 0; f < 4; f++)
                #pragma unroll
                for (int g = 0; g < 4; g++) {
                    mma16(acc[f][g], aH[f], bH[g]);
                    mma16(acc[f][g], aH[f], bL[g]);
                    mma16(acc[f][g], aL[f], bH[g]);
                }
        }
        __syncthreads();
        if (s + 2 < ST) load(s + 2);
        asm volatile("cp.async.commit_group;");
    }

    size_t off = (size_t)blockIdx.z * ((size_t)gridDim.y * 128) * N;
    const int tr = lane >> 2, tc = (lane & 3) * 2;
    #pragma unroll
    for (int f = 0; f < 4; f++) {
        int m = m0 + wm * 64 + f * 16 + tr;
        #pragma unroll
        for (int g = 0; g < 4; g++) {
            int n = n0 + wn * 32 + g * 8 + tc;
            *(float2*)&Cg[off + (size_t)m * N + n] = make_float2(acc[f][g][0], acc[f][g][1]);
            *(float2*)&Cg[off + (size_t)(m + 8) * N + n] = make_float2(acc[f][g][2], acc[f][g][3]);
        }
    }
}

// ---------------- host ----------------
extern "C" void kernel_launch(void* const* d_in, const int* in_sizes, int n_in,
                              void* d_out, int out_size) {
    (void)in_sizes; (void)n_in; (void)out_size;
    const float* dd  = (const float*)d_in[0];
    const float* dA  = (const float*)d_in[1];
    const float* dB  = (const float*)d_in[2];
    const float* dW1 = (const float*)d_in[3];
    const float* db1 = (const float*)d_in[4];
    const float* dW2 = (const float*)d_in[5];
    const float* db2 = (const float*)d_in[6];
    const float* dz0 = (const float*)d_in[7];
    float* out = (float*)d_out;

    void* p;
    cudaGetSymbolAddress(&p, g_S);   float* S    = (float*)p;
    cudaGetSymbolAddress(&p, g_Xa);  float* Xa   = (float*)p;
    cudaGetSymbolAddress(&p, g_Xb);  float* Xb   = (float*)p;
    cudaGetSymbolAddress(&p, g_T);   float* Tm   = (float*)p;
    cudaGetSymbolAddress(&p, g_G);   float* G    = (float*)p;
    cudaGetSymbolAddress(&p, g_At);  float* At   = (float*)p;
    cudaGetSymbolAddress(&p, g_W1t); float* W1t  = (float*)p;
    cudaGetSymbolAddress(&p, g_W2t); float* W2t  = (float*)p;
    cudaGetSymbolAddress(&p, g_c);   float* c    = (float*)p;
    cudaGetSymbolAddress(&p, g_tv);  float* tv   = (float*)p;
    cudaGetSymbolAddress(&p, g_v);   float* v    = (float*)p;
    cudaGetSymbolAddress(&p, g_y);   float* y    = (float*)p;
    cudaGetSymbolAddress(&p, g_h);   float* h    = (float*)p;
    cudaGetSymbolAddress(&p, g_w);   float* wbuf = (float*)p;
    cudaGetSymbolAddress(&p, g_za);  float* za   = (float*)p;
    cudaGetSymbolAddress(&p, g_zb);  float* zbb  = (float*)p;
    cudaGetSymbolAddress(&p, g_P);   float* P    = (float*)p;
    cudaGetSymbolAddress(&p, g_flag); int* flag  = (int*)p;
    cudaGetSymbolAddress(&p, g_Ah);  __half* Ahp = (__half*)p;
    cudaGetSymbolAddress(&p, g_Al);  __half* Alp = (__half*)p;
    cudaGetSymbolAddress(&p, g_Gh);  __half* Ghp = (__half*)p;
    cudaGetSymbolAddress(&p, g_Gl);  __half* Glp = (__half*)p;
    cudaGetSymbolAddress(&p, g_uh);  __half* uhp = (__half*)p;
    cudaGetSymbolAddress(&p, g_ul);  __half* ulp = (__half*)p;
    cudaGetSymbolAddress(&p, g_rth); __half* rthp = (__half*)p;
    cudaGetSymbolAddress(&p, g_rtl); __half* rtlp = (__half*)p;

    cudaFuncSetAttribute(tgemm_k<true>,
                         cudaFuncAttributeMaxDynamicSharedMemorySize, SMEM_BYTES);
    cudaFuncSetAttribute(tgemm_k<false>,
                         cudaFuncAttributeMaxDynamicSharedMemorySize, SMEM_BYTES);
    cudaFuncSetAttribute(hgemm_k,
                         cudaFuncAttributeMaxDynamicSharedMemorySize, HSMEM);

    init_k<<<1, 1>>>();
    copy4_k<<<(BC * N2C / 4) / 256, 256>>>((float4*)za, (const float4*)dz0);
    transp_k<<<dim3(N2C / 32, N1C / 32), dim3(32, 8)>>>(At, dA, N1C, N2C);

    // S = A A^T (legacy, split2)
    {
        dim3 g(N1C / 128, N1C / 128, 2);
        tgemm_k<true><<<g, NTHR, SMEM_BYTES>>>(dA, N2C, dA, N2C, P, N1C, N2C / 2);
        reduce_sum_k<<<(N1C * N1C / 4) / 256, 256>>>(P, S, (size_t)N1C * N1C / 4, 2, nullptr);
    }

    // A planes (scaled by 64)
    splitH_k<<<(int)(((size_t)N1C * N2C / 8) / 256), 256>>>(dA, Ahp, Alp, A_SC);

    transp_k<<<dim3(HC / 32, DC / 32), dim3(32, 8)>>>(W1t, dW1, DC, HC);
    transp_k<<<dim3(N2C / 32, HC / 32), dim3(32, 8)>>>(W2t, dW2, HC, N2C);

    // power iteration
    fill_k<<<N1C / 256, 256>>>(v, 0.03125f, N1C);
    for (int i = 0; i < PI_ITERS; i++) {
        spmv_k<<<N1C / 8, dim3(32, 8)>>>(S, v, y);
        pi_norm_k<<<1, 256>>>(y, v);
    }
    initX_k<<<(N1C * N1C) / 256, 256>>>(Xa);

    // Newton-Schulz
    float* Xc = Xa; float* Xn = Xb;
    {
        dim3 g(N1C / 128, N1C / 128, 2);
        size_t s4 = (size_t)N1C * N1C / 4;
        for (int i = 0; i < NS_ITERS; i++) {
            tgemm_k<true><<<g, NTHR, SMEM_BYTES>>>(Xc, N1C, S, N1C, P, N1C, N1C / 2);
            reduce_sum_k<<<(N1C * N1C / 4) / 256, 256>>>(P, Tm, s4, 2, nullptr);
            tgemm_k<true><<<g, NTHR, SMEM_BYTES>>>(Tm, N1C, Xc, N1C, P, N1C, N1C / 2);
            reduce_ns_k<<<(N1C * N1C / 4) / 256, 256>>>(P, Xc, Xn, s4, 2);
            float* t2 = Xc; Xc = Xn; Xn = t2;
        }
    }

    // c = A^T (X b)
    spmv_k<<<N1C / 8, dim3(32, 8)>>>(Xc, dB, tv);
    atmv_k<<<N2C / 256, 256>>>(dA, tv, c);

    // G = A^T X (legacy), then G planes (scaled by 32)
    {
        dim3 g(N1C / 128, N2C / 128, 1);
        tgemm_k<false><<<g, NTHR, SMEM_BYTES>>>(At, N1C, Xc, N1C, G, N1C, N1C);
    }
    splitH_k<<<(int)(((size_t)N2C * N1C / 8) / 256), 256>>>(G, Ghp, Glp, G_SC);

    // MLP
    {
        dim3 g1(HC / 128, BC / 128, 4);
        tgemm_k<true><<<g1, NTHR, SMEM_BYTES>>>(dd, DC, W1t, DC, P, HC, DC / 4);
        reduce_bias_k<true><<<(BC * HC / 4) / 256, 256>>>(
            P, db1, h, (size_t)BC * HC / 4, 4, HC / 4);
        dim3 g2(N2C / 128, BC / 128, 2);
        tgemm_k<true><<<g2, NTHR, SMEM_BYTES>>>(h, HC, W2t, HC, P, N2C, HC / 2);
        reduce_bias_k<false><<<(BC * N2C / 4) / 256, 256>>>(
            P, db2, wbuf, (size_t)BC * N2C / 4, 2, N2C / 4);
    }

    // initial u planes
    u0_k<<<(BC * N2C / 4) / 256, 256>>>(za, wbuf);

    // DYS loop: fp16x3 GEMMs
    dim3 gr(BC / 128, N1C / 128, 8);     // 64*(A u^T): M=1024 N=256 K=4096, split8
    dim3 gz(N2C / 128, BC / 128, 2);     // 32*(G r)^T: M=256 N=4096 K=1024, split2
    float* zb2[2] = { za, zbb };
    for (int it = 1; it <= 50; ++it) {
        const float* zin = zb2[(it - 1) & 1];
        float* zout = zb2[it & 1];
        hgemm_k<<<gr, 256, HSMEM>>>(Ahp, Alp, N2C, uhp, ulp, N2C, P, BC, N2C / 8, flag);
        reduce_tr_k<<<dim3(N1C / 32, BC / 32), dim3(32, 8)>>>(P, flag);
        hgemm_k<<<gz, 256, HSMEM>>>(rthp, rtlp, N1C, Ghp, Glp, N1C, P, N2C, N1C / 2, flag);
        zupd_k<false><<<(BC * N2C / 4) / 256, 256>>>(P, zin, wbuf, c, zout, flag);
    }

    // final unguarded step, relu into d_out
    hgemm_k<<<gr, 256, HSMEM>>>(Ahp, Alp, N2C, uhp, ulp, N2C, P, BC, N2C / 8, nullptr);
    reduce_tr_k<<<dim3(N1C / 32, BC / 32), dim3(32, 8)>>>(P, nullptr);
    hgemm_k<<<gz, 256, HSMEM>>>(rthp, rtlp, N1C, Ghp, Glp, N1C, P, N2C, N1C / 2, nullptr);
    zupd_k<true><<<(BC * N2C / 4) / 256, 256>>>(P, za, wbuf, c, out, nullptr);
}

// round 9
// speedup vs baseline: 4.1215x; 1.1398x over previous
#include <cuda_runtime.h>
#include <cuda_fp16.h>
#include <math.h>
#include <stdint.h>

// ----------------------------------------------------------------------------
// DYS_opt_net.  ALL GEMMs on legacy fp16 mma.sync m16n8k16 with fp16x3 split
// (hh+hl+lh, fp32 accum) and static per-matrix scaling. Newton-Schulz: 4 cheap
// single-product iterations + 3 precise fp16x3 iterations, with explicit
// symmetrization each iteration (the A*B^T GEMM form makes X S X^T exactly
// symmetric, so antisymmetric error in X would otherwise DOUBLE per iter).
// z' = relu(z) - a*w + c - (G (A u^T))^T,  u = |z| - a*w
// ----------------------------------------------------------------------------

#define N1C 1024
#define N2C 4096
#define BC  256
#define DC  512
#define HC  2048

#define ALPHA_C 0.05f
#define EPS_C   0.01f
#define NS_ITERS 7
#define NS_CHEAP 4
#define PI_ITERS 12

#define A_SC 64.f
#define G_SC 32.f
#define INV_A_SC 0.015625f
#define INV_G_SC 0.03125f

// fp16 GEMM tile config
#define HBK 32
#define HSTR 40                  // halves per smem row (32 + 8 pad)
#define HPL (128*HSTR)
#define HST (4*HPL)
#define HSMEM (2*HST*2)          // 81920 B

__device__ float g_S  [(size_t)N1C*N1C];
__device__ float g_Xa [(size_t)N1C*N1C];
__device__ float g_Xb [(size_t)N1C*N1C];
__device__ float g_T  [(size_t)N1C*N1C];
__device__ float g_G  [(size_t)N2C*N1C];
__device__ float g_At [(size_t)N2C*N1C];
__device__ float g_W1t[(size_t)HC*DC];
__device__ float g_W2t[(size_t)N2C*HC];
__device__ float g_c  [N2C];
__device__ float g_tv [N1C];
__device__ float g_v  [N1C];
__device__ float g_y  [N1C];
__device__ float g_h  [(size_t)BC*HC];
__device__ float g_w  [(size_t)BC*N2C];
__device__ float g_za [(size_t)BC*N2C];
__device__ float g_zb [(size_t)BC*N2C];
__device__ float g_P  [(size_t)4*1024*1024];
__device__ __half g_Ah [(size_t)N1C*N2C];
__device__ __half g_Al [(size_t)N1C*N2C];
__device__ __half g_Gh [(size_t)N2C*N1C];
__device__ __half g_Gl [(size_t)N2C*N1C];
__device__ __half g_uh [(size_t)BC*N2C];
__device__ __half g_ul [(size_t)BC*N2C];
__device__ __half g_rth[(size_t)BC*N1C];
__device__ __half g_rtl[(size_t)BC*N1C];
__device__ __half g_Sh [(size_t)N1C*N1C];
__device__ __half g_Sl [(size_t)N1C*N1C];
__device__ __half g_Xh [(size_t)N1C*N1C];
__device__ __half g_Xl [(size_t)N1C*N1C];
__device__ __half g_Th [(size_t)N1C*N1C];
__device__ __half g_Tl [(size_t)N1C*N1C];
__device__ __half g_dh [(size_t)BC*DC];
__device__ __half g_dl [(size_t)BC*DC];
__device__ __half g_W1h[(size_t)HC*DC];
__device__ __half g_W1l[(size_t)HC*DC];
__device__ __half g_W2h[(size_t)N2C*HC];
__device__ __half g_W2l[(size_t)N2C*HC];
__device__ __half g_hph[(size_t)BC*HC];
__device__ __half g_hpl[(size_t)BC*HC];
__device__ float g_lam;
__device__ float g_ss;
__device__ int   g_flag;
__device__ int   g_cnt;

// ---------------- small utility kernels ----------------
__global__ void init_k() { g_ss = 0.f; g_flag = 0; g_cnt = 0; }

__global__ void copy4_k(float4* __restrict__ dst, const float4* __restrict__ src) {
    int i = blockIdx.x * blockDim.x + threadIdx.x;
    dst[i] = src[i];
}

__global__ void fill_k(float* v, float val, int n) {
    int i = blockIdx.x * blockDim.x + threadIdx.x;
    if (i < n) v[i] = val;
}

// in-place symmetrization: X <- (X + X^T)/2.  Each (i<j) pair handled by
// exactly one thread (writes both mirror elements) -> race-free.
__global__ void symm_k(float* __restrict__ X) {
    int j = blockIdx.x * 32 + (threadIdx.x & 31);
    int i = blockIdx.y * 8 + (threadIdx.x >> 5);
    if (i < j) {
        size_t ij = (size_t)i * N1C + j;
        size_t ji = (size_t)j * N1C + i;
        float m = 0.5f * (X[ij] + X[ji]);
        X[ij] = m;
        X[ji] = m;
    }
}

__global__ void spmv_k(const float* __restrict__ M_, const float* __restrict__ v,
                       float* __restrict__ y) {
    int row = blockIdx.x * 8 + threadIdx.y;
    const float* mr = M_ + (size_t)row * N1C;
    float s = 0.f;
    for (int j = threadIdx.x; j < N1C; j += 32) s += mr[j] * v[j];
    #pragma unroll
    for (int o = 16; o; o >>= 1) s += __shfl_xor_sync(0xffffffffu, s, o);
    if (threadIdx.x == 0) y[row] = s;
}

__global__ void pi_norm_k(const float* __restrict__ y, float* __restrict__ v) {
    __shared__ float red[256];
    float s = 0.f;
    for (int i = threadIdx.x; i < N1C; i += 256) { float t = y[i]; s += t * t; }
    red[threadIdx.x] = s; __syncthreads();
    for (int o = 128; o; o >>= 1) {
        if (threadIdx.x < o) red[threadIdx.x] += red[threadIdx.x + o];
        __syncthreads();
    }
    float nrm = sqrtf(red[0]);
    float inv = 1.f / nrm;
    for (int i = threadIdx.x; i < N1C; i += 256) v[i] = y[i] * inv;
    if (threadIdx.x == 0) g_lam = nrm;
}

__global__ void initX_k(float* X) {
    float a = 1.8f / g_lam;
    int i = blockIdx.x * 256 + threadIdx.x;
    int rr = i / N1C, cc = i % N1C;
    X[i] = (rr == cc) ? a : 0.f;
}

__global__ void atmv_k(const float* __restrict__ A, const float* __restrict__ t,
                       float* __restrict__ c) {
    __shared__ float ts[N1C];
    for (int i = threadIdx.x; i < N1C; i += 256) ts[i] = t[i];
    __syncthreads();
    int j = blockIdx.x * 256 + threadIdx.x;
    float s = 0.f;
    for (int i = 0; i < N1C; i++) s += A[(size_t)i * N2C + j] * ts[i];
    c[j] = s;
}

__global__ void transp_k(float* __restrict__ dst, const float* __restrict__ src,
                         int R, int C) {
    __shared__ float t[32][33];
    int bx = blockIdx.x * 32, by = blockIdx.y * 32;
    #pragma unroll
    for (int i = 0; i < 4; i++) {
        int r = by + threadIdx.y + i * 8;
        t[threadIdx.y + i * 8][threadIdx.x] = src[(size_t)r * C + bx + threadIdx.x];
    }
    __syncthreads();
    #pragma unroll
    for (int i = 0; i < 4; i++) {
        int r = bx + threadIdx.y + i * 8;
        dst[(size_t)r * R + by + threadIdx.x] = t[threadIdx.x][threadIdx.y + i * 8];
    }
}

__device__ __forceinline__ void split2h(float x, __half& h, __half& l) {
    h = __float2half_rn(x);
    l = __float2half_rn(x - __half2float(h));
}

// split scaled fp32 -> (hi, lo) fp16 planes; 8 elements per thread
__global__ void splitH_k(const float* __restrict__ src, __half* __restrict__ ph,
                         __half* __restrict__ pl, float scale) {
    size_t e = ((size_t)blockIdx.x * 256 + threadIdx.x) * 8;
    uint32_t hh[4], ll[4];
    #pragma unroll
    for (int p = 0; p < 4; p++) {
        __half h0, h1, l0, l1;
        split2h(src[e + 2 * p] * scale, h0, l0);
        split2h(src[e + 2 * p + 1] * scale, h1, l1);
        __half2 hp = __halves2half2(h0, h1), lp = __halves2half2(l0, l1);
        hh[p] = *(uint32_t*)&hp; ll[p] = *(uint32_t*)&lp;
    }
    *(uint4*)(ph + e) = make_uint4(hh[0], hh[1], hh[2], hh[3]);
    *(uint4*)(pl + e) = make_uint4(ll[0], ll[1], ll[2], ll[3]);
}

// u = |z| - a*w -> u planes; 4 elements per thread
__global__ void u0_k(const float* __restrict__ z, const float* __restrict__ w) {
    size_t i = (size_t)blockIdx.x * 256 + threadIdx.x;
    float4 zv = ((const float4*)z)[i];
    float4 wv = ((const float4*)w)[i];
    __half h0, h1, h2, h3, l0, l1, l2, l3;
    split2h(fabsf(zv.x) - ALPHA_C * wv.x, h0, l0);
    split2h(fabsf(zv.y) - ALPHA_C * wv.y, h1, l1);
    split2h(fabsf(zv.z) - ALPHA_C * wv.z, h2, l2);
    split2h(fabsf(zv.w) - ALPHA_C * wv.w, h3, l3);
    __half2 ha = __halves2half2(h0, h1), hb = __halves2half2(h2, h3);
    __half2 la = __halves2half2(l0, l1), lb = __halves2half2(l2, l3);
    ((uint2*)g_uh)[i] = make_uint2(*(uint32_t*)&ha, *(uint32_t*)&hb);
    ((uint2*)g_ul)[i] = make_uint2(*(uint32_t*)&la, *(uint32_t*)&lb);
}

// ---------------- reduce kernels (2x float4 ILP, scaled) ----------------
__global__ void reduce_sum_k(const float* __restrict__ P, float* __restrict__ out,
                             size_t stride4, int ns, float scale) {
    size_t i = ((size_t)blockIdx.x * 256 + threadIdx.x) * 2;
    const float4* p = (const float4*)P;
    float4 s0 = p[i], s1 = p[i + 1];
    for (int sp = 1; sp < ns; sp++) {
        float4 t0 = p[(size_t)sp * stride4 + i];
        float4 t1 = p[(size_t)sp * stride4 + i + 1];
        s0.x += t0.x; s0.y += t0.y; s0.z += t0.z; s0.w += t0.w;
        s1.x += t1.x; s1.y += t1.y; s1.z += t1.z; s1.w += t1.w;
    }
    s0.x *= scale; s0.y *= scale; s0.z *= scale; s0.w *= scale;
    s1.x *= scale; s1.y *= scale; s1.z *= scale; s1.w *= scale;
    ((float4*)out)[i] = s0;
    ((float4*)out)[i + 1] = s1;
}

__global__ void reduce_ns_k(const float* __restrict__ P, const float* __restrict__ X,
                            float* __restrict__ out, size_t stride4, int ns, float scale) {
    size_t i = ((size_t)blockIdx.x * 256 + threadIdx.x) * 2;
    const float4* p = (const float4*)P;
    float4 s0 = p[i], s1 = p[i + 1];
    for (int sp = 1; sp < ns; sp++) {
        float4 t0 = p[(size_t)sp * stride4 + i];
        float4 t1 = p[(size_t)sp * stride4 + i + 1];
        s0.x += t0.x; s0.y += t0.y; s0.z += t0.z; s0.w += t0.w;
        s1.x += t1.x; s1.y += t1.y; s1.z += t1.z; s1.w += t1.w;
    }
    float4 x0 = ((const float4*)X)[i], x1 = ((const float4*)X)[i + 1];
    float4 o0, o1;
    o0.x = 2.f * x0.x - s0.x * scale; o0.y = 2.f * x0.y - s0.y * scale;
    o0.z = 2.f * x0.z - s0.z * scale; o0.w = 2.f * x0.w - s0.w * scale;
    o1.x = 2.f * x1.x - s1.x * scale; o1.y = 2.f * x1.y - s1.y * scale;
    o1.z = 2.f * x1.z - s1.z * scale; o1.w = 2.f * x1.w - s1.w * scale;
    ((float4*)out)[i] = o0;
    ((float4*)out)[i + 1] = o1;
}

template<bool RELU>
__global__ void reduce_bias_k(const float* __restrict__ P, const float* __restrict__ bias,
                              float* __restrict__ out, size_t stride4, int ns, int n4,
                              float scale) {
    size_t i = ((size_t)blockIdx.x * 256 + threadIdx.x) * 2;
    const float4* p = (const float4*)P;
    float4 s0 = p[i], s1 = p[i + 1];
    for (int sp = 1; sp < ns; sp++) {
        float4 t0 = p[(size_t)sp * stride4 + i];
        float4 t1 = p[(size_t)sp * stride4 + i + 1];
        s0.x += t0.x; s0.y += t0.y; s0.z += t0.z; s0.w += t0.w;
        s1.x += t1.x; s1.y += t1.y; s1.z += t1.z; s1.w += t1.w;
    }
    float4 b0 = ((const float4*)bias)[i % n4];
    float4 b1 = ((const float4*)bias)[(i + 1) % n4];
    s0.x = s0.x * scale + b0.x; s0.y = s0.y * scale + b0.y;
    s0.z = s0.z * scale + b0.z; s0.w = s0.w * scale + b0.w;
    s1.x = s1.x * scale + b1.x; s1.y = s1.y * scale + b1.y;
    s1.z = s1.z * scale + b1.z; s1.w = s1.w * scale + b1.w;
    if (RELU) {
        s0.x = fmaxf(s0.x, 0.f); s0.y = fmaxf(s0.y, 0.f);
        s0.z = fmaxf(s0.z, 0.f); s0.w = fmaxf(s0.w, 0.f);
        s1.x = fmaxf(s1.x, 0.f); s1.y = fmaxf(s1.y, 0.f);
        s1.z = fmaxf(s1.z, 0.f); s1.w = fmaxf(s1.w, 0.f);
    }
    ((float4*)out)[i] = s0;
    ((float4*)out)[i + 1] = s1;
}

// sum 8 partials of 64*(A u^T) [N1C][BC]; write rt planes [BC][N1C] (x 1/64)
__global__ void reduce_tr_k(const float* __restrict__ P, const int* __restrict__ guard) {
    if (guard && *guard) return;
    __shared__ float t[32][33];
    int bm = blockIdx.x * 32;
    int bb = blockIdx.y * 32;
    #pragma unroll
    for (int i = 0; i < 4; i++) {
        int m = bm + threadIdx.y + i * 8;
        size_t idx = (size_t)m * BC + bb + threadIdx.x;
        float s = 0.f;
        #pragma unroll
        for (int sp = 0; sp < 8; sp++) s += P[(size_t)sp * N1C * BC + idx];
        t[threadIdx.y + i * 8][threadIdx.x] = s;
    }
    __syncthreads();
    #pragma unroll
    for (int i = 0; i < 4; i++) {
        int b = bb + threadIdx.y + i * 8;
        float vv = t[threadIdx.x][threadIdx.y + i * 8] * INV_A_SC;
        __half h, l;
        split2h(vv, h, l);
        size_t o = (size_t)b * N1C + bm + threadIdx.x;
        g_rth[o] = h;
        g_rtl[o] = l;
    }
}

// z-update: zn = relu(z) - a*w + c - (1/32)*sum; + u planes + convergence check
template<bool FIN>
__global__ void zupd_k(const float* __restrict__ P, const float* __restrict__ zin,
                       const float* __restrict__ w, const float* __restrict__ c,
                       float* __restrict__ zout, const int* __restrict__ guard) {
    size_t gid = (size_t)blockIdx.x * 256 + threadIdx.x;
    size_t i = gid * 2;
    if (!FIN && guard && *guard) {
        ((float4*)zout)[i] = ((const float4*)zin)[i];
        ((float4*)zout)[i + 1] = ((const float4*)zin)[i + 1];
        return;
    }
    const float4* p = (const float4*)P;
    float ov[8], wv8[8];
    float ls = 0.f;
    #pragma unroll
    for (int q = 0; q < 2; q++) {
        float4 s = p[i + q];
        float4 t = p[(size_t)(BC * (N2C / 4)) + i + q];
        s.x += t.x; s.y += t.y; s.z += t.z; s.w += t.w;
        float4 z = ((const float4*)zin)[i + q];
        float4 ww = ((const float4*)w)[i + q];
        float4 cc = ((const float4*)c)[(i + q) & (N2C / 4 - 1)];
        float4 o;
        o.x = fmaxf(z.x, 0.f) - ALPHA_C * ww.x + cc.x - s.x * INV_G_SC;
        o.y = fmaxf(z.y, 0.f) - ALPHA_C * ww.y + cc.y - s.y * INV_G_SC;
        o.z = fmaxf(z.z, 0.f) - ALPHA_C * ww.z + cc.z - s.z * INV_G_SC;
        o.w = fmaxf(z.w, 0.f) - ALPHA_C * ww.w + cc.w - s.w * INV_G_SC;
        if (FIN) {
            o.x = fmaxf(o.x, 0.f); o.y = fmaxf(o.y, 0.f);
            o.z = fmaxf(o.z, 0.f); o.w = fmaxf(o.w, 0.f);
            ((float4*)zout)[i + q] = o;
        } else {
            ((float4*)zout)[i + q] = o;
            float dx = o.x - z.x, dy = o.y - z.y, dz = o.z - z.z, dw = o.w - z.w;
            ls += dx * dx + dy * dy + dz * dz + dw * dw;
            ov[q * 4 + 0] = o.x; ov[q * 4 + 1] = o.y;
            ov[q * 4 + 2] = o.z; ov[q * 4 + 3] = o.w;
            wv8[q * 4 + 0] = ww.x; wv8[q * 4 + 1] = ww.y;
            wv8[q * 4 + 2] = ww.z; wv8[q * 4 + 3] = ww.w;
        }
    }
    if (!FIN) {
        uint32_t hh[4], ll[4];
        #pragma unroll
        for (int pq = 0; pq < 4; pq++) {
            __half h0, h1, l0, l1;
            split2h(fabsf(ov[2 * pq]) - ALPHA_C * wv8[2 * pq], h0, l0);
            split2h(fabsf(ov[2 * pq + 1]) - ALPHA_C * wv8[2 * pq + 1], h1, l1);
            __half2 hp = __halves2half2(h0, h1), lp = __halves2half2(l0, l1);
            hh[pq] = *(uint32_t*)&hp; ll[pq] = *(uint32_t*)&lp;
        }
        size_t e = gid * 8;
        *(uint4*)(g_uh + e) = make_uint4(hh[0], hh[1], hh[2], hh[3]);
        *(uint4*)(g_ul + e) = make_uint4(ll[0], ll[1], ll[2], ll[3]);

        __shared__ float red[256];
        red[threadIdx.x] = ls;
        __syncthreads();
        for (int o2 = 128; o2; o2 >>= 1) {
            if (threadIdx.x < o2) red[threadIdx.x] += red[threadIdx.x + o2];
            __syncthreads();
        }
        if (threadIdx.x == 0) {
            atomicAdd(&g_ss, red[0]);
            __threadfence();
            int t = atomicAdd(&g_cnt, 1);
            if (t == (int)gridDim.x - 1) {
                if (g_ss <= EPS_C * EPS_C) g_flag = 1;
                g_ss = 0.f;
                g_cnt = 0;
            }
        }
    }
}

// ---------------- fp16 GEMM (NP=3: hh+hl+lh; NP=1: hh only) ----------------
__device__ __forceinline__ uint32_t smem_u32(const void* p) {
    uint32_t a;
    asm("{ .reg .u64 t; cvta.to.shared.u64 t, %1; cvt.u32.u64 %0, t; }" : "=r"(a) : "l"(p));
    return a;
}
__device__ __forceinline__ void cp16(uint32_t dst, const void* src) {
    asm volatile("cp.async.cg.shared.global [%0], [%1], 16;" :: "r"(dst), "l"(src));
}
__device__ __forceinline__ void ldsm4(uint32_t* r, uint32_t a) {
    asm volatile("ldmatrix.sync.aligned.m8n8.x4.shared.b16 {%0,%1,%2,%3}, [%4];"
        : "=r"(r[0]), "=r"(r[1]), "=r"(r[2]), "=r"(r[3]) : "r"(a));
}
__device__ __forceinline__ void mma16(float* c, const uint32_t* a, const uint32_t* b) {
    asm volatile("mma.sync.aligned.m16n8k16.row.col.f32.f16.f16.f32 "
        "{%0,%1,%2,%3}, {%4,%5,%6,%7}, {%8,%9}, {%0,%1,%2,%3};"
        : "+f"(c[0]), "+f"(c[1]), "+f"(c[2]), "+f"(c[3])
        : "r"(a[0]), "r"(a[1]), "r"(a[2]), "r"(a[3]), "r"(b[0]), "r"(b[1]));
}

template<int NP>
__global__ void __launch_bounds__(256)
hgemm_k(const __half* __restrict__ Ahp, const __half* __restrict__ Alp, int lda,
        const __half* __restrict__ Bhp, const __half* __restrict__ Blp, int ldb,
        float* __restrict__ Cg, int N, int kchunk, const int* __restrict__ guard)
{
    if (guard && *guard) return;
    extern __shared__ __half hsm[];
    const int tid = threadIdx.x, lane = tid & 31, wid = tid >> 5;
    const int wm = wid >> 2, wn = wid & 3;
    const int m0 = blockIdx.y * 128, n0 = blockIdx.x * 128;
    const int k0 = blockIdx.z * kchunk;
    const int ST = kchunk / HBK;
    const __half* psrc[4] = { Ahp, Alp, Bhp, Blp };
    uint32_t sbase = smem_u32(hsm);

    auto load = [&](int s) {
        int buf = s & 1;
        int kb = k0 + s * HBK;
        #pragma unroll
        for (int t = 0; t < (NP == 3 ? 8 : 4); t++) {
            int id = t * 256 + tid;
            int pl = (NP == 3) ? (id >> 9) : ((id >> 9) * 2);
            int idx = id & 511;
            int row = idx >> 2, kc = idx & 3;
            int isB = pl >> 1;
            const __half* src = psrc[pl] +
                (size_t)((isB ? n0 : m0) + row) * (isB ? ldb : lda) + kb + kc * 8;
            uint32_t dst = sbase + (uint32_t)(buf * HST + pl * HPL + row * HSTR + kc * 8) * 2;
            cp16(dst, src);
        }
    };

    float acc[4][4][4];
    #pragma unroll
    for (int f = 0; f < 4; f++)
        #pragma unroll
        for (int g = 0; g < 4; g++)
            #pragma unroll
            for (int e = 0; e < 4; e++) acc[f][g][e] = 0.f;

    load(0);
    asm volatile("cp.async.commit_group;");
    load(1);
    asm volatile("cp.async.commit_group;");

    const int offA = (lane & 15) * HSTR + (lane >> 4) * 8;
    const int offB = ((lane & 7) + ((lane >> 4) << 3)) * HSTR + ((lane >> 3) & 1) * 8;

    for (int s = 0; s < ST; s++) {
        asm volatile("cp.async.wait_group 1;");
        __syncthreads();
        uint32_t stg = sbase + (uint32_t)((s & 1) * HST) * 2;
        #pragma unroll
        for (int ks = 0; ks < 2; ks++) {
            uint32_t aH[4][4], aL[4][4], bH[4][2], bL[4][2];
            #pragma unroll
            for (int f = 0; f < 4; f++) {
                uint32_t base = stg + (uint32_t)((wm * 64 + f * 16) * HSTR + ks * 16 + offA) * 2;
                ldsm4(aH[f], base);
                if (NP == 3) ldsm4(aL[f], base + HPL * 2);
            }
            #pragma unroll
            for (int gp = 0; gp < 2; gp++) {
                uint32_t r[4];
                uint32_t base = stg + (uint32_t)(2 * HPL + (wn * 32 + gp * 16) * HSTR + ks * 16 + offB) * 2;
                ldsm4(r, base);
                bH[gp * 2][0] = r[0]; bH[gp * 2][1] = r[1];
                bH[gp * 2 + 1][0] = r[2]; bH[gp * 2 + 1][1] = r[3];
                if (NP == 3) {
                    ldsm4(r, base + HPL * 2);
                    bL[gp * 2][0] = r[0]; bL[gp * 2][1] = r[1];
                    bL[gp * 2 + 1][0] = r[2]; bL[gp * 2 + 1][1] = r[3];
                }
            }
            #pragma unroll
            for (int f = 0; f < 4; f++)
                #pragma unroll
                for (int g = 0; g < 4; g++) {
                    mma16(acc[f][g], aH[f], bH[g]);
                    if (NP == 3) {
                        mma16(acc[f][g], aH[f], bL[g]);
                        mma16(acc[f][g], aL[f], bH[g]);
                    }
                }
        }
        __syncthreads();
        if (s + 2 < ST) load(s + 2);
        asm volatile("cp.async.commit_group;");
    }

    size_t off = (size_t)blockIdx.z * ((size_t)gridDim.y * 128) * N;
    const int tr = lane >> 2, tc = (lane & 3) * 2;
    #pragma unroll
    for (int f = 0; f < 4; f++) {
        int m = m0 + wm * 64 + f * 16 + tr;
        #pragma unroll
        for (int g = 0; g < 4; g++) {
            int n = n0 + wn * 32 + g * 8 + tc;
            *(float2*)&Cg[off + (size_t)m * N + n] = make_float2(acc[f][g][0], acc[f][g][1]);
            *(float2*)&Cg[off + (size_t)(m + 8) * N + n] = make_float2(acc[f][g][2], acc[f][g][3]);
        }
    }
}

// ---------------- host ----------------
extern "C" void kernel_launch(void* const* d_in, const int* in_sizes, int n_in,
                              void* d_out, int out_size) {
    (void)in_sizes; (void)n_in; (void)out_size;
    const float* dd  = (const float*)d_in[0];
    const float* dA  = (const float*)d_in[1];
    const float* dB  = (const float*)d_in[2];
    const float* dW1 = (const float*)d_in[3];
    const float* db1 = (const float*)d_in[4];
    const float* dW2 = (const float*)d_in[5];
    const float* db2 = (const float*)d_in[6];
    const float* dz0 = (const float*)d_in[7];
    float* out = (float*)d_out;

    void* p;
    cudaGetSymbolAddress(&p, g_S);   float* S    = (float*)p;
    cudaGetSymbolAddress(&p, g_Xa);  float* Xa   = (float*)p;
    cudaGetSymbolAddress(&p, g_Xb);  float* Xb   = (float*)p;
    cudaGetSymbolAddress(&p, g_T);   float* Tm   = (float*)p;
    cudaGetSymbolAddress(&p, g_G);   float* G    = (float*)p;
    cudaGetSymbolAddress(&p, g_At);  float* At   = (float*)p;
    cudaGetSymbolAddress(&p, g_W1t); float* W1t  = (float*)p;
    cudaGetSymbolAddress(&p, g_W2t); float* W2t  = (float*)p;
    cudaGetSymbolAddress(&p, g_c);   float* c    = (float*)p;
    cudaGetSymbolAddress(&p, g_tv);  float* tv   = (float*)p;
    cudaGetSymbolAddress(&p, g_v);   float* v    = (float*)p;
    cudaGetSymbolAddress(&p, g_y);   float* y    = (float*)p;
    cudaGetSymbolAddress(&p, g_h);   float* h    = (float*)p;
    cudaGetSymbolAddress(&p, g_w);   float* wbuf = (float*)p;
    cudaGetSymbolAddress(&p, g_za);  float* za   = (float*)p;
    cudaGetSymbolAddress(&p, g_zb);  float* zbb  = (float*)p;
    cudaGetSymbolAddress(&p, g_P);   float* P    = (float*)p;
    cudaGetSymbolAddress(&p, g_flag); int* flag  = (int*)p;
    cudaGetSymbolAddress(&p, g_Ah);  __half* Ahp = (__half*)p;
    cudaGetSymbolAddress(&p, g_Al);  __half* Alp = (__half*)p;
    cudaGetSymbolAddress(&p, g_Gh);  __half* Ghp = (__half*)p;
    cudaGetSymbolAddress(&p, g_Gl);  __half* Glp = (__half*)p;
    cudaGetSymbolAddress(&p, g_uh);  __half* uhp = (__half*)p;
    cudaGetSymbolAddress(&p, g_ul);  __half* ulp = (__half*)p;
    cudaGetSymbolAddress(&p, g_rth); __half* rthp = (__half*)p;
    cudaGetSymbolAddress(&p, g_rtl); __half* rtlp = (__half*)p;
    cudaGetSymbolAddress(&p, g_Sh);  __half* Shp = (__half*)p;
    cudaGetSymbolAddress(&p, g_Sl);  __half* Slp = (__half*)p;
    cudaGetSymbolAddress(&p, g_Xh);  __half* Xhp = (__half*)p;
    cudaGetSymbolAddress(&p, g_Xl);  __half* Xlp = (__half*)p;
    cudaGetSymbolAddress(&p, g_Th);  __half* Thp = (__half*)p;
    cudaGetSymbolAddress(&p, g_Tl);  __half* Tlp = (__half*)p;
    cudaGetSymbolAddress(&p, g_dh);  __half* dhp = (__half*)p;
    cudaGetSymbolAddress(&p, g_dl);  __half* dlp = (__half*)p;
    cudaGetSymbolAddress(&p, g_W1h); __half* W1h = (__half*)p;
    cudaGetSymbolAddress(&p, g_W1l); __half* W1l = (__half*)p;
    cudaGetSymbolAddress(&p, g_W2h); __half* W2h = (__half*)p;
    cudaGetSymbolAddress(&p, g_W2l); __half* W2l = (__half*)p;
    cudaGetSymbolAddress(&p, g_hph); __half* hph = (__half*)p;
    cudaGetSymbolAddress(&p, g_hpl); __half* hpl = (__half*)p;

    cudaFuncSetAttribute(hgemm_k<3>,
                         cudaFuncAttributeMaxDynamicSharedMemorySize, HSMEM);
    cudaFuncSetAttribute(hgemm_k<1>,
                         cudaFuncAttributeMaxDynamicSharedMemorySize, HSMEM);

    init_k<<<1, 1>>>();
    copy4_k<<<(BC * N2C / 4) / 256, 256>>>((float4*)za, (const float4*)dz0);

    // A planes (x64)
    splitH_k<<<(int)(((size_t)N1C * N2C / 8) / 256), 256>>>(dA, Ahp, Alp, A_SC);

    // S = A A^T : hgemm, accum = 4096*S
    {
        dim3 g(N1C / 128, N1C / 128, 2);
        hgemm_k<3><<<g, 256, HSMEM>>>(Ahp, Alp, N2C, Ahp, Alp, N2C, P, N1C, N2C / 2, nullptr);
        reduce_sum_k<<<(N1C * N1C / 8) / 256, 256>>>(P, S, (size_t)N1C * N1C / 4, 2, 1.f / 4096.f);
    }

    // power iteration (fp32 S)
    fill_k<<<N1C / 256, 256>>>(v, 0.03125f, N1C);
    for (int i = 0; i < PI_ITERS; i++) {
        spmv_k<<<N1C / 8, dim3(32, 8)>>>(S, v, y);
        pi_norm_k<<<1, 256>>>(y, v);
    }
    initX_k<<<(N1C * N1C) / 256, 256>>>(Xa);

    // S planes (x16)
    splitH_k<<<(int)(((size_t)N1C * N1C / 8) / 256), 256>>>(S, Shp, Slp, 16.f);

    // Newton-Schulz: 4 cheap (NP=1) + 3 precise (NP=3), symmetrized each iter
    float* Xc = Xa; float* Xn = Xb;
    {
        dim3 g(N1C / 128, N1C / 128, 2);
        dim3 gsym(N1C / 32, N1C / 8);
        size_t s4 = (size_t)N1C * N1C / 4;
        int nsgrid = (N1C * N1C / 8) / 256;
        for (int i = 0; i < NS_ITERS; i++) {
            symm_k<<<gsym, 256>>>(Xc);
            splitH_k<<<(N1C * N1C / 8) / 256, 256>>>(Xc, Xhp, Xlp, 32.f);
            if (i < NS_CHEAP)
                hgemm_k<1><<<g, 256, HSMEM>>>(Xhp, Xlp, N1C, Shp, Slp, N1C, P, N1C, N1C / 2, nullptr);
            else
                hgemm_k<3><<<g, 256, HSMEM>>>(Xhp, Xlp, N1C, Shp, Slp, N1C, P, N1C, N1C / 2, nullptr);
            reduce_sum_k<<<nsgrid, 256>>>(P, Tm, s4, 2, 1.f / 512.f);
            splitH_k<<<(N1C * N1C / 8) / 256, 256>>>(Tm, Thp, Tlp, 32.f);
            if (i < NS_CHEAP)
                hgemm_k<1><<<g, 256, HSMEM>>>(Thp, Tlp, N1C, Xhp, Xlp, N1C, P, N1C, N1C / 2, nullptr);
            else
                hgemm_k<3><<<g, 256, HSMEM>>>(Thp, Tlp, N1C, Xhp, Xlp, N1C, P, N1C, N1C / 2, nullptr);
            reduce_ns_k<<<nsgrid, 256>>>(P, Xc, Xn, s4, 2, 1.f / 1024.f);
            float* t2 = Xc; Xc = Xn; Xn = t2;
        }
        // final symmetrization before using X for c and G
        symm_k<<<gsym, 256>>>(Xc);
    }

    // c = A^T (X b)
    spmv_k<<<N1C / 8, dim3(32, 8)>>>(Xc, dB, tv);
    atmv_k<<<N2C / 256, 256>>>(dA, tv, c);

    // G = A^T X: At planes (x64, temp in Gh/Gl), X planes (x32) -> accum 2048*G
    transp_k<<<dim3(N2C / 32, N1C / 32), dim3(32, 8)>>>(At, dA, N1C, N2C);
    splitH_k<<<(int)(((size_t)N2C * N1C / 8) / 256), 256>>>(At, Ghp, Glp, A_SC);
    splitH_k<<<(N1C * N1C / 8) / 256, 256>>>(Xc, Xhp, Xlp, 32.f);
    {
        dim3 g(N1C / 128, N2C / 128, 1);
        hgemm_k<3><<<g, 256, HSMEM>>>(Ghp, Glp, N1C, Xhp, Xlp, N1C, P, N1C, N1C, nullptr);
        reduce_sum_k<<<(int)(((size_t)N2C * N1C / 8) / 256), 256>>>(
            P, G, 0, 1, 1.f / 2048.f);
    }
    // G planes (x32), overwriting At planes
    splitH_k<<<(int)(((size_t)N2C * N1C / 8) / 256), 256>>>(G, Ghp, Glp, G_SC);

    // MLP on hgemm
    transp_k<<<dim3(HC / 32, DC / 32), dim3(32, 8)>>>(W1t, dW1, DC, HC);
    splitH_k<<<(int)(((size_t)HC * DC / 8) / 256), 256>>>(W1t, W1h, W1l, 32.f);
    transp_k<<<dim3(N2C / 32, HC / 32), dim3(32, 8)>>>(W2t, dW2, HC, N2C);
    splitH_k<<<(int)(((size_t)N2C * HC / 8) / 256), 256>>>(W2t, W2h, W2l, 32.f);
    splitH_k<<<(BC * DC / 8) / 256, 256>>>(dd, dhp, dlp, 1.f);
    {
        dim3 g1(HC / 128, BC / 128, 4);
        hgemm_k<3><<<g1, 256, HSMEM>>>(dhp, dlp, DC, W1h, W1l, DC, P, HC, DC / 4, nullptr);
        reduce_bias_k<true><<<(BC * HC / 8) / 256, 256>>>(
            P, db1, h, (size_t)BC * HC / 4, 4, HC / 4, 1.f / 32.f);
        splitH_k<<<(BC * HC / 8) / 256, 256>>>(h, hph, hpl, 1.f);
        dim3 g2(N2C / 128, BC / 128, 2);
        hgemm_k<3><<<g2, 256, HSMEM>>>(hph, hpl, HC, W2h, W2l, HC, P, N2C, HC / 2, nullptr);
        reduce_bias_k<false><<<(BC * N2C / 8) / 256, 256>>>(
            P, db2, wbuf, (size_t)BC * N2C / 4, 2, N2C / 4, 1.f / 32.f);
    }

    // initial u planes
    u0_k<<<(BC * N2C / 4) / 256, 256>>>(za, wbuf);

    // DYS loop
    dim3 gr(BC / 128, N1C / 128, 8);     // 64*(A u^T): split8
    dim3 gz(N2C / 128, BC / 128, 2);     // 32*(G r)^T: split2
    float* zb2[2] = { za, zbb };
    for (int it = 1; it <= 50; ++it) {
        const float* zin = zb2[(it - 1) & 1];
        float* zout = zb2[it & 1];
        hgemm_k<3><<<gr, 256, HSMEM>>>(Ahp, Alp, N2C, uhp, ulp, N2C, P, BC, N2C / 8, flag);
        reduce_tr_k<<<dim3(N1C / 32, BC / 32), dim3(32, 8)>>>(P, flag);
        hgemm_k<3><<<gz, 256, HSMEM>>>(rthp, rtlp, N1C, Ghp, Glp, N1C, P, N2C, N1C / 2, flag);
        zupd_k<false><<<(BC * N2C / 8) / 256, 256>>>(P, zin, wbuf, c, zout, flag);
    }

    // final unguarded step, relu into d_out
    hgemm_k<3><<<gr, 256, HSMEM>>>(Ahp, Alp, N2C, uhp, ulp, N2C, P, BC, N2C / 8, nullptr);
    reduce_tr_k<<<dim3(N1C / 32, BC / 32), dim3(32, 8)>>>(P, nullptr);
    hgemm_k<3><<<gz, 256, HSMEM>>>(rthp, rtlp, N1C, Ghp, Glp, N1C, P, N2C, N1C / 2, nullptr);
    zupd_k<true><<<(BC * N2C / 8) / 256, 256>>>(P, za, wbuf, c, out, nullptr);
}

// round 10
// speedup vs baseline: 4.1523x; 1.0075x over previous
#include <cuda_runtime.h>
#include <cuda_fp16.h>
#include <math.h>
#include <stdint.h>

// ----------------------------------------------------------------------------
// DYS_opt_net.  ALL GEMMs on legacy fp16 mma.sync m16n8k16 with fp16x3 split
// (hh+hl+lh, fp32 accum), static per-matrix scaling, explicit symmetrization
// in Newton-Schulz (4 cheap + 2 precise iters). R10: product-pass MMA ordering
// (16 independent MMAs between accumulator reuses) + 3-stage cp.async pipeline.
// z' = relu(z) - a*w + c - (G (A u^T))^T,  u = |z| - a*w
// ----------------------------------------------------------------------------

#define N1C 1024
#define N2C 4096
#define BC  256
#define DC  512
#define HC  2048

#define ALPHA_C 0.05f
#define EPS_C   0.01f
#define NS_ITERS 6
#define NS_CHEAP 4
#define PI_ITERS 12

#define A_SC 64.f
#define G_SC 32.f
#define INV_A_SC 0.015625f
#define INV_G_SC 0.03125f

// fp16 GEMM tile config
#define HBK 32
#define HSTR 40                  // halves per smem row (32 + 8 pad)
#define HPL (128*HSTR)
#define HST (4*HPL)
#define HSMEM (3*HST*2)          // 3 stages: 122880 B

__device__ float g_S  [(size_t)N1C*N1C];
__device__ float g_Xa [(size_t)N1C*N1C];
__device__ float g_Xb [(size_t)N1C*N1C];
__device__ float g_T  [(size_t)N1C*N1C];
__device__ float g_G  [(size_t)N2C*N1C];
__device__ float g_At [(size_t)N2C*N1C];
__device__ float g_W1t[(size_t)HC*DC];
__device__ float g_W2t[(size_t)N2C*HC];
__device__ float g_c  [N2C];
__device__ float g_tv [N1C];
__device__ float g_v  [N1C];
__device__ float g_y  [N1C];
__device__ float g_h  [(size_t)BC*HC];
__device__ float g_w  [(size_t)BC*N2C];
__device__ float g_za [(size_t)BC*N2C];
__device__ float g_zb [(size_t)BC*N2C];
__device__ float g_P  [(size_t)4*1024*1024];
__device__ __half g_Ah [(size_t)N1C*N2C];
__device__ __half g_Al [(size_t)N1C*N2C];
__device__ __half g_Gh [(size_t)N2C*N1C];
__device__ __half g_Gl [(size_t)N2C*N1C];
__device__ __half g_uh [(size_t)BC*N2C];
__device__ __half g_ul [(size_t)BC*N2C];
__device__ __half g_rth[(size_t)BC*N1C];
__device__ __half g_rtl[(size_t)BC*N1C];
__device__ __half g_Sh [(size_t)N1C*N1C];
__device__ __half g_Sl [(size_t)N1C*N1C];
__device__ __half g_Xh [(size_t)N1C*N1C];
__device__ __half g_Xl [(size_t)N1C*N1C];
__device__ __half g_Th [(size_t)N1C*N1C];
__device__ __half g_Tl [(size_t)N1C*N1C];
__device__ __half g_dh [(size_t)BC*DC];
__device__ __half g_dl [(size_t)BC*DC];
__device__ __half g_W1h[(size_t)HC*DC];
__device__ __half g_W1l[(size_t)HC*DC];
__device__ __half g_W2h[(size_t)N2C*HC];
__device__ __half g_W2l[(size_t)N2C*HC];
__device__ __half g_hph[(size_t)BC*HC];
__device__ __half g_hpl[(size_t)BC*HC];
__device__ float g_lam;
__device__ float g_ss;
__device__ int   g_flag;
__device__ int   g_cnt;

// ---------------- small utility kernels ----------------
__global__ void init_k() { g_ss = 0.f; g_flag = 0; g_cnt = 0; }

__global__ void copy4_k(float4* __restrict__ dst, const float4* __restrict__ src) {
    int i = blockIdx.x * blockDim.x + threadIdx.x;
    dst[i] = src[i];
}

__global__ void fill_k(float* v, float val, int n) {
    int i = blockIdx.x * blockDim.x + threadIdx.x;
    if (i < n) v[i] = val;
}

// in-place symmetrization: X <- (X + X^T)/2 (one thread per i<j pair)
__global__ void symm_k(float* __restrict__ X) {
    int j = blockIdx.x * 32 + (threadIdx.x & 31);
    int i = blockIdx.y * 8 + (threadIdx.x >> 5);
    if (i < j) {
        size_t ij = (size_t)i * N1C + j;
        size_t ji = (size_t)j * N1C + i;
        float m = 0.5f * (X[ij] + X[ji]);
        X[ij] = m;
        X[ji] = m;
    }
}

__global__ void spmv_k(const float* __restrict__ M_, const float* __restrict__ v,
                       float* __restrict__ y) {
    int row = blockIdx.x * 8 + threadIdx.y;
    const float* mr = M_ + (size_t)row * N1C;
    float s = 0.f;
    for (int j = threadIdx.x; j < N1C; j += 32) s += mr[j] * v[j];
    #pragma unroll
    for (int o = 16; o; o >>= 1) s += __shfl_xor_sync(0xffffffffu, s, o);
    if (threadIdx.x == 0) y[row] = s;
}

__global__ void pi_norm_k(const float* __restrict__ y, float* __restrict__ v) {
    __shared__ float red[256];
    float s = 0.f;
    for (int i = threadIdx.x; i < N1C; i += 256) { float t = y[i]; s += t * t; }
    red[threadIdx.x] = s; __syncthreads();
    for (int o = 128; o; o >>= 1) {
        if (threadIdx.x < o) red[threadIdx.x] += red[threadIdx.x + o];
        __syncthreads();
    }
    float nrm = sqrtf(red[0]);
    float inv = 1.f / nrm;
    for (int i = threadIdx.x; i < N1C; i += 256) v[i] = y[i] * inv;
    if (threadIdx.x == 0) g_lam = nrm;
}

__global__ void initX_k(float* X) {
    float a = 1.8f / g_lam;
    int i = blockIdx.x * 256 + threadIdx.x;
    int rr = i / N1C, cc = i % N1C;
    X[i] = (rr == cc) ? a : 0.f;
}

__global__ void atmv_k(const float* __restrict__ A, const float* __restrict__ t,
                       float* __restrict__ c) {
    __shared__ float ts[N1C];
    for (int i = threadIdx.x; i < N1C; i += 256) ts[i] = t[i];
    __syncthreads();
    int j = blockIdx.x * 256 + threadIdx.x;
    float s = 0.f;
    for (int i = 0; i < N1C; i++) s += A[(size_t)i * N2C + j] * ts[i];
    c[j] = s;
}

__global__ void transp_k(float* __restrict__ dst, const float* __restrict__ src,
                         int R, int C) {
    __shared__ float t[32][33];
    int bx = blockIdx.x * 32, by = blockIdx.y * 32;
    #pragma unroll
    for (int i = 0; i < 4; i++) {
        int r = by + threadIdx.y + i * 8;
        t[threadIdx.y + i * 8][threadIdx.x] = src[(size_t)r * C + bx + threadIdx.x];
    }
    __syncthreads();
    #pragma unroll
    for (int i = 0; i < 4; i++) {
        int r = bx + threadIdx.y + i * 8;
        dst[(size_t)r * R + by + threadIdx.x] = t[threadIdx.x][threadIdx.y + i * 8];
    }
}

__device__ __forceinline__ void split2h(float x, __half& h, __half& l) {
    h = __float2half_rn(x);
    l = __float2half_rn(x - __half2float(h));
}

// split scaled fp32 -> (hi, lo) fp16 planes; 8 elements per thread
__global__ void splitH_k(const float* __restrict__ src, __half* __restrict__ ph,
                         __half* __restrict__ pl, float scale) {
    size_t e = ((size_t)blockIdx.x * 256 + threadIdx.x) * 8;
    uint32_t hh[4], ll[4];
    #pragma unroll
    for (int p = 0; p < 4; p++) {
        __half h0, h1, l0, l1;
        split2h(src[e + 2 * p] * scale, h0, l0);
        split2h(src[e + 2 * p + 1] * scale, h1, l1);
        __half2 hp = __halves2half2(h0, h1), lp = __halves2half2(l0, l1);
        hh[p] = *(uint32_t*)&hp; ll[p] = *(uint32_t*)&lp;
    }
    *(uint4*)(ph + e) = make_uint4(hh[0], hh[1], hh[2], hh[3]);
    *(uint4*)(pl + e) = make_uint4(ll[0], ll[1], ll[2], ll[3]);
}

// u = |z| - a*w -> u planes; 4 elements per thread
__global__ void u0_k(const float* __restrict__ z, const float* __restrict__ w) {
    size_t i = (size_t)blockIdx.x * 256 + threadIdx.x;
    float4 zv = ((const float4*)z)[i];
    float4 wv = ((const float4*)w)[i];
    __half h0, h1, h2, h3, l0, l1, l2, l3;
    split2h(fabsf(zv.x) - ALPHA_C * wv.x, h0, l0);
    split2h(fabsf(zv.y) - ALPHA_C * wv.y, h1, l1);
    split2h(fabsf(zv.z) - ALPHA_C * wv.z, h2, l2);
    split2h(fabsf(zv.w) - ALPHA_C * wv.w, h3, l3);
    __half2 ha = __halves2half2(h0, h1), hb = __halves2half2(h2, h3);
    __half2 la = __halves2half2(l0, l1), lb = __halves2half2(l2, l3);
    ((uint2*)g_uh)[i] = make_uint2(*(uint32_t*)&ha, *(uint32_t*)&hb);
    ((uint2*)g_ul)[i] = make_uint2(*(uint32_t*)&la, *(uint32_t*)&lb);
}

// ---------------- reduce kernels (2x float4 ILP, scaled) ----------------
__global__ void reduce_sum_k(const float* __restrict__ P, float* __restrict__ out,
                             size_t stride4, int ns, float scale) {
    size_t i = ((size_t)blockIdx.x * 256 + threadIdx.x) * 2;
    const float4* p = (const float4*)P;
    float4 s0 = p[i], s1 = p[i + 1];
    for (int sp = 1; sp < ns; sp++) {
        float4 t0 = p[(size_t)sp * stride4 + i];
        float4 t1 = p[(size_t)sp * stride4 + i + 1];
        s0.x += t0.x; s0.y += t0.y; s0.z += t0.z; s0.w += t0.w;
        s1.x += t1.x; s1.y += t1.y; s1.z += t1.z; s1.w += t1.w;
    }
    s0.x *= scale; s0.y *= scale; s0.z *= scale; s0.w *= scale;
    s1.x *= scale; s1.y *= scale; s1.z *= scale; s1.w *= scale;
    ((float4*)out)[i] = s0;
    ((float4*)out)[i + 1] = s1;
}

__global__ void reduce_ns_k(const float* __restrict__ P, const float* __restrict__ X,
                            float* __restrict__ out, size_t stride4, int ns, float scale) {
    size_t i = ((size_t)blockIdx.x * 256 + threadIdx.x) * 2;
    const float4* p = (const float4*)P;
    float4 s0 = p[i], s1 = p[i + 1];
    for (int sp = 1; sp < ns; sp++) {
        float4 t0 = p[(size_t)sp * stride4 + i];
        float4 t1 = p[(size_t)sp * stride4 + i + 1];
        s0.x += t0.x; s0.y += t0.y; s0.z += t0.z; s0.w += t0.w;
        s1.x += t1.x; s1.y += t1.y; s1.z += t1.z; s1.w += t1.w;
    }
    float4 x0 = ((const float4*)X)[i], x1 = ((const float4*)X)[i + 1];
    float4 o0, o1;
    o0.x = 2.f * x0.x - s0.x * scale; o0.y = 2.f * x0.y - s0.y * scale;
    o0.z = 2.f * x0.z - s0.z * scale; o0.w = 2.f * x0.w - s0.w * scale;
    o1.x = 2.f * x1.x - s1.x * scale; o1.y = 2.f * x1.y - s1.y * scale;
    o1.z = 2.f * x1.z - s1.z * scale; o1.w = 2.f * x1.w - s1.w * scale;
    ((float4*)out)[i] = o0;
    ((float4*)out)[i + 1] = o1;
}

template<bool RELU>
__global__ void reduce_bias_k(const float* __restrict__ P, const float* __restrict__ bias,
                              float* __restrict__ out, size_t stride4, int ns, int n4,
                              float scale) {
    size_t i = ((size_t)blockIdx.x * 256 + threadIdx.x) * 2;
    const float4* p = (const float4*)P;
    float4 s0 = p[i], s1 = p[i + 1];
    for (int sp = 1; sp < ns; sp++) {
        float4 t0 = p[(size_t)sp * stride4 + i];
        float4 t1 = p[(size_t)sp * stride4 + i + 1];
        s0.x += t0.x; s0.y += t0.y; s0.z += t0.z; s0.w += t0.w;
        s1.x += t1.x; s1.y += t1.y; s1.z += t1.z; s1.w += t1.w;
    }
    float4 b0 = ((const float4*)bias)[i % n4];
    float4 b1 = ((const float4*)bias)[(i + 1) % n4];
    s0.x = s0.x * scale + b0.x; s0.y = s0.y * scale + b0.y;
    s0.z = s0.z * scale + b0.z; s0.w = s0.w * scale + b0.w;
    s1.x = s1.x * scale + b1.x; s1.y = s1.y * scale + b1.y;
    s1.z = s1.z * scale + b1.z; s1.w = s1.w * scale + b1.w;
    if (RELU) {
        s0.x = fmaxf(s0.x, 0.f); s0.y = fmaxf(s0.y, 0.f);
        s0.z = fmaxf(s0.z, 0.f); s0.w = fmaxf(s0.w, 0.f);
        s1.x = fmaxf(s1.x, 0.f); s1.y = fmaxf(s1.y, 0.f);
        s1.z = fmaxf(s1.z, 0.f); s1.w = fmaxf(s1.w, 0.f);
    }
    ((float4*)out)[i] = s0;
    ((float4*)out)[i + 1] = s1;
}

// sum 8 partials of 64*(A u^T) [N1C][BC]; write rt planes [BC][N1C] (x 1/64)
__global__ void reduce_tr_k(const float* __restrict__ P, const int* __restrict__ guard) {
    if (guard && *guard) return;
    __shared__ float t[32][33];
    int bm = blockIdx.x * 32;
    int bb = blockIdx.y * 32;
    #pragma unroll
    for (int i = 0; i < 4; i++) {
        int m = bm + threadIdx.y + i * 8;
        size_t idx = (size_t)m * BC + bb + threadIdx.x;
        float s = 0.f;
        #pragma unroll
        for (int sp = 0; sp < 8; sp++) s += P[(size_t)sp * N1C * BC + idx];
        t[threadIdx.y + i * 8][threadIdx.x] = s;
    }
    __syncthreads();
    #pragma unroll
    for (int i = 0; i < 4; i++) {
        int b = bb + threadIdx.y + i * 8;
        float vv = t[threadIdx.x][threadIdx.y + i * 8] * INV_A_SC;
        __half h, l;
        split2h(vv, h, l);
        size_t o = (size_t)b * N1C + bm + threadIdx.x;
        g_rth[o] = h;
        g_rtl[o] = l;
    }
}

// z-update: zn = relu(z) - a*w + c - (1/32)*sum; + u planes + convergence check
template<bool FIN>
__global__ void zupd_k(const float* __restrict__ P, const float* __restrict__ zin,
                       const float* __restrict__ w, const float* __restrict__ c,
                       float* __restrict__ zout, const int* __restrict__ guard) {
    size_t gid = (size_t)blockIdx.x * 256 + threadIdx.x;
    size_t i = gid * 2;
    if (!FIN && guard && *guard) {
        ((float4*)zout)[i] = ((const float4*)zin)[i];
        ((float4*)zout)[i + 1] = ((const float4*)zin)[i + 1];
        return;
    }
    const float4* p = (const float4*)P;
    float ov[8], wv8[8];
    float ls = 0.f;
    #pragma unroll
    for (int q = 0; q < 2; q++) {
        float4 s = p[i + q];
        float4 t = p[(size_t)(BC * (N2C / 4)) + i + q];
        s.x += t.x; s.y += t.y; s.z += t.z; s.w += t.w;
        float4 z = ((const float4*)zin)[i + q];
        float4 ww = ((const float4*)w)[i + q];
        float4 cc = ((const float4*)c)[(i + q) & (N2C / 4 - 1)];
        float4 o;
        o.x = fmaxf(z.x, 0.f) - ALPHA_C * ww.x + cc.x - s.x * INV_G_SC;
        o.y = fmaxf(z.y, 0.f) - ALPHA_C * ww.y + cc.y - s.y * INV_G_SC;
        o.z = fmaxf(z.z, 0.f) - ALPHA_C * ww.z + cc.z - s.z * INV_G_SC;
        o.w = fmaxf(z.w, 0.f) - ALPHA_C * ww.w + cc.w - s.w * INV_G_SC;
        if (FIN) {
            o.x = fmaxf(o.x, 0.f); o.y = fmaxf(o.y, 0.f);
            o.z = fmaxf(o.z, 0.f); o.w = fmaxf(o.w, 0.f);
            ((float4*)zout)[i + q] = o;
        } else {
            ((float4*)zout)[i + q] = o;
            float dx = o.x - z.x, dy = o.y - z.y, dz = o.z - z.z, dw = o.w - z.w;
            ls += dx * dx + dy * dy + dz * dz + dw * dw;
            ov[q * 4 + 0] = o.x; ov[q * 4 + 1] = o.y;
            ov[q * 4 + 2] = o.z; ov[q * 4 + 3] = o.w;
            wv8[q * 4 + 0] = ww.x; wv8[q * 4 + 1] = ww.y;
            wv8[q * 4 + 2] = ww.z; wv8[q * 4 + 3] = ww.w;
        }
    }
    if (!FIN) {
        uint32_t hh[4], ll[4];
        #pragma unroll
        for (int pq = 0; pq < 4; pq++) {
            __half h0, h1, l0, l1;
            split2h(fabsf(ov[2 * pq]) - ALPHA_C * wv8[2 * pq], h0, l0);
            split2h(fabsf(ov[2 * pq + 1]) - ALPHA_C * wv8[2 * pq + 1], h1, l1);
            __half2 hp = __halves2half2(h0, h1), lp = __halves2half2(l0, l1);
            hh[pq] = *(uint32_t*)&hp; ll[pq] = *(uint32_t*)&lp;
        }
        size_t e = gid * 8;
        *(uint4*)(g_uh + e) = make_uint4(hh[0], hh[1], hh[2], hh[3]);
        *(uint4*)(g_ul + e) = make_uint4(ll[0], ll[1], ll[2], ll[3]);

        __shared__ float red[256];
        red[threadIdx.x] = ls;
        __syncthreads();
        for (int o2 = 128; o2; o2 >>= 1) {
            if (threadIdx.x < o2) red[threadIdx.x] += red[threadIdx.x + o2];
            __syncthreads();
        }
        if (threadIdx.x == 0) {
            atomicAdd(&g_ss, red[0]);
            __threadfence();
            int t = atomicAdd(&g_cnt, 1);
            if (t == (int)gridDim.x - 1) {
                if (g_ss <= EPS_C * EPS_C) g_flag = 1;
                g_ss = 0.f;
                g_cnt = 0;
            }
        }
    }
}

// ---------------- fp16 GEMM (NP=3: hh+hl+lh; NP=1: hh only) ----------------
__device__ __forceinline__ uint32_t smem_u32(const void* p) {
    uint32_t a;
    asm("{ .reg .u64 t; cvta.to.shared.u64 t, %1; cvt.u32.u64 %0, t; }" : "=r"(a) : "l"(p));
    return a;
}
__device__ __forceinline__ void cp16(uint32_t dst, const void* src) {
    asm volatile("cp.async.cg.shared.global [%0], [%1], 16;" :: "r"(dst), "l"(src));
}
__device__ __forceinline__ void ldsm4(uint32_t* r, uint32_t a) {
    asm volatile("ldmatrix.sync.aligned.m8n8.x4.shared.b16 {%0,%1,%2,%3}, [%4];"
        : "=r"(r[0]), "=r"(r[1]), "=r"(r[2]), "=r"(r[3]) : "r"(a));
}
__device__ __forceinline__ void mma16(float* c, const uint32_t* a, const uint32_t* b) {
    asm volatile("mma.sync.aligned.m16n8k16.row.col.f32.f16.f16.f32 "
        "{%0,%1,%2,%3}, {%4,%5,%6,%7}, {%8,%9}, {%0,%1,%2,%3};"
        : "+f"(c[0]), "+f"(c[1]), "+f"(c[2]), "+f"(c[3])
        : "r"(a[0]), "r"(a[1]), "r"(a[2]), "r"(a[3]), "r"(b[0]), "r"(b[1]));
}

template<int NP>
__global__ void __launch_bounds__(256)
hgemm_k(const __half* __restrict__ Ahp, const __half* __restrict__ Alp, int lda,
        const __half* __restrict__ Bhp, const __half* __restrict__ Blp, int ldb,
        float* __restrict__ Cg, int N, int kchunk, const int* __restrict__ guard)
{
    if (guard && *guard) return;
    extern __shared__ __half hsm[];
    const int tid = threadIdx.x, lane = tid & 31, wid = tid >> 5;
    const int wm = wid >> 2, wn = wid & 3;
    const int m0 = blockIdx.y * 128, n0 = blockIdx.x * 128;
    const int k0 = blockIdx.z * kchunk;
    const int ST = kchunk / HBK;
    const __half* psrc[4] = { Ahp, Alp, Bhp, Blp };
    uint32_t sbase = smem_u32(hsm);

    auto load = [&](int s) {
        int buf = s % 3;
        int kb = k0 + s * HBK;
        #pragma unroll
        for (int t = 0; t < (NP == 3 ? 8 : 4); t++) {
            int id = t * 256 + tid;
            int pl = (NP == 3) ? (id >> 9) : ((id >> 9) * 2);
            int idx = id & 511;
            int row = idx >> 2, kc = idx & 3;
            int isB = pl >> 1;
            const __half* src = psrc[pl] +
                (size_t)((isB ? n0 : m0) + row) * (isB ? ldb : lda) + kb + kc * 8;
            uint32_t dst = sbase + (uint32_t)(buf * HST + pl * HPL + row * HSTR + kc * 8) * 2;
            cp16(dst, src);
        }
    };

    float acc[4][4][4];
    #pragma unroll
    for (int f = 0; f < 4; f++)
        #pragma unroll
        for (int g = 0; g < 4; g++)
            #pragma unroll
            for (int e = 0; e < 4; e++) acc[f][g][e] = 0.f;

    load(0);
    asm volatile("cp.async.commit_group;");
    load(1);
    asm volatile("cp.async.commit_group;");
    load(2);
    asm volatile("cp.async.commit_group;");

    const int offA = (lane & 15) * HSTR + (lane >> 4) * 8;
    const int offB = ((lane & 7) + ((lane >> 4) << 3)) * HSTR + ((lane >> 3) & 1) * 8;

    for (int s = 0; s < ST; s++) {
        asm volatile("cp.async.wait_group 2;");
        __syncthreads();
        uint32_t stg = sbase + (uint32_t)((s % 3) * HST) * 2;
        #pragma unroll
        for (int ks = 0; ks < 2; ks++) {
            uint32_t aH[4][4], aL[4][4], bH[4][2], bL[4][2];
            #pragma unroll
            for (int f = 0; f < 4; f++) {
                uint32_t base = stg + (uint32_t)((wm * 64 + f * 16) * HSTR + ks * 16 + offA) * 2;
                ldsm4(aH[f], base);
                if (NP == 3) ldsm4(aL[f], base + HPL * 2);
            }
            #pragma unroll
            for (int gp = 0; gp < 2; gp++) {
                uint32_t r[4];
                uint32_t base = stg + (uint32_t)(2 * HPL + (wn * 32 + gp * 16) * HSTR + ks * 16 + offB) * 2;
                ldsm4(r, base);
                bH[gp * 2][0] = r[0]; bH[gp * 2][1] = r[1];
                bH[gp * 2 + 1][0] = r[2]; bH[gp * 2 + 1][1] = r[3];
                if (NP == 3) {
                    ldsm4(r, base + HPL * 2);
                    bL[gp * 2][0] = r[0]; bL[gp * 2][1] = r[1];
                    bL[gp * 2 + 1][0] = r[2]; bL[gp * 2 + 1][1] = r[3];
                }
            }
            // product-pass ordering: 16 independent MMAs between reuses of
            // any accumulator tile (hides HMMA accumulator RAW latency)
            #pragma unroll
            for (int f = 0; f < 4; f++)
                #pragma unroll
                for (int g = 0; g < 4; g++)
                    mma16(acc[f][g], aH[f], bH[g]);
            if (NP == 3) {
                #pragma unroll
                for (int f = 0; f < 4; f++)
                    #pragma unroll
                    for (int g = 0; g < 4; g++)
                        mma16(acc[f][g], aH[f], bL[g]);
                #pragma unroll
                for (int f = 0; f < 4; f++)
                    #pragma unroll
                    for (int g = 0; g < 4; g++)
                        mma16(acc[f][g], aL[f], bH[g]);
            }
        }
        __syncthreads();
        if (s + 3 < ST) load(s + 3);
        asm volatile("cp.async.commit_group;");
    }

    size_t off = (size_t)blockIdx.z * ((size_t)gridDim.y * 128) * N;
    const int tr = lane >> 2, tc = (lane & 3) * 2;
    #pragma unroll
    for (int f = 0; f < 4; f++) {
        int m = m0 + wm * 64 + f * 16 + tr;
        #pragma unroll
        for (int g = 0; g < 4; g++) {
            int n = n0 + wn * 32 + g * 8 + tc;
            *(float2*)&Cg[off + (size_t)m * N + n] = make_float2(acc[f][g][0], acc[f][g][1]);
            *(float2*)&Cg[off + (size_t)(m + 8) * N + n] = make_float2(acc[f][g][2], acc[f][g][3]);
        }
    }
}

// ---------------- host ----------------
extern "C" void kernel_launch(void* const* d_in, const int* in_sizes, int n_in,
                              void* d_out, int out_size) {
    (void)in_sizes; (void)n_in; (void)out_size;
    const float* dd  = (const float*)d_in[0];
    const float* dA  = (const float*)d_in[1];
    const float* dB  = (const float*)d_in[2];
    const float* dW1 = (const float*)d_in[3];
    const float* db1 = (const float*)d_in[4];
    const float* dW2 = (const float*)d_in[5];
    const float* db2 = (const float*)d_in[6];
    const float* dz0 = (const float*)d_in[7];
    float* out = (float*)d_out;

    void* p;
    cudaGetSymbolAddress(&p, g_S);   float* S    = (float*)p;
    cudaGetSymbolAddress(&p, g_Xa);  float* Xa   = (float*)p;
    cudaGetSymbolAddress(&p, g_Xb);  float* Xb   = (float*)p;
    cudaGetSymbolAddress(&p, g_T);   float* Tm   = (float*)p;
    cudaGetSymbolAddress(&p, g_G);   float* G    = (float*)p;
    cudaGetSymbolAddress(&p, g_At);  float* At   = (float*)p;
    cudaGetSymbolAddress(&p, g_W1t); float* W1t  = (float*)p;
    cudaGetSymbolAddress(&p, g_W2t); float* W2t  = (float*)p;
    cudaGetSymbolAddress(&p, g_c);   float* c    = (float*)p;
    cudaGetSymbolAddress(&p, g_tv);  float* tv   = (float*)p;
    cudaGetSymbolAddress(&p, g_v);   float* v    = (float*)p;
    cudaGetSymbolAddress(&p, g_y);   float* y    = (float*)p;
    cudaGetSymbolAddress(&p, g_h);   float* h    = (float*)p;
    cudaGetSymbolAddress(&p, g_w);   float* wbuf = (float*)p;
    cudaGetSymbolAddress(&p, g_za);  float* za   = (float*)p;
    cudaGetSymbolAddress(&p, g_zb);  float* zbb  = (float*)p;
    cudaGetSymbolAddress(&p, g_P);   float* P    = (float*)p;
    cudaGetSymbolAddress(&p, g_flag); int* flag  = (int*)p;
    cudaGetSymbolAddress(&p, g_Ah);  __half* Ahp = (__half*)p;
    cudaGetSymbolAddress(&p, g_Al);  __half* Alp = (__half*)p;
    cudaGetSymbolAddress(&p, g_Gh);  __half* Ghp = (__half*)p;
    cudaGetSymbolAddress(&p, g_Gl);  __half* Glp = (__half*)p;
    cudaGetSymbolAddress(&p, g_uh);  __half* uhp = (__half*)p;
    cudaGetSymbolAddress(&p, g_ul);  __half* ulp = (__half*)p;
    cudaGetSymbolAddress(&p, g_rth); __half* rthp = (__half*)p;
    cudaGetSymbolAddress(&p, g_rtl); __half* rtlp = (__half*)p;
    cudaGetSymbolAddress(&p, g_Sh);  __half* Shp = (__half*)p;
    cudaGetSymbolAddress(&p, g_Sl);  __half* Slp = (__half*)p;
    cudaGetSymbolAddress(&p, g_Xh);  __half* Xhp = (__half*)p;
    cudaGetSymbolAddress(&p, g_Xl);  __half* Xlp = (__half*)p;
    cudaGetSymbolAddress(&p, g_Th);  __half* Thp = (__half*)p;
    cudaGetSymbolAddress(&p, g_Tl);  __half* Tlp = (__half*)p;
    cudaGetSymbolAddress(&p, g_dh);  __half* dhp = (__half*)p;
    cudaGetSymbolAddress(&p, g_dl);  __half* dlp = (__half*)p;
    cudaGetSymbolAddress(&p, g_W1h); __half* W1h = (__half*)p;
    cudaGetSymbolAddress(&p, g_W1l); __half* W1l = (__half*)p;
    cudaGetSymbolAddress(&p, g_W2h); __half* W2h = (__half*)p;
    cudaGetSymbolAddress(&p, g_W2l); __half* W2l = (__half*)p;
    cudaGetSymbolAddress(&p, g_hph); __half* hph = (__half*)p;
    cudaGetSymbolAddress(&p, g_hpl); __half* hpl = (__half*)p;

    cudaFuncSetAttribute(hgemm_k<3>,
                         cudaFuncAttributeMaxDynamicSharedMemorySize, HSMEM);
    cudaFuncSetAttribute(hgemm_k<1>,
                         cudaFuncAttributeMaxDynamicSharedMemorySize, HSMEM);

    init_k<<<1, 1>>>();
    copy4_k<<<(BC * N2C / 4) / 256, 256>>>((float4*)za, (const float4*)dz0);

    // A planes (x64)
    splitH_k<<<(int)(((size_t)N1C * N2C / 8) / 256), 256>>>(dA, Ahp, Alp, A_SC);

    // S = A A^T : hgemm, accum = 4096*S
    {
        dim3 g(N1C / 128, N1C / 128, 2);
        hgemm_k<3><<<g, 256, HSMEM>>>(Ahp, Alp, N2C, Ahp, Alp, N2C, P, N1C, N2C / 2, nullptr);
        reduce_sum_k<<<(N1C * N1C / 8) / 256, 256>>>(P, S, (size_t)N1C * N1C / 4, 2, 1.f / 4096.f);
    }

    // power iteration (fp32 S)
    fill_k<<<N1C / 256, 256>>>(v, 0.03125f, N1C);
    for (int i = 0; i < PI_ITERS; i++) {
        spmv_k<<<N1C / 8, dim3(32, 8)>>>(S, v, y);
        pi_norm_k<<<1, 256>>>(y, v);
    }
    initX_k<<<(N1C * N1C) / 256, 256>>>(Xa);

    // S planes (x16)
    splitH_k<<<(int)(((size_t)N1C * N1C / 8) / 256), 256>>>(S, Shp, Slp, 16.f);

    // Newton-Schulz: 4 cheap (NP=1) + 2 precise (NP=3), symmetrized each iter
    float* Xc = Xa; float* Xn = Xb;
    {
        dim3 g(N1C / 128, N1C / 128, 2);
        dim3 gsym(N1C / 32, N1C / 8);
        size_t s4 = (size_t)N1C * N1C / 4;
        int nsgrid = (N1C * N1C / 8) / 256;
        for (int i = 0; i < NS_ITERS; i++) {
            symm_k<<<gsym, 256>>>(Xc);
            splitH_k<<<(N1C * N1C / 8) / 256, 256>>>(Xc, Xhp, Xlp, 32.f);
            if (i < NS_CHEAP)
                hgemm_k<1><<<g, 256, HSMEM>>>(Xhp, Xlp, N1C, Shp, Slp, N1C, P, N1C, N1C / 2, nullptr);
            else
                hgemm_k<3><<<g, 256, HSMEM>>>(Xhp, Xlp, N1C, Shp, Slp, N1C, P, N1C, N1C / 2, nullptr);
            reduce_sum_k<<<nsgrid, 256>>>(P, Tm, s4, 2, 1.f / 512.f);
            splitH_k<<<(N1C * N1C / 8) / 256, 256>>>(Tm, Thp, Tlp, 32.f);
            if (i < NS_CHEAP)
                hgemm_k<1><<<g, 256, HSMEM>>>(Thp, Tlp, N1C, Xhp, Xlp, N1C, P, N1C, N1C / 2, nullptr);
            else
                hgemm_k<3><<<g, 256, HSMEM>>>(Thp, Tlp, N1C, Xhp, Xlp, N1C, P, N1C, N1C / 2, nullptr);
            reduce_ns_k<<<nsgrid, 256>>>(P, Xc, Xn, s4, 2, 1.f / 1024.f);
            float* t2 = Xc; Xc = Xn; Xn = t2;
        }
        // final symmetrization before using X for c and G
        symm_k<<<gsym, 256>>>(Xc);
    }

    // c = A^T (X b)
    spmv_k<<<N1C / 8, dim3(32, 8)>>>(Xc, dB, tv);
    atmv_k<<<N2C / 256, 256>>>(dA, tv, c);

    // G = A^T X: At planes (x64, temp in Gh/Gl), X planes (x32) -> accum 2048*G
    transp_k<<<dim3(N2C / 32, N1C / 32), dim3(32, 8)>>>(At, dA, N1C, N2C);
    splitH_k<<<(int)(((size_t)N2C * N1C / 8) / 256), 256>>>(At, Ghp, Glp, A_SC);
    splitH_k<<<(N1C * N1C / 8) / 256, 256>>>(Xc, Xhp, Xlp, 32.f);
    {
        dim3 g(N1C / 128, N2C / 128, 1);
        hgemm_k<3><<<g, 256, HSMEM>>>(Ghp, Glp, N1C, Xhp, Xlp, N1C, P, N1C, N1C, nullptr);
        reduce_sum_k<<<(int)(((size_t)N2C * N1C / 8) / 256), 256>>>(
            P, G, 0, 1, 1.f / 2048.f);
    }
    // G planes (x32), overwriting At planes
    splitH_k<<<(int)(((size_t)N2C * N1C / 8) / 256), 256>>>(G, Ghp, Glp, G_SC);

    // MLP on hgemm
    transp_k<<<dim3(HC / 32, DC / 32), dim3(32, 8)>>>(W1t, dW1, DC, HC);
    splitH_k<<<(int)(((size_t)HC * DC / 8) / 256), 256>>>(W1t, W1h, W1l, 32.f);
    transp_k<<<dim3(N2C / 32, HC / 32), dim3(32, 8)>>>(W2t, dW2, HC, N2C);
    splitH_k<<<(int)(((size_t)N2C * HC / 8) / 256), 256>>>(W2t, W2h, W2l, 32.f);
    splitH_k<<<(BC * DC / 8) / 256, 256>>>(dd, dhp, dlp, 1.f);
    {
        dim3 g1(HC / 128, BC / 128, 4);
        hgemm_k<3><<<g1, 256, HSMEM>>>(dhp, dlp, DC, W1h, W1l, DC, P, HC, DC / 4, nullptr);
        reduce_bias_k<true><<<(BC * HC / 8) / 256, 256>>>(
            P, db1, h, (size_t)BC * HC / 4, 4, HC / 4, 1.f / 32.f);
        splitH_k<<<(BC * HC / 8) / 256, 256>>>(h, hph, hpl, 1.f);
        dim3 g2(N2C / 128, BC / 128, 2);
        hgemm_k<3><<<g2, 256, HSMEM>>>(hph, hpl, HC, W2h, W2l, HC, P, N2C, HC / 2, nullptr);
        reduce_bias_k<false><<<(BC * N2C / 8) / 256, 256>>>(
            P, db2, wbuf, (size_t)BC * N2C / 4, 2, N2C / 4, 1.f / 32.f);
    }

    // initial u planes
    u0_k<<<(BC * N2C / 4) / 256, 256>>>(za, wbuf);

    // DYS loop
    dim3 gr(BC / 128, N1C / 128, 8);     // 64*(A u^T): split8
    dim3 gz(N2C / 128, BC / 128, 2);     // 32*(G r)^T: split2
    float* zb2[2] = { za, zbb };
    for (int it = 1; it <= 50; ++it) {
        const float* zin = zb2[(it - 1) & 1];
        float* zout = zb2[it & 1];
        hgemm_k<3><<<gr, 256, HSMEM>>>(Ahp, Alp, N2C, uhp, ulp, N2C, P, BC, N2C / 8, flag);
        reduce_tr_k<<<dim3(N1C / 32, BC / 32), dim3(32, 8)>>>(P, flag);
        hgemm_k<3><<<gz, 256, HSMEM>>>(rthp, rtlp, N1C, Ghp, Glp, N1C, P, N2C, N1C / 2, flag);
        zupd_k<false><<<(BC * N2C / 8) / 256, 256>>>(P, zin, wbuf, c, zout, flag);
    }

    // final unguarded step, relu into d_out
    hgemm_k<3><<<gr, 256, HSMEM>>>(Ahp, Alp, N2C, uhp, ulp, N2C, P, BC, N2C / 8, nullptr);
    reduce_tr_k<<<dim3(N1C / 32, BC / 32), dim3(32, 8)>>>(P, nullptr);
    hgemm_k<3><<<gz, 256, HSMEM>>>(rthp, rtlp, N1C, Ghp, Glp, N1C, P, N2C, N1C / 2, nullptr);
    zupd_k<true><<<(BC * N2C / 8) / 256, 256>>>(P, za, wbuf, c, out, nullptr);
}

// round 13
// speedup vs baseline: 4.1782x; 1.0062x over previous
#include <cuda_runtime.h>
#include <cuda_fp16.h>
#include <math.h>
#include <stdint.h>

// ----------------------------------------------------------------------------
// DYS_opt_net.  ALL GEMMs on legacy fp16 mma.sync m16n8k16 with fp16x3 split
// (hh+hl+lh, fp32 accum), static per-matrix scaling, explicit symmetrization
// in Newton-Schulz (4 cheap + 2 precise iters).
// R11: 2-stage pipeline (80KB smem -> 2 CTAs/SM) + split-K doubled so every
// GEMM launches ~256 CTAs (2 resident CTAs hide each other's sync bubbles).
// z' = relu(z) - a*w + c - (G (A u^T))^T,  u = |z| - a*w
// ----------------------------------------------------------------------------

#define N1C 1024
#define N2C 4096
#define BC  256
#define DC  512
#define HC  2048

#define ALPHA_C 0.05f
#define EPS_C   0.01f
#define NS_ITERS 6
#define NS_CHEAP 4
#define PI_ITERS 12

#define A_SC 64.f
#define G_SC 32.f
#define INV_A_SC 0.015625f
#define INV_G_SC 0.03125f

// splits (grids ~256 CTAs everywhere)
#define SPL_GR 16
#define SPL_GZ 4
#define SPL_S  4
#define SPL_NS 4
#define SPL_M1 8
#define SPL_M2 4

// fp16 GEMM tile config
#define HBK 32
#define HSTR 40                  // halves per smem row (32 + 8 pad)
#define HPL (128*HSTR)
#define HST (4*HPL)
#define HSMEM (2*HST*2)          // 2 stages: 81920 B -> 2 CTAs/SM

__device__ float g_S  [(size_t)N1C*N1C];
__device__ float g_Xa [(size_t)N1C*N1C];
__device__ float g_Xb [(size_t)N1C*N1C];
__device__ float g_T  [(size_t)N1C*N1C];
__device__ float g_G  [(size_t)N2C*N1C];
__device__ float g_At [(size_t)N2C*N1C];
__device__ float g_W1t[(size_t)HC*DC];
__device__ float g_W2t[(size_t)N2C*HC];
__device__ float g_c  [N2C];
__device__ float g_tv [N1C];
__device__ float g_v  [N1C];
__device__ float g_y  [N1C];
__device__ float g_h  [(size_t)BC*HC];
__device__ float g_w  [(size_t)BC*N2C];
__device__ float g_za [(size_t)BC*N2C];
__device__ float g_zb [(size_t)BC*N2C];
__device__ float g_P  [(size_t)4*1024*1024];
__device__ __half g_Ah [(size_t)N1C*N2C];
__device__ __half g_Al [(size_t)N1C*N2C];
__device__ __half g_Gh [(size_t)N2C*N1C];
__device__ __half g_Gl [(size_t)N2C*N1C];
__device__ __half g_uh [(size_t)BC*N2C];
__device__ __half g_ul [(size_t)BC*N2C];
__device__ __half g_rth[(size_t)BC*N1C];
__device__ __half g_rtl[(size_t)BC*N1C];
__device__ __half g_Sh [(size_t)N1C*N1C];
__device__ __half g_Sl [(size_t)N1C*N1C];
__device__ __half g_Xh [(size_t)N1C*N1C];
__device__ __half g_Xl [(size_t)N1C*N1C];
__device__ __half g_Th [(size_t)N1C*N1C];
__device__ __half g_Tl [(size_t)N1C*N1C];
__device__ __half g_dh [(size_t)BC*DC];
__device__ __half g_dl [(size_t)BC*DC];
__device__ __half g_W1h[(size_t)HC*DC];
__device__ __half g_W1l[(size_t)HC*DC];
__device__ __half g_W2h[(size_t)N2C*HC];
__device__ __half g_W2l[(size_t)N2C*HC];
__device__ __half g_hph[(size_t)BC*HC];
__device__ __half g_hpl[(size_t)BC*HC];
__device__ float g_lam;
__device__ float g_ss;
__device__ int   g_flag;
__device__ int   g_cnt;

// ---------------- small utility kernels ----------------
__global__ void init_k() { g_ss = 0.f; g_flag = 0; g_cnt = 0; }

__global__ void copy4_k(float4* __restrict__ dst, const float4* __restrict__ src) {
    int i = blockIdx.x * blockDim.x + threadIdx.x;
    dst[i] = src[i];
}

__global__ void fill_k(float* v, float val, int n) {
    int i = blockIdx.x * blockDim.x + threadIdx.x;
    if (i < n) v[i] = val;
}

// in-place symmetrization: X <- (X + X^T)/2 (one thread per i<j pair)
__global__ void symm_k(float* __restrict__ X) {
    int j = blockIdx.x * 32 + (threadIdx.x & 31);
    int i = blockIdx.y * 8 + (threadIdx.x >> 5);
    if (i < j) {
        size_t ij = (size_t)i * N1C + j;
        size_t ji = (size_t)j * N1C + i;
        float m = 0.5f * (X[ij] + X[ji]);
        X[ij] = m;
        X[ji] = m;
    }
}

__global__ void spmv_k(const float* __restrict__ M_, const float* __restrict__ v,
                       float* __restrict__ y) {
    int row = blockIdx.x * 8 + threadIdx.y;
    const float* mr = M_ + (size_t)row * N1C;
    float s = 0.f;
    for (int j = threadIdx.x; j < N1C; j += 32) s += mr[j] * v[j];
    #pragma unroll
    for (int o = 16; o; o >>= 1) s += __shfl_xor_sync(0xffffffffu, s, o);
    if (threadIdx.x == 0) y[row] = s;
}

__global__ void pi_norm_k(const float* __restrict__ y, float* __restrict__ v) {
    __shared__ float red[256];
    float s = 0.f;
    for (int i = threadIdx.x; i < N1C; i += 256) { float t = y[i]; s += t * t; }
    red[threadIdx.x] = s; __syncthreads();
    for (int o = 128; o; o >>= 1) {
        if (threadIdx.x < o) red[threadIdx.x] += red[threadIdx.x + o];
        __syncthreads();
    }
    float nrm = sqrtf(red[0]);
    float inv = 1.f / nrm;
    for (int i = threadIdx.x; i < N1C; i += 256) v[i] = y[i] * inv;
    if (threadIdx.x == 0) g_lam = nrm;
}

__global__ void initX_k(float* X) {
    float a = 1.8f / g_lam;
    int i = blockIdx.x * 256 + threadIdx.x;
    int rr = i / N1C, cc = i % N1C;
    X[i] = (rr == cc) ? a : 0.f;
}

__global__ void atmv_k(const float* __restrict__ A, const float* __restrict__ t,
                       float* __restrict__ c) {
    __shared__ float ts[N1C];
    for (int i = threadIdx.x; i < N1C; i += 256) ts[i] = t[i];
    __syncthreads();
    int j = blockIdx.x * 256 + threadIdx.x;
    float s = 0.f;
    for (int i = 0; i < N1C; i++) s += A[(size_t)i * N2C + j] * ts[i];
    c[j] = s;
}

__global__ void transp_k(float* __restrict__ dst, const float* __restrict__ src,
                         int R, int C) {
    __shared__ float t[32][33];
    int bx = blockIdx.x * 32, by = blockIdx.y * 32;
    #pragma unroll
    for (int i = 0; i < 4; i++) {
        int r = by + threadIdx.y + i * 8;
        t[threadIdx.y + i * 8][threadIdx.x] = src[(size_t)r * C + bx + threadIdx.x];
    }
    __syncthreads();
    #pragma unroll
    for (int i = 0; i < 4; i++) {
        int r = bx + threadIdx.y + i * 8;
        dst[(size_t)r * R + by + threadIdx.x] = t[threadIdx.x][threadIdx.y + i * 8];
    }
}

__device__ __forceinline__ void split2h(float x, __half& h, __half& l) {
    h = __float2half_rn(x);
    l = __float2half_rn(x - __half2float(h));
}

// split scaled fp32 -> (hi, lo) fp16 planes; 8 elements per thread
__global__ void splitH_k(const float* __restrict__ src, __half* __restrict__ ph,
                         __half* __restrict__ pl, float scale) {
    size_t e = ((size_t)blockIdx.x * 256 + threadIdx.x) * 8;
    uint32_t hh[4], ll[4];
    #pragma unroll
    for (int p = 0; p < 4; p++) {
        __half h0, h1, l0, l1;
        split2h(src[e + 2 * p] * scale, h0, l0);
        split2h(src[e + 2 * p + 1] * scale, h1, l1);
        __half2 hp = __halves2half2(h0, h1), lp = __halves2half2(l0, l1);
        hh[p] = *(uint32_t*)&hp; ll[p] = *(uint32_t*)&lp;
    }
    *(uint4*)(ph + e) = make_uint4(hh[0], hh[1], hh[2], hh[3]);
    *(uint4*)(pl + e) = make_uint4(ll[0], ll[1], ll[2], ll[3]);
}

// u = |z| - a*w -> u planes; 4 elements per thread
__global__ void u0_k(const float* __restrict__ z, const float* __restrict__ w) {
    size_t i = (size_t)blockIdx.x * 256 + threadIdx.x;
    float4 zv = ((const float4*)z)[i];
    float4 wv = ((const float4*)w)[i];
    __half h0, h1, h2, h3, l0, l1, l2, l3;
    split2h(fabsf(zv.x) - ALPHA_C * wv.x, h0, l0);
    split2h(fabsf(zv.y) - ALPHA_C * wv.y, h1, l1);
    split2h(fabsf(zv.z) - ALPHA_C * wv.z, h2, l2);
    split2h(fabsf(zv.w) - ALPHA_C * wv.w, h3, l3);
    __half2 ha = __halves2half2(h0, h1), hb = __halves2half2(h2, h3);
    __half2 la = __halves2half2(l0, l1), lb = __halves2half2(l2, l3);
    ((uint2*)g_uh)[i] = make_uint2(*(uint32_t*)&ha, *(uint32_t*)&hb);
    ((uint2*)g_ul)[i] = make_uint2(*(uint32_t*)&la, *(uint32_t*)&lb);
}

// ---------------- reduce kernels (2x float4 ILP, scaled) ----------------
__global__ void reduce_sum_k(const float* __restrict__ P, float* __restrict__ out,
                             size_t stride4, int ns, float scale) {
    size_t i = ((size_t)blockIdx.x * 256 + threadIdx.x) * 2;
    const float4* p = (const float4*)P;
    float4 s0 = p[i], s1 = p[i + 1];
    for (int sp = 1; sp < ns; sp++) {
        float4 t0 = p[(size_t)sp * stride4 + i];
        float4 t1 = p[(size_t)sp * stride4 + i + 1];
        s0.x += t0.x; s0.y += t0.y; s0.z += t0.z; s0.w += t0.w;
        s1.x += t1.x; s1.y += t1.y; s1.z += t1.z; s1.w += t1.w;
    }
    s0.x *= scale; s0.y *= scale; s0.z *= scale; s0.w *= scale;
    s1.x *= scale; s1.y *= scale; s1.z *= scale; s1.w *= scale;
    ((float4*)out)[i] = s0;
    ((float4*)out)[i + 1] = s1;
}

__global__ void reduce_ns_k(const float* __restrict__ P, const float* __restrict__ X,
                            float* __restrict__ out, size_t stride4, int ns, float scale) {
    size_t i = ((size_t)blockIdx.x * 256 + threadIdx.x) * 2;
    const float4* p = (const float4*)P;
    float4 s0 = p[i], s1 = p[i + 1];
    for (int sp = 1; sp < ns; sp++) {
        float4 t0 = p[(size_t)sp * stride4 + i];
        float4 t1 = p[(size_t)sp * stride4 + i + 1];
        s0.x += t0.x; s0.y += t0.y; s0.z += t0.z; s0.w += t0.w;
        s1.x += t1.x; s1.y += t1.y; s1.z += t1.z; s1.w += t1.w;
    }
    float4 x0 = ((const float4*)X)[i], x1 = ((const float4*)X)[i + 1];
    float4 o0, o1;
    o0.x = 2.f * x0.x - s0.x * scale; o0.y = 2.f * x0.y - s0.y * scale;
    o0.z = 2.f * x0.z - s0.z * scale; o0.w = 2.f * x0.w - s0.w * scale;
    o1.x = 2.f * x1.x - s1.x * scale; o1.y = 2.f * x1.y - s1.y * scale;
    o1.z = 2.f * x1.z - s1.z * scale; o1.w = 2.f * x1.w - s1.w * scale;
    ((float4*)out)[i] = o0;
    ((float4*)out)[i + 1] = o1;
}

template<bool RELU>
__global__ void reduce_bias_k(const float* __restrict__ P, const float* __restrict__ bias,
                              float* __restrict__ out, size_t stride4, int ns, int n4,
                              float scale) {
    size_t i = ((size_t)blockIdx.x * 256 + threadIdx.x) * 2;
    const float4* p = (const float4*)P;
    float4 s0 = p[i], s1 = p[i + 1];
    for (int sp = 1; sp < ns; sp++) {
        float4 t0 = p[(size_t)sp * stride4 + i];
        float4 t1 = p[(size_t)sp * stride4 + i + 1];
        s0.x += t0.x; s0.y += t0.y; s0.z += t0.z; s0.w += t0.w;
        s1.x += t1.x; s1.y += t1.y; s1.z += t1.z; s1.w += t1.w;
    }
    float4 b0 = ((const float4*)bias)[i % n4];
    float4 b1 = ((const float4*)bias)[(i + 1) % n4];
    s0.x = s0.x * scale + b0.x; s0.y = s0.y * scale + b0.y;
    s0.z = s0.z * scale + b0.z; s0.w = s0.w * scale + b0.w;
    s1.x = s1.x * scale + b1.x; s1.y = s1.y * scale + b1.y;
    s1.z = s1.z * scale + b1.z; s1.w = s1.w * scale + b1.w;
    if (RELU) {
        s0.x = fmaxf(s0.x, 0.f); s0.y = fmaxf(s0.y, 0.f);
        s0.z = fmaxf(s0.z, 0.f); s0.w = fmaxf(s0.w, 0.f);
        s1.x = fmaxf(s1.x, 0.f); s1.y = fmaxf(s1.y, 0.f);
        s1.z = fmaxf(s1.z, 0.f); s1.w = fmaxf(s1.w, 0.f);
    }
    ((float4*)out)[i] = s0;
    ((float4*)out)[i + 1] = s1;
}

// sum SPL_GR partials of 64*(A u^T) [N1C][BC]; write rt planes [BC][N1C] (x 1/64)
__global__ void reduce_tr_k(const float* __restrict__ P, const int* __restrict__ guard) {
    if (guard && *guard) return;
    __shared__ float t[32][33];
    int bm = blockIdx.x * 32;
    int bb = blockIdx.y * 32;
    #pragma unroll
    for (int i = 0; i < 4; i++) {
        int m = bm + threadIdx.y + i * 8;
        size_t idx = (size_t)m * BC + bb + threadIdx.x;
        float s = 0.f;
        #pragma unroll
        for (int sp = 0; sp < SPL_GR; sp++) s += P[(size_t)sp * N1C * BC + idx];
        t[threadIdx.y + i * 8][threadIdx.x] = s;
    }
    __syncthreads();
    #pragma unroll
    for (int i = 0; i < 4; i++) {
        int b = bb + threadIdx.y + i * 8;
        float vv = t[threadIdx.x][threadIdx.y + i * 8] * INV_A_SC;
        __half h, l;
        split2h(vv, h, l);
        size_t o = (size_t)b * N1C + bm + threadIdx.x;
        g_rth[o] = h;
        g_rtl[o] = l;
    }
}

// z-update: zn = relu(z) - a*w + c - (1/32)*sum(SPL_GZ partials); + u planes + check
template<bool FIN>
__global__ void zupd_k(const float* __restrict__ P, const float* __restrict__ zin,
                       const float* __restrict__ w, const float* __restrict__ c,
                       float* __restrict__ zout, const int* __restrict__ guard) {
    size_t gid = (size_t)blockIdx.x * 256 + threadIdx.x;
    size_t i = gid * 2;
    if (!FIN && guard && *guard) {
        ((float4*)zout)[i] = ((const float4*)zin)[i];
        ((float4*)zout)[i + 1] = ((const float4*)zin)[i + 1];
        return;
    }
    const float4* p = (const float4*)P;
    float ov[8], wv8[8];
    float ls = 0.f;
    #pragma unroll
    for (int q = 0; q < 2; q++) {
        float4 s = p[i + q];
        #pragma unroll
        for (int sp = 1; sp < SPL_GZ; sp++) {
            float4 t = p[(size_t)sp * (BC * (N2C / 4)) + i + q];
            s.x += t.x; s.y += t.y; s.z += t.z; s.w += t.w;
        }
        float4 z = ((const float4*)zin)[i + q];
        float4 ww = ((const float4*)w)[i + q];
        float4 cc = ((const float4*)c)[(i + q) & (N2C / 4 - 1)];
        float4 o;
        o.x = fmaxf(z.x, 0.f) - ALPHA_C * ww.x + cc.x - s.x * INV_G_SC;
        o.y = fmaxf(z.y, 0.f) - ALPHA_C * ww.y + cc.y - s.y * INV_G_SC;
        o.z = fmaxf(z.z, 0.f) - ALPHA_C * ww.z + cc.z - s.z * INV_G_SC;
        o.w = fmaxf(z.w, 0.f) - ALPHA_C * ww.w + cc.w - s.w * INV_G_SC;
        if (FIN) {
            o.x = fmaxf(o.x, 0.f); o.y = fmaxf(o.y, 0.f);
            o.z = fmaxf(o.z, 0.f); o.w = fmaxf(o.w, 0.f);
            ((float4*)zout)[i + q] = o;
        } else {
            ((float4*)zout)[i + q] = o;
            float dx = o.x - z.x, dy = o.y - z.y, dz = o.z - z.z, dw = o.w - z.w;
            ls += dx * dx + dy * dy + dz * dz + dw * dw;
            ov[q * 4 + 0] = o.x; ov[q * 4 + 1] = o.y;
            ov[q * 4 + 2] = o.z; ov[q * 4 + 3] = o.w;
            wv8[q * 4 + 0] = ww.x; wv8[q * 4 + 1] = ww.y;
            wv8[q * 4 + 2] = ww.z; wv8[q * 4 + 3] = ww.w;
        }
    }
    if (!FIN) {
        uint32_t hh[4], ll[4];
        #pragma unroll
        for (int pq = 0; pq < 4; pq++) {
            __half h0, h1, l0, l1;
            split2h(fabsf(ov[2 * pq]) - ALPHA_C * wv8[2 * pq], h0, l0);
            split2h(fabsf(ov[2 * pq + 1]) - ALPHA_C * wv8[2 * pq + 1], h1, l1);
            __half2 hp = __halves2half2(h0, h1), lp = __halves2half2(l0, l1);
            hh[pq] = *(uint32_t*)&hp; ll[pq] = *(uint32_t*)&lp;
        }
        size_t e = gid * 8;
        *(uint4*)(g_uh + e) = make_uint4(hh[0], hh[1], hh[2], hh[3]);
        *(uint4*)(g_ul + e) = make_uint4(ll[0], ll[1], ll[2], ll[3]);

        __shared__ float red[256];
        red[threadIdx.x] = ls;
        __syncthreads();
        for (int o2 = 128; o2; o2 >>= 1) {
            if (threadIdx.x < o2) red[threadIdx.x] += red[threadIdx.x + o2];
            __syncthreads();
        }
        if (threadIdx.x == 0) {
            atomicAdd(&g_ss, red[0]);
            __threadfence();
            int t = atomicAdd(&g_cnt, 1);
            if (t == (int)gridDim.x - 1) {
                if (g_ss <= EPS_C * EPS_C) g_flag = 1;
                g_ss = 0.f;
                g_cnt = 0;
            }
        }
    }
}

// ---------------- fp16 GEMM (NP=3: hh+hl+lh; NP=1: hh only) ----------------
__device__ __forceinline__ uint32_t smem_u32(const void* p) {
    uint32_t a;
    asm("{ .reg .u64 t; cvta.to.shared.u64 t, %1; cvt.u32.u64 %0, t; }" : "=r"(a) : "l"(p));
    return a;
}
__device__ __forceinline__ void cp16(uint32_t dst, const void* src) {
    asm volatile("cp.async.cg.shared.global [%0], [%1], 16;" :: "r"(dst), "l"(src));
}
__device__ __forceinline__ void ldsm4(uint32_t* r, uint32_t a) {
    asm volatile("ldmatrix.sync.aligned.m8n8.x4.shared.b16 {%0,%1,%2,%3}, [%4];"
        : "=r"(r[0]), "=r"(r[1]), "=r"(r[2]), "=r"(r[3]) : "r"(a));
}
__device__ __forceinline__ void mma16(float* c, const uint32_t* a, const uint32_t* b) {
    asm volatile("mma.sync.aligned.m16n8k16.row.col.f32.f16.f16.f32 "
        "{%0,%1,%2,%3}, {%4,%5,%6,%7}, {%8,%9}, {%0,%1,%2,%3};"
        : "+f"(c[0]), "+f"(c[1]), "+f"(c[2]), "+f"(c[3])
        : "r"(a[0]), "r"(a[1]), "r"(a[2]), "r"(a[3]), "r"(b[0]), "r"(b[1]));
}

template<int NP>
__global__ void __launch_bounds__(256)
hgemm_k(const __half* __restrict__ Ahp, const __half* __restrict__ Alp, int lda,
        const __half* __restrict__ Bhp, const __half* __restrict__ Blp, int ldb,
        float* __restrict__ Cg, int N, int kchunk, const int* __restrict__ guard)
{
    if (guard && *guard) return;
    extern __shared__ __half hsm[];
    const int tid = threadIdx.x, lane = tid & 31, wid = tid >> 5;
    const int wm = wid >> 2, wn = wid & 3;
    const int m0 = blockIdx.y * 128, n0 = blockIdx.x * 128;
    const int k0 = blockIdx.z * kchunk;
    const int ST = kchunk / HBK;
    const __half* psrc[4] = { Ahp, Alp, Bhp, Blp };
    uint32_t sbase = smem_u32(hsm);

    auto load = [&](int s) {
        int buf = s & 1;
        int kb = k0 + s * HBK;
        #pragma unroll
        for (int t = 0; t < (NP == 3 ? 8 : 4); t++) {
            int id = t * 256 + tid;
            int pl = (NP == 3) ? (id >> 9) : ((id >> 9) * 2);
            int idx = id & 511;
            int row = idx >> 2, kc = idx & 3;
            int isB = pl >> 1;
            const __half* src = psrc[pl] +
                (size_t)((isB ? n0 : m0) + row) * (isB ? ldb : lda) + kb + kc * 8;
            uint32_t dst = sbase + (uint32_t)(buf * HST + pl * HPL + row * HSTR + kc * 8) * 2;
            cp16(dst, src);
        }
    };

    float acc[4][4][4];
    #pragma unroll
    for (int f = 0; f < 4; f++)
        #pragma unroll
        for (int g = 0; g < 4; g++)
            #pragma unroll
            for (int e = 0; e < 4; e++) acc[f][g][e] = 0.f;

    load(0);
    asm volatile("cp.async.commit_group;");
    load(1);
    asm volatile("cp.async.commit_group;");

    const int offA = (lane & 15) * HSTR + (lane >> 4) * 8;
    const int offB = ((lane & 7) + ((lane >> 4) << 3)) * HSTR + ((lane >> 3) & 1) * 8;

    for (int s = 0; s < ST; s++) {
        asm volatile("cp.async.wait_group 1;");
        __syncthreads();
        uint32_t stg = sbase + (uint32_t)((s & 1) * HST) * 2;
        #pragma unroll
        for (int ks = 0; ks < 2; ks++) {
            uint32_t aH[4][4], aL[4][4], bH[4][2], bL[4][2];
            #pragma unroll
            for (int f = 0; f < 4; f++) {
                uint32_t base = stg + (uint32_t)((wm * 64 + f * 16) * HSTR + ks * 16 + offA) * 2;
                ldsm4(aH[f], base);
                if (NP == 3) ldsm4(aL[f], base + HPL * 2);
            }
            #pragma unroll
            for (int gp = 0; gp < 2; gp++) {
                uint32_t r[4];
                uint32_t base = stg + (uint32_t)(2 * HPL + (wn * 32 + gp * 16) * HSTR + ks * 16 + offB) * 2;
                ldsm4(r, base);
                bH[gp * 2][0] = r[0]; bH[gp * 2][1] = r[1];
                bH[gp * 2 + 1][0] = r[2]; bH[gp * 2 + 1][1] = r[3];
                if (NP == 3) {
                    ldsm4(r, base + HPL * 2);
                    bL[gp * 2][0] = r[0]; bL[gp * 2][1] = r[1];
                    bL[gp * 2 + 1][0] = r[2]; bL[gp * 2 + 1][1] = r[3];
                }
            }
            #pragma unroll
            for (int f = 0; f < 4; f++)
                #pragma unroll
                for (int g = 0; g < 4; g++)
                    mma16(acc[f][g], aH[f], bH[g]);
            if (NP == 3) {
                #pragma unroll
                for (int f = 0; f < 4; f++)
                    #pragma unroll
                    for (int g = 0; g < 4; g++)
                        mma16(acc[f][g], aH[f], bL[g]);
                #pragma unroll
                for (int f = 0; f < 4; f++)
                    #pragma unroll
                    for (int g = 0; g < 4; g++)
                        mma16(acc[f][g], aL[f], bH[g]);
            }
        }
        __syncthreads();
        if (s + 2 < ST) load(s + 2);
        asm volatile("cp.async.commit_group;");
    }

    size_t off = (size_t)blockIdx.z * ((size_t)gridDim.y * 128) * N;
    const int tr = lane >> 2, tc = (lane & 3) * 2;
    #pragma unroll
    for (int f = 0; f < 4; f++) {
        int m = m0 + wm * 64 + f * 16 + tr;
        #pragma unroll
        for (int g = 0; g < 4; g++) {
            int n = n0 + wn * 32 + g * 8 + tc;
            *(float2*)&Cg[off + (size_t)m * N + n] = make_float2(acc[f][g][0], acc[f][g][1]);
            *(float2*)&Cg[off + (size_t)(m + 8) * N + n] = make_float2(acc[f][g][2], acc[f][g][3]);
        }
    }
}

// ---------------- host ----------------
extern "C" void kernel_launch(void* const* d_in, const int* in_sizes, int n_in,
                              void* d_out, int out_size) {
    (void)in_sizes; (void)n_in; (void)out_size;
    const float* dd  = (const float*)d_in[0];
    const float* dA  = (const float*)d_in[1];
    const float* dB  = (const float*)d_in[2];
    const float* dW1 = (const float*)d_in[3];
    const float* db1 = (const float*)d_in[4];
    const float* dW2 = (const float*)d_in[5];
    const float* db2 = (const float*)d_in[6];
    const float* dz0 = (const float*)d_in[7];
    float* out = (float*)d_out;

    void* p;
    cudaGetSymbolAddress(&p, g_S);   float* S    = (float*)p;
    cudaGetSymbolAddress(&p, g_Xa);  float* Xa   = (float*)p;
    cudaGetSymbolAddress(&p, g_Xb);  float* Xb   = (float*)p;
    cudaGetSymbolAddress(&p, g_T);   float* Tm   = (float*)p;
    cudaGetSymbolAddress(&p, g_G);   float* G    = (float*)p;
    cudaGetSymbolAddress(&p, g_At);  float* At   = (float*)p;
    cudaGetSymbolAddress(&p, g_W1t); float* W1t  = (float*)p;
    cudaGetSymbolAddress(&p, g_W2t); float* W2t  = (float*)p;
    cudaGetSymbolAddress(&p, g_c);   float* c    = (float*)p;
    cudaGetSymbolAddress(&p, g_tv);  float* tv   = (float*)p;
    cudaGetSymbolAddress(&p, g_v);   float* v    = (float*)p;
    cudaGetSymbolAddress(&p, g_y);   float* y    = (float*)p;
    cudaGetSymbolAddress(&p, g_h);   float* h    = (float*)p;
    cudaGetSymbolAddress(&p, g_w);   float* wbuf = (float*)p;
    cudaGetSymbolAddress(&p, g_za);  float* za   = (float*)p;
    cudaGetSymbolAddress(&p, g_zb);  float* zbb  = (float*)p;
    cudaGetSymbolAddress(&p, g_P);   float* P    = (float*)p;
    cudaGetSymbolAddress(&p, g_flag); int* flag  = (int*)p;
    cudaGetSymbolAddress(&p, g_Ah);  __half* Ahp = (__half*)p;
    cudaGetSymbolAddress(&p, g_Al);  __half* Alp = (__half*)p;
    cudaGetSymbolAddress(&p, g_Gh);  __half* Ghp = (__half*)p;
    cudaGetSymbolAddress(&p, g_Gl);  __half* Glp = (__half*)p;
    cudaGetSymbolAddress(&p, g_uh);  __half* uhp = (__half*)p;
    cudaGetSymbolAddress(&p, g_ul);  __half* ulp = (__half*)p;
    cudaGetSymbolAddress(&p, g_rth); __half* rthp = (__half*)p;
    cudaGetSymbolAddress(&p, g_rtl); __half* rtlp = (__half*)p;
    cudaGetSymbolAddress(&p, g_Sh);  __half* Shp = (__half*)p;
    cudaGetSymbolAddress(&p, g_Sl);  __half* Slp = (__half*)p;
    cudaGetSymbolAddress(&p, g_Xh);  __half* Xhp = (__half*)p;
    cudaGetSymbolAddress(&p, g_Xl);  __half* Xlp = (__half*)p;
    cudaGetSymbolAddress(&p, g_Th);  __half* Thp = (__half*)p;
    cudaGetSymbolAddress(&p, g_Tl);  __half* Tlp = (__half*)p;
    cudaGetSymbolAddress(&p, g_dh);  __half* dhp = (__half*)p;
    cudaGetSymbolAddress(&p, g_dl);  __half* dlp = (__half*)p;
    cudaGetSymbolAddress(&p, g_W1h); __half* W1h = (__half*)p;
    cudaGetSymbolAddress(&p, g_W1l); __half* W1l = (__half*)p;
    cudaGetSymbolAddress(&p, g_W2h); __half* W2h = (__half*)p;
    cudaGetSymbolAddress(&p, g_W2l); __half* W2l = (__half*)p;
    cudaGetSymbolAddress(&p, g_hph); __half* hph = (__half*)p;
    cudaGetSymbolAddress(&p, g_hpl); __half* hpl = (__half*)p;

    cudaFuncSetAttribute(hgemm_k<3>,
                         cudaFuncAttributeMaxDynamicSharedMemorySize, HSMEM);
    cudaFuncSetAttribute(hgemm_k<1>,
                         cudaFuncAttributeMaxDynamicSharedMemorySize, HSMEM);

    init_k<<<1, 1>>>();
    copy4_k<<<(BC * N2C / 4) / 256, 256>>>((float4*)za, (const float4*)dz0);

    // A planes (x64)
    splitH_k<<<(int)(((size_t)N1C * N2C / 8) / 256), 256>>>(dA, Ahp, Alp, A_SC);

    // S = A A^T : hgemm, accum = 4096*S, split 4 -> 256 CTAs
    {
        dim3 g(N1C / 128, N1C / 128, SPL_S);
        hgemm_k<3><<<g, 256, HSMEM>>>(Ahp, Alp, N2C, Ahp, Alp, N2C, P, N1C, N2C / SPL_S, nullptr);
        reduce_sum_k<<<(N1C * N1C / 8) / 256, 256>>>(P, S, (size_t)N1C * N1C / 4, SPL_S, 1.f / 4096.f);
    }

    // power iteration (fp32 S)
    fill_k<<<N1C / 256, 256>>>(v, 0.03125f, N1C);
    for (int i = 0; i < PI_ITERS; i++) {
        spmv_k<<<N1C / 8, dim3(32, 8)>>>(S, v, y);
        pi_norm_k<<<1, 256>>>(y, v);
    }
    initX_k<<<(N1C * N1C) / 256, 256>>>(Xa);

    // S planes (x16)
    splitH_k<<<(int)(((size_t)N1C * N1C / 8) / 256), 256>>>(S, Shp, Slp, 16.f);

    // Newton-Schulz: 4 cheap (NP=1) + 2 precise (NP=3), symmetrized, split 4
    float* Xc = Xa; float* Xn = Xb;
    {
        dim3 g(N1C / 128, N1C / 128, SPL_NS);
        dim3 gsym(N1C / 32, N1C / 8);
        size_t s4 = (size_t)N1C * N1C / 4;
        int nsgrid = (N1C * N1C / 8) / 256;
        for (int i = 0; i < NS_ITERS; i++) {
            symm_k<<<gsym, 256>>>(Xc);
            splitH_k<<<(N1C * N1C / 8) / 256, 256>>>(Xc, Xhp, Xlp, 32.f);
            if (i < NS_CHEAP)
                hgemm_k<1><<<g, 256, HSMEM>>>(Xhp, Xlp, N1C, Shp, Slp, N1C, P, N1C, N1C / SPL_NS, nullptr);
            else
                hgemm_k<3><<<g, 256, HSMEM>>>(Xhp, Xlp, N1C, Shp, Slp, N1C, P, N1C, N1C / SPL_NS, nullptr);
            reduce_sum_k<<<nsgrid, 256>>>(P, Tm, s4, SPL_NS, 1.f / 512.f);
            splitH_k<<<(N1C * N1C / 8) / 256, 256>>>(Tm, Thp, Tlp, 32.f);
            if (i < NS_CHEAP)
                hgemm_k<1><<<g, 256, HSMEM>>>(Thp, Tlp, N1C, Xhp, Xlp, N1C, P, N1C, N1C / SPL_NS, nullptr);
            else
                hgemm_k<3><<<g, 256, HSMEM>>>(Thp, Tlp, N1C, Xhp, Xlp, N1C, P, N1C, N1C / SPL_NS, nullptr);
            reduce_ns_k<<<nsgrid, 256>>>(P, Xc, Xn, s4, SPL_NS, 1.f / 1024.f);
            float* t2 = Xc; Xc = Xn; Xn = t2;
        }
        symm_k<<<gsym, 256>>>(Xc);
    }

    // c = A^T (X b)
    spmv_k<<<N1C / 8, dim3(32, 8)>>>(Xc, dB, tv);
    atmv_k<<<N2C / 256, 256>>>(dA, tv, c);

    // G = A^T X: At planes (x64, temp in Gh/Gl), X planes (x32) -> accum 2048*G
    transp_k<<<dim3(N2C / 32, N1C / 32), dim3(32, 8)>>>(At, dA, N1C, N2C);
    splitH_k<<<(int)(((size_t)N2C * N1C / 8) / 256), 256>>>(At, Ghp, Glp, A_SC);
    splitH_k<<<(N1C * N1C / 8) / 256, 256>>>(Xc, Xhp, Xlp, 32.f);
    {
        dim3 g(N1C / 128, N2C / 128, 1);      // 256 CTAs already
        hgemm_k<3><<<g, 256, HSMEM>>>(Ghp, Glp, N1C, Xhp, Xlp, N1C, P, N1C, N1C, nullptr);
        reduce_sum_k<<<(int)(((size_t)N2C * N1C / 8) / 256), 256>>>(
            P, G, 0, 1, 1.f / 2048.f);
    }
    splitH_k<<<(int)(((size_t)N2C * N1C / 8) / 256), 256>>>(G, Ghp, Glp, G_SC);

    // MLP on hgemm (split 8 / 4 -> 256 CTAs each)
    transp_k<<<dim3(HC / 32, DC / 32), dim3(32, 8)>>>(W1t, dW1, DC, HC);
    splitH_k<<<(int)(((size_t)HC * DC / 8) / 256), 256>>>(W1t, W1h, W1l, 32.f);
    transp_k<<<dim3(N2C / 32, HC / 32), dim3(32, 8)>>>(W2t, dW2, HC, N2C);
    splitH_k<<<(int)(((size_t)N2C * HC / 8) / 256), 256>>>(W2t, W2h, W2l, 32.f);
    splitH_k<<<(BC * DC / 8) / 256, 256>>>(dd, dhp, dlp, 1.f);
    {
        dim3 g1(HC / 128, BC / 128, SPL_M1);
        hgemm_k<3><<<g1, 256, HSMEM>>>(dhp, dlp, DC, W1h, W1l, DC, P, HC, DC / SPL_M1, nullptr);
        reduce_bias_k<true><<<(BC * HC / 8) / 256, 256>>>(
            P, db1, h, (size_t)BC * HC / 4, SPL_M1, HC / 4, 1.f / 32.f);
        splitH_k<<<(BC * HC / 8) / 256, 256>>>(h, hph, hpl, 1.f);
        dim3 g2(N2C / 128, BC / 128, SPL_M2);
        hgemm_k<3><<<g2, 256, HSMEM>>>(hph, hpl, HC, W2h, W2l, HC, P, N2C, HC / SPL_M2, nullptr);
        reduce_bias_k<false><<<(BC * N2C / 8) / 256, 256>>>(
            P, db2, wbuf, (size_t)BC * N2C / 4, SPL_M2, N2C / 4, 1.f / 32.f);
    }

    // initial u planes
    u0_k<<<(BC * N2C / 4) / 256, 256>>>(za, wbuf);

    // DYS loop (gr split 16 -> 256 CTAs, gz split 4 -> 256 CTAs)
    dim3 gr(BC / 128, N1C / 128, SPL_GR);
    dim3 gz(N2C / 128, BC / 128, SPL_GZ);
    float* zb2[2] = { za, zbb };
    for (int it = 1; it <= 50; ++it) {
        const float* zin = zb2[(it - 1) & 1];
        float* zout = zb2[it & 1];
        hgemm_k<3><<<gr, 256, HSMEM>>>(Ahp, Alp, N2C, uhp, ulp, N2C, P, BC, N2C / SPL_GR, flag);
        reduce_tr_k<<<dim3(N1C / 32, BC / 32), dim3(32, 8)>>>(P, flag);
        hgemm_k<3><<<gz, 256, HSMEM>>>(rthp, rtlp, N1C, Ghp, Glp, N1C, P, N2C, N1C / SPL_GZ, flag);
        zupd_k<false><<<(BC * N2C / 8) / 256, 256>>>(P, zin, wbuf, c, zout, flag);
    }

    // final unguarded step, relu into d_out
    hgemm_k<3><<<gr, 256, HSMEM>>>(Ahp, Alp, N2C, uhp, ulp, N2C, P, BC, N2C / SPL_GR, nullptr);
    reduce_tr_k<<<dim3(N1C / 32, BC / 32), dim3(32, 8)>>>(P, nullptr);
    hgemm_k<3><<<gz, 256, HSMEM>>>(rthp, rtlp, N1C, Ghp, Glp, N1C, P, N2C, N1C / SPL_GZ, nullptr);
    zupd_k<true><<<(BC * N2C / 8) / 256, 256>>>(P, za, wbuf, c, out, nullptr);
}

// round 14
// speedup vs baseline: 4.2541x; 1.0182x over previous
#include <cuda_runtime.h>
#include <cuda_fp16.h>
#include <math.h>
#include <stdint.h>

// ----------------------------------------------------------------------------
// DYS_opt_net.  ALL GEMMs on legacy fp16 mma.sync m16n8k16 with fp16x3 split
// (hh+hl+lh, fp32 accum), static per-matrix scaling, explicit symmetrization
// in Newton-Schulz (4 cheap + 2 precise iters), 2-stage cp.async, 2 CTAs/SM.
// R14: fine-grained LDSM/MMA interleave — B frags staged per-ks, A frags
// loaded per-row immediately before that row's 12 MMAs (hides LDSM latency
// under the tensor-pipe queue; lower reg pressure lets ptxas pipeline).
// z' = relu(z) - a*w + c - (G (A u^T))^T,  u = |z| - a*w
// ----------------------------------------------------------------------------

#define N1C 1024
#define N2C 4096
#define BC  256
#define DC  512
#define HC  2048

#define ALPHA_C 0.05f
#define EPS_C   0.01f
#define NS_ITERS 6
#define NS_CHEAP 4
#define PI_ITERS 12

#define A_SC 64.f
#define G_SC 32.f
#define INV_A_SC 0.015625f
#define INV_G_SC 0.03125f

// splits (grids ~256 CTAs everywhere)
#define SPL_GR 16
#define SPL_GZ 4
#define SPL_S  4
#define SPL_NS 4
#define SPL_M1 8
#define SPL_M2 4

// fp16 GEMM tile config
#define HBK 32
#define HSTR 40                  // halves per smem row (32 + 8 pad)
#define HPL (128*HSTR)
#define HST (4*HPL)
#define HSMEM (2*HST*2)          // 2 stages: 81920 B -> 2 CTAs/SM

__device__ float g_S  [(size_t)N1C*N1C];
__device__ float g_Xa [(size_t)N1C*N1C];
__device__ float g_Xb [(size_t)N1C*N1C];
__device__ float g_T  [(size_t)N1C*N1C];
__device__ float g_G  [(size_t)N2C*N1C];
__device__ float g_At [(size_t)N2C*N1C];
__device__ float g_W1t[(size_t)HC*DC];
__device__ float g_W2t[(size_t)N2C*HC];
__device__ float g_c  [N2C];
__device__ float g_tv [N1C];
__device__ float g_v  [N1C];
__device__ float g_y  [N1C];
__device__ float g_h  [(size_t)BC*HC];
__device__ float g_w  [(size_t)BC*N2C];
__device__ float g_za [(size_t)BC*N2C];
__device__ float g_zb [(size_t)BC*N2C];
__device__ float g_P  [(size_t)4*1024*1024];
__device__ __half g_Ah [(size_t)N1C*N2C];
__device__ __half g_Al [(size_t)N1C*N2C];
__device__ __half g_Gh [(size_t)N2C*N1C];
__device__ __half g_Gl [(size_t)N2C*N1C];
__device__ __half g_uh [(size_t)BC*N2C];
__device__ __half g_ul [(size_t)BC*N2C];
__device__ __half g_rth[(size_t)BC*N1C];
__device__ __half g_rtl[(size_t)BC*N1C];
__device__ __half g_Sh [(size_t)N1C*N1C];
__device__ __half g_Sl [(size_t)N1C*N1C];
__device__ __half g_Xh [(size_t)N1C*N1C];
__device__ __half g_Xl [(size_t)N1C*N1C];
__device__ __half g_Th [(size_t)N1C*N1C];
__device__ __half g_Tl [(size_t)N1C*N1C];
__device__ __half g_dh [(size_t)BC*DC];
__device__ __half g_dl [(size_t)BC*DC];
__device__ __half g_W1h[(size_t)HC*DC];
__device__ __half g_W1l[(size_t)HC*DC];
__device__ __half g_W2h[(size_t)N2C*HC];
__device__ __half g_W2l[(size_t)N2C*HC];
__device__ __half g_hph[(size_t)BC*HC];
__device__ __half g_hpl[(size_t)BC*HC];
__device__ float g_lam;
__device__ float g_ss;
__device__ int   g_flag;
__device__ int   g_cnt;

// ---------------- small utility kernels ----------------
__global__ void init_k() { g_ss = 0.f; g_flag = 0; g_cnt = 0; }

__global__ void copy4_k(float4* __restrict__ dst, const float4* __restrict__ src) {
    int i = blockIdx.x * blockDim.x + threadIdx.x;
    dst[i] = src[i];
}

__global__ void fill_k(float* v, float val, int n) {
    int i = blockIdx.x * blockDim.x + threadIdx.x;
    if (i < n) v[i] = val;
}

// in-place symmetrization: X <- (X + X^T)/2 (one thread per i<j pair)
__global__ void symm_k(float* __restrict__ X) {
    int j = blockIdx.x * 32 + (threadIdx.x & 31);
    int i = blockIdx.y * 8 + (threadIdx.x >> 5);
    if (i < j) {
        size_t ij = (size_t)i * N1C + j;
        size_t ji = (size_t)j * N1C + i;
        float m = 0.5f * (X[ij] + X[ji]);
        X[ij] = m;
        X[ji] = m;
    }
}

__global__ void spmv_k(const float* __restrict__ M_, const float* __restrict__ v,
                       float* __restrict__ y) {
    int row = blockIdx.x * 8 + threadIdx.y;
    const float* mr = M_ + (size_t)row * N1C;
    float s = 0.f;
    for (int j = threadIdx.x; j < N1C; j += 32) s += mr[j] * v[j];
    #pragma unroll
    for (int o = 16; o; o >>= 1) s += __shfl_xor_sync(0xffffffffu, s, o);
    if (threadIdx.x == 0) y[row] = s;
}

__global__ void pi_norm_k(const float* __restrict__ y, float* __restrict__ v) {
    __shared__ float red[256];
    float s = 0.f;
    for (int i = threadIdx.x; i < N1C; i += 256) { float t = y[i]; s += t * t; }
    red[threadIdx.x] = s; __syncthreads();
    for (int o = 128; o; o >>= 1) {
        if (threadIdx.x < o) red[threadIdx.x] += red[threadIdx.x + o];
        __syncthreads();
    }
    float nrm = sqrtf(red[0]);
    float inv = 1.f / nrm;
    for (int i = threadIdx.x; i < N1C; i += 256) v[i] = y[i] * inv;
    if (threadIdx.x == 0) g_lam = nrm;
}

__global__ void initX_k(float* X) {
    float a = 1.8f / g_lam;
    int i = blockIdx.x * 256 + threadIdx.x;
    int rr = i / N1C, cc = i % N1C;
    X[i] = (rr == cc) ? a : 0.f;
}

__global__ void atmv_k(const float* __restrict__ A, const float* __restrict__ t,
                       float* __restrict__ c) {
    __shared__ float ts[N1C];
    for (int i = threadIdx.x; i < N1C; i += 256) ts[i] = t[i];
    __syncthreads();
    int j = blockIdx.x * 256 + threadIdx.x;
    float s = 0.f;
    for (int i = 0; i < N1C; i++) s += A[(size_t)i * N2C + j] * ts[i];
    c[j] = s;
}

__global__ void transp_k(float* __restrict__ dst, const float* __restrict__ src,
                         int R, int C) {
    __shared__ float t[32][33];
    int bx = blockIdx.x * 32, by = blockIdx.y * 32;
    #pragma unroll
    for (int i = 0; i < 4; i++) {
        int r = by + threadIdx.y + i * 8;
        t[threadIdx.y + i * 8][threadIdx.x] = src[(size_t)r * C + bx + threadIdx.x];
    }
    __syncthreads();
    #pragma unroll
    for (int i = 0; i < 4; i++) {
        int r = bx + threadIdx.y + i * 8;
        dst[(size_t)r * R + by + threadIdx.x] = t[threadIdx.x][threadIdx.y + i * 8];
    }
}

__device__ __forceinline__ void split2h(float x, __half& h, __half& l) {
    h = __float2half_rn(x);
    l = __float2half_rn(x - __half2float(h));
}

// split scaled fp32 -> (hi, lo) fp16 planes; 8 elements per thread
__global__ void splitH_k(const float* __restrict__ src, __half* __restrict__ ph,
                         __half* __restrict__ pl, float scale) {
    size_t e = ((size_t)blockIdx.x * 256 + threadIdx.x) * 8;
    uint32_t hh[4], ll[4];
    #pragma unroll
    for (int p = 0; p < 4; p++) {
        __half h0, h1, l0, l1;
        split2h(src[e + 2 * p] * scale, h0, l0);
        split2h(src[e + 2 * p + 1] * scale, h1, l1);
        __half2 hp = __halves2half2(h0, h1), lp = __halves2half2(l0, l1);
        hh[p] = *(uint32_t*)&hp; ll[p] = *(uint32_t*)&lp;
    }
    *(uint4*)(ph + e) = make_uint4(hh[0], hh[1], hh[2], hh[3]);
    *(uint4*)(pl + e) = make_uint4(ll[0], ll[1], ll[2], ll[3]);
}

// u = |z| - a*w -> u planes; 4 elements per thread
__global__ void u0_k(const float* __restrict__ z, const float* __restrict__ w) {
    size_t i = (size_t)blockIdx.x * 256 + threadIdx.x;
    float4 zv = ((const float4*)z)[i];
    float4 wv = ((const float4*)w)[i];
    __half h0, h1, h2, h3, l0, l1, l2, l3;
    split2h(fabsf(zv.x) - ALPHA_C * wv.x, h0, l0);
    split2h(fabsf(zv.y) - ALPHA_C * wv.y, h1, l1);
    split2h(fabsf(zv.z) - ALPHA_C * wv.z, h2, l2);
    split2h(fabsf(zv.w) - ALPHA_C * wv.w, h3, l3);
    __half2 ha = __halves2half2(h0, h1), hb = __halves2half2(h2, h3);
    __half2 la = __halves2half2(l0, l1), lb = __halves2half2(l2, l3);
    ((uint2*)g_uh)[i] = make_uint2(*(uint32_t*)&ha, *(uint32_t*)&hb);
    ((uint2*)g_ul)[i] = make_uint2(*(uint32_t*)&la, *(uint32_t*)&lb);
}

// ---------------- reduce kernels (2x float4 ILP, scaled) ----------------
__global__ void reduce_sum_k(const float* __restrict__ P, float* __restrict__ out,
                             size_t stride4, int ns, float scale) {
    size_t i = ((size_t)blockIdx.x * 256 + threadIdx.x) * 2;
    const float4* p = (const float4*)P;
    float4 s0 = p[i], s1 = p[i + 1];
    for (int sp = 1; sp < ns; sp++) {
        float4 t0 = p[(size_t)sp * stride4 + i];
        float4 t1 = p[(size_t)sp * stride4 + i + 1];
        s0.x += t0.x; s0.y += t0.y; s0.z += t0.z; s0.w += t0.w;
        s1.x += t1.x; s1.y += t1.y; s1.z += t1.z; s1.w += t1.w;
    }
    s0.x *= scale; s0.y *= scale; s0.z *= scale; s0.w *= scale;
    s1.x *= scale; s1.y *= scale; s1.z *= scale; s1.w *= scale;
    ((float4*)out)[i] = s0;
    ((float4*)out)[i + 1] = s1;
}

__global__ void reduce_ns_k(const float* __restrict__ P, const float* __restrict__ X,
                            float* __restrict__ out, size_t stride4, int ns, float scale) {
    size_t i = ((size_t)blockIdx.x * 256 + threadIdx.x) * 2;
    const float4* p = (const float4*)P;
    float4 s0 = p[i], s1 = p[i + 1];
    for (int sp = 1; sp < ns; sp++) {
        float4 t0 = p[(size_t)sp * stride4 + i];
        float4 t1 = p[(size_t)sp * stride4 + i + 1];
        s0.x += t0.x; s0.y += t0.y; s0.z += t0.z; s0.w += t0.w;
        s1.x += t1.x; s1.y += t1.y; s1.z += t1.z; s1.w += t1.w;
    }
    float4 x0 = ((const float4*)X)[i], x1 = ((const float4*)X)[i + 1];
    float4 o0, o1;
    o0.x = 2.f * x0.x - s0.x * scale; o0.y = 2.f * x0.y - s0.y * scale;
    o0.z = 2.f * x0.z - s0.z * scale; o0.w = 2.f * x0.w - s0.w * scale;
    o1.x = 2.f * x1.x - s1.x * scale; o1.y = 2.f * x1.y - s1.y * scale;
    o1.z = 2.f * x1.z - s1.z * scale; o1.w = 2.f * x1.w - s1.w * scale;
    ((float4*)out)[i] = o0;
    ((float4*)out)[i + 1] = o1;
}

template<bool RELU>
__global__ void reduce_bias_k(const float* __restrict__ P, const float* __restrict__ bias,
                              float* __restrict__ out, size_t stride4, int ns, int n4,
                              float scale) {
    size_t i = ((size_t)blockIdx.x * 256 + threadIdx.x) * 2;
    const float4* p = (const float4*)P;
    float4 s0 = p[i], s1 = p[i + 1];
    for (int sp = 1; sp < ns; sp++) {
        float4 t0 = p[(size_t)sp * stride4 + i];
        float4 t1 = p[(size_t)sp * stride4 + i + 1];
        s0.x += t0.x; s0.y += t0.y; s0.z += t0.z; s0.w += t0.w;
        s1.x += t1.x; s1.y += t1.y; s1.z += t1.z; s1.w += t1.w;
    }
    float4 b0 = ((const float4*)bias)[i % n4];
    float4 b1 = ((const float4*)bias)[(i + 1) % n4];
    s0.x = s0.x * scale + b0.x; s0.y = s0.y * scale + b0.y;
    s0.z = s0.z * scale + b0.z; s0.w = s0.w * scale + b0.w;
    s1.x = s1.x * scale + b1.x; s1.y = s1.y * scale + b1.y;
    s1.z = s1.z * scale + b1.z; s1.w = s1.w * scale + b1.w;
    if (RELU) {
        s0.x = fmaxf(s0.x, 0.f); s0.y = fmaxf(s0.y, 0.f);
        s0.z = fmaxf(s0.z, 0.f); s0.w = fmaxf(s0.w, 0.f);
        s1.x = fmaxf(s1.x, 0.f); s1.y = fmaxf(s1.y, 0.f);
        s1.z = fmaxf(s1.z, 0.f); s1.w = fmaxf(s1.w, 0.f);
    }
    ((float4*)out)[i] = s0;
    ((float4*)out)[i + 1] = s1;
}

// sum SPL_GR partials of 64*(A u^T) [N1C][BC]; write rt planes [BC][N1C] (x 1/64)
__global__ void reduce_tr_k(const float* __restrict__ P, const int* __restrict__ guard) {
    if (guard && *guard) return;
    __shared__ float t[32][33];
    int bm = blockIdx.x * 32;
    int bb = blockIdx.y * 32;
    #pragma unroll
    for (int i = 0; i < 4; i++) {
        int m = bm + threadIdx.y + i * 8;
        size_t idx = (size_t)m * BC + bb + threadIdx.x;
        float s = 0.f;
        #pragma unroll
        for (int sp = 0; sp < SPL_GR; sp++) s += P[(size_t)sp * N1C * BC + idx];
        t[threadIdx.y + i * 8][threadIdx.x] = s;
    }
    __syncthreads();
    #pragma unroll
    for (int i = 0; i < 4; i++) {
        int b = bb + threadIdx.y + i * 8;
        float vv = t[threadIdx.x][threadIdx.y + i * 8] * INV_A_SC;
        __half h, l;
        split2h(vv, h, l);
        size_t o = (size_t)b * N1C + bm + threadIdx.x;
        g_rth[o] = h;
        g_rtl[o] = l;
    }
}

// z-update: zn = relu(z) - a*w + c - (1/32)*sum(SPL_GZ partials); + u planes + check
template<bool FIN>
__global__ void zupd_k(const float* __restrict__ P, const float* __restrict__ zin,
                       const float* __restrict__ w, const float* __restrict__ c,
                       float* __restrict__ zout, const int* __restrict__ guard) {
    size_t gid = (size_t)blockIdx.x * 256 + threadIdx.x;
    size_t i = gid * 2;
    if (!FIN && guard && *guard) {
        ((float4*)zout)[i] = ((const float4*)zin)[i];
        ((float4*)zout)[i + 1] = ((const float4*)zin)[i + 1];
        return;
    }
    const float4* p = (const float4*)P;
    float ov[8], wv8[8];
    float ls = 0.f;
    #pragma unroll
    for (int q = 0; q < 2; q++) {
        float4 s = p[i + q];
        #pragma unroll
        for (int sp = 1; sp < SPL_GZ; sp++) {
            float4 t = p[(size_t)sp * (BC * (N2C / 4)) + i + q];
            s.x += t.x; s.y += t.y; s.z += t.z; s.w += t.w;
        }
        float4 z = ((const float4*)zin)[i + q];
        float4 ww = ((const float4*)w)[i + q];
        float4 cc = ((const float4*)c)[(i + q) & (N2C / 4 - 1)];
        float4 o;
        o.x = fmaxf(z.x, 0.f) - ALPHA_C * ww.x + cc.x - s.x * INV_G_SC;
        o.y = fmaxf(z.y, 0.f) - ALPHA_C * ww.y + cc.y - s.y * INV_G_SC;
        o.z = fmaxf(z.z, 0.f) - ALPHA_C * ww.z + cc.z - s.z * INV_G_SC;
        o.w = fmaxf(z.w, 0.f) - ALPHA_C * ww.w + cc.w - s.w * INV_G_SC;
        if (FIN) {
            o.x = fmaxf(o.x, 0.f); o.y = fmaxf(o.y, 0.f);
            o.z = fmaxf(o.z, 0.f); o.w = fmaxf(o.w, 0.f);
            ((float4*)zout)[i + q] = o;
        } else {
            ((float4*)zout)[i + q] = o;
            float dx = o.x - z.x, dy = o.y - z.y, dz = o.z - z.z, dw = o.w - z.w;
            ls += dx * dx + dy * dy + dz * dz + dw * dw;
            ov[q * 4 + 0] = o.x; ov[q * 4 + 1] = o.y;
            ov[q * 4 + 2] = o.z; ov[q * 4 + 3] = o.w;
            wv8[q * 4 + 0] = ww.x; wv8[q * 4 + 1] = ww.y;
            wv8[q * 4 + 2] = ww.z; wv8[q * 4 + 3] = ww.w;
        }
    }
    if (!FIN) {
        uint32_t hh[4], ll[4];
        #pragma unroll
        for (int pq = 0; pq < 4; pq++) {
            __half h0, h1, l0, l1;
            split2h(fabsf(ov[2 * pq]) - ALPHA_C * wv8[2 * pq], h0, l0);
            split2h(fabsf(ov[2 * pq + 1]) - ALPHA_C * wv8[2 * pq + 1], h1, l1);
            __half2 hp = __halves2half2(h0, h1), lp = __halves2half2(l0, l1);
            hh[pq] = *(uint32_t*)&hp; ll[pq] = *(uint32_t*)&lp;
        }
        size_t e = gid * 8;
        *(uint4*)(g_uh + e) = make_uint4(hh[0], hh[1], hh[2], hh[3]);
        *(uint4*)(g_ul + e) = make_uint4(ll[0], ll[1], ll[2], ll[3]);

        __shared__ float red[256];
        red[threadIdx.x] = ls;
        __syncthreads();
        for (int o2 = 128; o2; o2 >>= 1) {
            if (threadIdx.x < o2) red[threadIdx.x] += red[threadIdx.x + o2];
            __syncthreads();
        }
        if (threadIdx.x == 0) {
            atomicAdd(&g_ss, red[0]);
            __threadfence();
            int t = atomicAdd(&g_cnt, 1);
            if (t == (int)gridDim.x - 1) {
                if (g_ss <= EPS_C * EPS_C) g_flag = 1;
                g_ss = 0.f;
                g_cnt = 0;
            }
        }
    }
}

// ---------------- fp16 GEMM (NP=3: hh+hl+lh; NP=1: hh only) ----------------
__device__ __forceinline__ uint32_t smem_u32(const void* p) {
    uint32_t a;
    asm("{ .reg .u64 t; cvta.to.shared.u64 t, %1; cvt.u32.u64 %0, t; }" : "=r"(a) : "l"(p));
    return a;
}
__device__ __forceinline__ void cp16(uint32_t dst, const void* src) {
    asm volatile("cp.async.cg.shared.global [%0], [%1], 16;" :: "r"(dst), "l"(src));
}
__device__ __forceinline__ void ldsm4(uint32_t* r, uint32_t a) {
    asm volatile("ldmatrix.sync.aligned.m8n8.x4.shared.b16 {%0,%1,%2,%3}, [%4];"
        : "=r"(r[0]), "=r"(r[1]), "=r"(r[2]), "=r"(r[3]) : "r"(a));
}
__device__ __forceinline__ void mma16(float* c, const uint32_t* a, const uint32_t* b) {
    asm volatile("mma.sync.aligned.m16n8k16.row.col.f32.f16.f16.f32 "
        "{%0,%1,%2,%3}, {%4,%5,%6,%7}, {%8,%9}, {%0,%1,%2,%3};"
        : "+f"(c[0]), "+f"(c[1]), "+f"(c[2]), "+f"(c[3])
        : "r"(a[0]), "r"(a[1]), "r"(a[2]), "r"(a[3]), "r"(b[0]), "r"(b[1]));
}

template<int NP>
__global__ void __launch_bounds__(256)
hgemm_k(const __half* __restrict__ Ahp, const __half* __restrict__ Alp, int lda,
        const __half* __restrict__ Bhp, const __half* __restrict__ Blp, int ldb,
        float* __restrict__ Cg, int N, int kchunk, const int* __restrict__ guard)
{
    if (guard && *guard) return;
    extern __shared__ __half hsm[];
    const int tid = threadIdx.x, lane = tid & 31, wid = tid >> 5;
    const int wm = wid >> 2, wn = wid & 3;
    const int m0 = blockIdx.y * 128, n0 = blockIdx.x * 128;
    const int k0 = blockIdx.z * kchunk;
    const int ST = kchunk / HBK;
    const __half* psrc[4] = { Ahp, Alp, Bhp, Blp };
    uint32_t sbase = smem_u32(hsm);

    auto load = [&](int s) {
        int buf = s & 1;
        int kb = k0 + s * HBK;
        #pragma unroll
        for (int t = 0; t < (NP == 3 ? 8 : 4); t++) {
            int id = t * 256 + tid;
            int pl = (NP == 3) ? (id >> 9) : ((id >> 9) * 2);
            int idx = id & 511;
            int row = idx >> 2, kc = idx & 3;
            int isB = pl >> 1;
            const __half* src = psrc[pl] +
                (size_t)((isB ? n0 : m0) + row) * (isB ? ldb : lda) + kb + kc * 8;
            uint32_t dst = sbase + (uint32_t)(buf * HST + pl * HPL + row * HSTR + kc * 8) * 2;
            cp16(dst, src);
        }
    };

    float acc[4][4][4];
    #pragma unroll
    for (int f = 0; f < 4; f++)
        #pragma unroll
        for (int g = 0; g < 4; g++)
            #pragma unroll
            for (int e = 0; e < 4; e++) acc[f][g][e] = 0.f;

    load(0);
    asm volatile("cp.async.commit_group;");
    load(1);
    asm volatile("cp.async.commit_group;");

    const int offA = (lane & 15) * HSTR + (lane >> 4) * 8;
    const int offB = ((lane & 7) + ((lane >> 4) << 3)) * HSTR + ((lane >> 3) & 1) * 8;

    for (int s = 0; s < ST; s++) {
        asm volatile("cp.async.wait_group 1;");
        __syncthreads();
        uint32_t stg = sbase + (uint32_t)((s & 1) * HST) * 2;
        #pragma unroll
        for (int ks = 0; ks < 2; ks++) {
            // stage all B fragments for this ks
            uint32_t bH[4][2], bL[4][2];
            #pragma unroll
            for (int gp = 0; gp < 2; gp++) {
                uint32_t r[4];
                uint32_t base = stg + (uint32_t)(2 * HPL + (wn * 32 + gp * 16) * HSTR + ks * 16 + offB) * 2;
                ldsm4(r, base);
                bH[gp * 2][0] = r[0]; bH[gp * 2][1] = r[1];
                bH[gp * 2 + 1][0] = r[2]; bH[gp * 2 + 1][1] = r[3];
                if (NP == 3) {
                    ldsm4(r, base + HPL * 2);
                    bL[gp * 2][0] = r[0]; bL[gp * 2][1] = r[1];
                    bL[gp * 2 + 1][0] = r[2]; bL[gp * 2 + 1][1] = r[3];
                }
            }
            // per A-row: 2 LDSM immediately followed by that row's MMAs.
            // LDSM latency of row f+1 hides under row f's tensor-pipe queue.
            #pragma unroll
            for (int f = 0; f < 4; f++) {
                uint32_t aH[4], aL[4];
                uint32_t base = stg + (uint32_t)((wm * 64 + f * 16) * HSTR + ks * 16 + offA) * 2;
                ldsm4(aH, base);
                if (NP == 3) ldsm4(aL, base + HPL * 2);
                #pragma unroll
                for (int g = 0; g < 4; g++)
                    mma16(acc[f][g], aH, bH[g]);
                if (NP == 3) {
                    #pragma unroll
                    for (int g = 0; g < 4; g++)
                        mma16(acc[f][g], aH, bL[g]);
                    #pragma unroll
                    for (int g = 0; g < 4; g++)
                        mma16(acc[f][g], aL, bH[g]);
                }
            }
        }
        __syncthreads();
        if (s + 2 < ST) load(s + 2);
        asm volatile("cp.async.commit_group;");
    }

    size_t off = (size_t)blockIdx.z * ((size_t)gridDim.y * 128) * N;
    const int tr = lane >> 2, tc = (lane & 3) * 2;
    #pragma unroll
    for (int f = 0; f < 4; f++) {
        int m = m0 + wm * 64 + f * 16 + tr;
        #pragma unroll
        for (int g = 0; g < 4; g++) {
            int n = n0 + wn * 32 + g * 8 + tc;
            *(float2*)&Cg[off + (size_t)m * N + n] = make_float2(acc[f][g][0], acc[f][g][1]);
            *(float2*)&Cg[off + (size_t)(m + 8) * N + n] = make_float2(acc[f][g][2], acc[f][g][3]);
        }
    }
}

// ---------------- host ----------------
extern "C" void kernel_launch(void* const* d_in, const int* in_sizes, int n_in,
                              void* d_out, int out_size) {
    (void)in_sizes; (void)n_in; (void)out_size;
    const float* dd  = (const float*)d_in[0];
    const float* dA  = (const float*)d_in[1];
    const float* dB  = (const float*)d_in[2];
    const float* dW1 = (const float*)d_in[3];
    const float* db1 = (const float*)d_in[4];
    const float* dW2 = (const float*)d_in[5];
    const float* db2 = (const float*)d_in[6];
    const float* dz0 = (const float*)d_in[7];
    float* out = (float*)d_out;

    void* p;
    cudaGetSymbolAddress(&p, g_S);   float* S    = (float*)p;
    cudaGetSymbolAddress(&p, g_Xa);  float* Xa   = (float*)p;
    cudaGetSymbolAddress(&p, g_Xb);  float* Xb   = (float*)p;
    cudaGetSymbolAddress(&p, g_T);   float* Tm   = (float*)p;
    cudaGetSymbolAddress(&p, g_G);   float* G    = (float*)p;
    cudaGetSymbolAddress(&p, g_At);  float* At   = (float*)p;
    cudaGetSymbolAddress(&p, g_W1t); float* W1t  = (float*)p;
    cudaGetSymbolAddress(&p, g_W2t); float* W2t  = (float*)p;
    cudaGetSymbolAddress(&p, g_c);   float* c    = (float*)p;
    cudaGetSymbolAddress(&p, g_tv);  float* tv   = (float*)p;
    cudaGetSymbolAddress(&p, g_v);   float* v    = (float*)p;
    cudaGetSymbolAddress(&p, g_y);   float* y    = (float*)p;
    cudaGetSymbolAddress(&p, g_h);   float* h    = (float*)p;
    cudaGetSymbolAddress(&p, g_w);   float* wbuf = (float*)p;
    cudaGetSymbolAddress(&p, g_za);  float* za   = (float*)p;
    cudaGetSymbolAddress(&p, g_zb);  float* zbb  = (float*)p;
    cudaGetSymbolAddress(&p, g_P);   float* P    = (float*)p;
    cudaGetSymbolAddress(&p, g_flag); int* flag  = (int*)p;
    cudaGetSymbolAddress(&p, g_Ah);  __half* Ahp = (__half*)p;
    cudaGetSymbolAddress(&p, g_Al);  __half* Alp = (__half*)p;
    cudaGetSymbolAddress(&p, g_Gh);  __half* Ghp = (__half*)p;
    cudaGetSymbolAddress(&p, g_Gl);  __half* Glp = (__half*)p;
    cudaGetSymbolAddress(&p, g_uh);  __half* uhp = (__half*)p;
    cudaGetSymbolAddress(&p, g_ul);  __half* ulp = (__half*)p;
    cudaGetSymbolAddress(&p, g_rth); __half* rthp = (__half*)p;
    cudaGetSymbolAddress(&p, g_rtl); __half* rtlp = (__half*)p;
    cudaGetSymbolAddress(&p, g_Sh);  __half* Shp = (__half*)p;
    cudaGetSymbolAddress(&p, g_Sl);  __half* Slp = (__half*)p;
    cudaGetSymbolAddress(&p, g_Xh);  __half* Xhp = (__half*)p;
    cudaGetSymbolAddress(&p, g_Xl);  __half* Xlp = (__half*)p;
    cudaGetSymbolAddress(&p, g_Th);  __half* Thp = (__half*)p;
    cudaGetSymbolAddress(&p, g_Tl);  __half* Tlp = (__half*)p;
    cudaGetSymbolAddress(&p, g_dh);  __half* dhp = (__half*)p;
    cudaGetSymbolAddress(&p, g_dl);  __half* dlp = (__half*)p;
    cudaGetSymbolAddress(&p, g_W1h); __half* W1h = (__half*)p;
    cudaGetSymbolAddress(&p, g_W1l); __half* W1l = (__half*)p;
    cudaGetSymbolAddress(&p, g_W2h); __half* W2h = (__half*)p;
    cudaGetSymbolAddress(&p, g_W2l); __half* W2l = (__half*)p;
    cudaGetSymbolAddress(&p, g_hph); __half* hph = (__half*)p;
    cudaGetSymbolAddress(&p, g_hpl); __half* hpl = (__half*)p;

    cudaFuncSetAttribute(hgemm_k<3>,
                         cudaFuncAttributeMaxDynamicSharedMemorySize, HSMEM);
    cudaFuncSetAttribute(hgemm_k<1>,
                         cudaFuncAttributeMaxDynamicSharedMemorySize, HSMEM);

    init_k<<<1, 1>>>();
    copy4_k<<<(BC * N2C / 4) / 256, 256>>>((float4*)za, (const float4*)dz0);

    // A planes (x64)
    splitH_k<<<(int)(((size_t)N1C * N2C / 8) / 256), 256>>>(dA, Ahp, Alp, A_SC);

    // S = A A^T : hgemm, accum = 4096*S, split 4 -> 256 CTAs
    {
        dim3 g(N1C / 128, N1C / 128, SPL_S);
        hgemm_k<3><<<g, 256, HSMEM>>>(Ahp, Alp, N2C, Ahp, Alp, N2C, P, N1C, N2C / SPL_S, nullptr);
        reduce_sum_k<<<(N1C * N1C / 8) / 256, 256>>>(P, S, (size_t)N1C * N1C / 4, SPL_S, 1.f / 4096.f);
    }

    // power iteration (fp32 S)
    fill_k<<<N1C / 256, 256>>>(v, 0.03125f, N1C);
    for (int i = 0; i < PI_ITERS; i++) {
        spmv_k<<<N1C / 8, dim3(32, 8)>>>(S, v, y);
        pi_norm_k<<<1, 256>>>(y, v);
    }
    initX_k<<<(N1C * N1C) / 256, 256>>>(Xa);

    // S planes (x16)
    splitH_k<<<(int)(((size_t)N1C * N1C / 8) / 256), 256>>>(S, Shp, Slp, 16.f);

    // Newton-Schulz: 4 cheap (NP=1) + 2 precise (NP=3), symmetrized, split 4
    float* Xc = Xa; float* Xn = Xb;
    {
        dim3 g(N1C / 128, N1C / 128, SPL_NS);
        dim3 gsym(N1C / 32, N1C / 8);
        size_t s4 = (size_t)N1C * N1C / 4;
        int nsgrid = (N1C * N1C / 8) / 256;
        for (int i = 0; i < NS_ITERS; i++) {
            symm_k<<<gsym, 256>>>(Xc);
            splitH_k<<<(N1C * N1C / 8) / 256, 256>>>(Xc, Xhp, Xlp, 32.f);
            if (i < NS_CHEAP)
                hgemm_k<1><<<g, 256, HSMEM>>>(Xhp, Xlp, N1C, Shp, Slp, N1C, P, N1C, N1C / SPL_NS, nullptr);
            else
                hgemm_k<3><<<g, 256, HSMEM>>>(Xhp, Xlp, N1C, Shp, Slp, N1C, P, N1C, N1C / SPL_NS, nullptr);
            reduce_sum_k<<<nsgrid, 256>>>(P, Tm, s4, SPL_NS, 1.f / 512.f);
            splitH_k<<<(N1C * N1C / 8) / 256, 256>>>(Tm, Thp, Tlp, 32.f);
            if (i < NS_CHEAP)
                hgemm_k<1><<<g, 256, HSMEM>>>(Thp, Tlp, N1C, Xhp, Xlp, N1C, P, N1C, N1C / SPL_NS, nullptr);
            else
                hgemm_k<3><<<g, 256, HSMEM>>>(Thp, Tlp, N1C, Xhp, Xlp, N1C, P, N1C, N1C / SPL_NS, nullptr);
            reduce_ns_k<<<nsgrid, 256>>>(P, Xc, Xn, s4, SPL_NS, 1.f / 1024.f);
            float* t2 = Xc; Xc = Xn; Xn = t2;
        }
        symm_k<<<gsym, 256>>>(Xc);
    }

    // c = A^T (X b)
    spmv_k<<<N1C / 8, dim3(32, 8)>>>(Xc, dB, tv);
    atmv_k<<<N2C / 256, 256>>>(dA, tv, c);

    // G = A^T X: At planes (x64, temp in Gh/Gl), X planes (x32) -> accum 2048*G
    transp_k<<<dim3(N2C / 32, N1C / 32), dim3(32, 8)>>>(At, dA, N1C, N2C);
    splitH_k<<<(int)(((size_t)N2C * N1C / 8) / 256), 256>>>(At, Ghp, Glp, A_SC);
    splitH_k<<<(N1C * N1C / 8) / 256, 256>>>(Xc, Xhp, Xlp, 32.f);
    {
        dim3 g(N1C / 128, N2C / 128, 1);      // 256 CTAs already
        hgemm_k<3><<<g, 256, HSMEM>>>(Ghp, Glp, N1C, Xhp, Xlp, N1C, P, N1C, N1C, nullptr);
        reduce_sum_k<<<(int)(((size_t)N2C * N1C / 8) / 256), 256>>>(
            P, G, 0, 1, 1.f / 2048.f);
    }
    splitH_k<<<(int)(((size_t)N2C * N1C / 8) / 256), 256>>>(G, Ghp, Glp, G_SC);

    // MLP on hgemm (split 8 / 4 -> 256 CTAs each)
    transp_k<<<dim3(HC / 32, DC / 32), dim3(32, 8)>>>(W1t, dW1, DC, HC);
    splitH_k<<<(int)(((size_t)HC * DC / 8) / 256), 256>>>(W1t, W1h, W1l, 32.f);
    transp_k<<<dim3(N2C / 32, HC / 32), dim3(32, 8)>>>(W2t, dW2, HC, N2C);
    splitH_k<<<(int)(((size_t)N2C * HC / 8) / 256), 256>>>(W2t, W2h, W2l, 32.f);
    splitH_k<<<(BC * DC / 8) / 256, 256>>>(dd, dhp, dlp, 1.f);
    {
        dim3 g1(HC / 128, BC / 128, SPL_M1);
        hgemm_k<3><<<g1, 256, HSMEM>>>(dhp, dlp, DC, W1h, W1l, DC, P, HC, DC / SPL_M1, nullptr);
        reduce_bias_k<true><<<(BC * HC / 8) / 256, 256>>>(
            P, db1, h, (size_t)BC * HC / 4, SPL_M1, HC / 4, 1.f / 32.f);
        splitH_k<<<(BC * HC / 8) / 256, 256>>>(h, hph, hpl, 1.f);
        dim3 g2(N2C / 128, BC / 128, SPL_M2);
        hgemm_k<3><<<g2, 256, HSMEM>>>(hph, hpl, HC, W2h, W2l, HC, P, N2C, HC / SPL_M2, nullptr);
        reduce_bias_k<false><<<(BC * N2C / 8) / 256, 256>>>(
            P, db2, wbuf, (size_t)BC * N2C / 4, SPL_M2, N2C / 4, 1.f / 32.f);
    }

    // initial u planes
    u0_k<<<(BC * N2C / 4) / 256, 256>>>(za, wbuf);

    // DYS loop (gr split 16 -> 256 CTAs, gz split 4 -> 256 CTAs)
    dim3 gr(BC / 128, N1C / 128, SPL_GR);
    dim3 gz(N2C / 128, BC / 128, SPL_GZ);
    float* zb2[2] = { za, zbb };
    for (int it = 1; it <= 50; ++it) {
        const float* zin = zb2[(it - 1) & 1];
        float* zout = zb2[it & 1];
        hgemm_k<3><<<gr, 256, HSMEM>>>(Ahp, Alp, N2C, uhp, ulp, N2C, P, BC, N2C / SPL_GR, flag);
        reduce_tr_k<<<dim3(N1C / 32, BC / 32), dim3(32, 8)>>>(P, flag);
        hgemm_k<3><<<gz, 256, HSMEM>>>(rthp, rtlp, N1C, Ghp, Glp, N1C, P, N2C, N1C / SPL_GZ, flag);
        zupd_k<false><<<(BC * N2C / 8) / 256, 256>>>(P, zin, wbuf, c, zout, flag);
    }

    // final unguarded step, relu into d_out
    hgemm_k<3><<<gr, 256, HSMEM>>>(Ahp, Alp, N2C, uhp, ulp, N2C, P, BC, N2C / SPL_GR, nullptr);
    reduce_tr_k<<<dim3(N1C / 32, BC / 32), dim3(32, 8)>>>(P, nullptr);
    hgemm_k<3><<<gz, 256, HSMEM>>>(rthp, rtlp, N1C, Ghp, Glp, N1C, P, N2C, N1C / SPL_GZ, nullptr);
    zupd_k<true><<<(BC * N2C / 8) / 256, 256>>>(P, za, wbuf, c, out, nullptr);
}